// round 2
// baseline (speedup 1.0000x reference)
#include <cuda_runtime.h>
#include <math.h>

#define NB 16
#define NC 64
#define NT 128
#define ND 256
#define NH 8
#define NKD 32
#define NTOPK 8

// ---------------- device scratch (no allocations allowed) ----------------
__device__ float g_hmean[NB * NC * ND];
__device__ float g_adaptive[NB * NC * NC];
__device__ unsigned long long g_maskcol[NB * NC];  // bit i set => edge i -> j
__device__ float g_vsrc[NH * ND];
__device__ float g_vdst[NH * ND];

// ---------------- kernel A: temporal mean ----------------
__global__ void k_hmean(const float* __restrict__ x) {
    int bc = blockIdx.x;     // b*C + c
    int d = threadIdx.x;     // 256 threads
    const float* p = x + (size_t)bc * NT * ND + d;
    float s = 0.f;
#pragma unroll 8
    for (int t = 0; t < NT; ++t) s += p[(size_t)t * ND];
    g_hmean[bc * ND + d] = s * (1.0f / NT);
}

// ---------------- kernel D: v_src[h,d] = sum_f att[h,f] * gat_lin[h*D+f, d] ----------------
__global__ void k_vsd(const float* __restrict__ gat_lin,
                      const float* __restrict__ att_src,
                      const float* __restrict__ att_dst) {
    int h = blockIdx.x & 7;
    int isdst = blockIdx.x >> 3;
    int d = threadIdx.x;  // 256
    const float* att = isdst ? att_dst : att_src;
    float acc = 0.f;
#pragma unroll 4
    for (int f = 0; f < ND; ++f)
        acc += att[h * ND + f] * gat_lin[((size_t)(h * ND + f)) * ND + d];
    (isdst ? g_vdst : g_vsrc)[h * ND + d] = acc;
}

// ---------------- kernel B: q/k, sim, tanh -> delta_a (output) + adaptive; init self loops ----------------
__global__ void k_adj(const float* __restrict__ static_adj,
                      const float* __restrict__ w_q,
                      const float* __restrict__ w_k,
                      float* __restrict__ delta_out) {
    __shared__ float q_s[NC * NKD];
    __shared__ float k_s[NC * NKD];
    int b = blockIdx.x;
    int tid = threadIdx.x;  // 256
    if (tid < NC) g_maskcol[b * NC + tid] = 1ull << tid;  // self loop

    for (int task = tid; task < 2 * NC * NKD; task += 256) {
        int which = task >= NC * NKD;
        int t2 = task - which * NC * NKD;
        int c = t2 / NKD, kd = t2 % NKD;
        const float* w = which ? w_k : w_q;
        const float* hrow = g_hmean + (size_t)(b * NC + c) * ND;
        const float* wrow = w + (size_t)kd * ND;
        float acc = 0.f;
#pragma unroll 4
        for (int d = 0; d < ND; ++d) acc += hrow[d] * wrow[d];
        (which ? k_s : q_s)[c * NKD + kd] = acc;
    }
    __syncthreads();
    const float inv = 0.17677669529663687f;  // 1/sqrt(32)
    for (int task = tid; task < NC * NC; task += 256) {
        int i = task / NC, j = task % NC;
        float acc = 0.f;
#pragma unroll
        for (int kd = 0; kd < NKD; ++kd) acc += q_s[i * NKD + kd] * k_s[j * NKD + kd];
        float delta = tanhf(acc * inv);
        delta_out[b * NC * NC + task] = delta;
        g_adaptive[b * NC * NC + task] = static_adj[task] + delta;
    }
}

// ---------------- kernel C: per-row top-8 of |adaptive| -> column bitmasks ----------------
__global__ void k_topk() {
    int b = blockIdx.x / NC, i = blockIdx.x % NC;
    int lane = threadIdx.x;  // 32
    const float* row = g_adaptive + (size_t)(b * NC + i) * NC;
    float v0 = fabsf(row[lane]);
    float v1 = fabsf(row[lane + 32]);
    for (int s = 0; s < NTOPK; ++s) {
        float bv; int bj;
        if (v0 >= v1) { bv = v0; bj = lane; } else { bv = v1; bj = lane + 32; }
#pragma unroll
        for (int off = 16; off > 0; off >>= 1) {
            float ov = __shfl_xor_sync(0xffffffffu, bv, off);
            int   oj = __shfl_xor_sync(0xffffffffu, bj, off);
            if (ov > bv || (ov == bv && oj < bj)) { bv = ov; bj = oj; }
        }
        if (lane == 0) atomicOr(&g_maskcol[b * NC + bj], 1ull << i);
        if (bj == lane)      v0 = -1.0f;
        if (bj == lane + 32) v1 = -1.0f;
    }
}

// ---------------- kernel F: main GAT per (b,t) ----------------
#define XS_STRIDE 264
#define GS_STRIDE 33
#define AS_STRIDE 65
#define FTHREADS 512
#define SMEM_FLOATS (NC * XS_STRIDE * 2 + NC * AS_STRIDE + ND * GS_STRIDE + 2 * NH * ND + 2 * NH * NC)
#define SMEM_BYTES (SMEM_FLOATS * 4)

__global__ __launch_bounds__(FTHREADS, 1)
void k_main(const float* __restrict__ x,
            const float* __restrict__ gat_lin,
            const float* __restrict__ gat_bias,
            float* __restrict__ out) {
    extern __shared__ float sm[];
    float* x_s     = sm;                       // [64][264]
    float* z_s     = x_s + NC * XS_STRIDE;     // [64][264]
    float* alpha_s = z_s + NC * XS_STRIDE;     // [64 i][65] (col j)
    float* g_s     = alpha_s + NC * AS_STRIDE; // [256 f][33]
    float* v_s     = g_s + ND * GS_STRIDE;     // [2][8][256]
    float* as_s    = v_s + 2 * NH * ND;        // [8 h][64 i]
    float* ad_s    = as_s + NH * NC;           // [8 h][64 j]

    int bt = blockIdx.x;
    int b = bt >> 7;
    int t = bt & 127;
    int tid = threadIdx.x;

    // load x_bt [64 x 256]
    for (int idx = tid; idx < NC * ND; idx += FTHREADS) {
        int i = idx >> 8, d = idx & 255;
        x_s[i * XS_STRIDE + d] = x[(((size_t)b * NC + i) * NT + t) * ND + d];
    }
    for (int idx = tid; idx < 2 * NH * ND; idx += FTHREADS)
        v_s[idx] = (idx < NH * ND) ? g_vsrc[idx] : g_vdst[idx - NH * ND];
    __syncthreads();

    // a_src[i,h], a_dst[i,h]
    for (int task = tid; task < NC * 2 * NH; task += FTHREADS) {
        int i = task >> 4;
        int hh = task & 15;
        int h = hh & 7, isd = hh >> 3;
        const float* v = v_s + (isd * NH + h) * ND;
        const float* xr = x_s + i * XS_STRIDE;
        float acc = 0.f;
#pragma unroll 8
        for (int d = 0; d < ND; ++d) acc += xr[d] * v[d];
        (isd ? ad_s : as_s)[h * NC + i] = acc;
    }
    __syncthreads();

    const int tf = tid & 31;  // f = tf + 32*s (s<8) / d = tf + 32*s
    const int tj = tid >> 5;  // j = tj + 16*r (r<4), warp-uniform
    float out_acc[4][8];
#pragma unroll
    for (int r = 0; r < 4; ++r)
#pragma unroll
        for (int s = 0; s < 8; ++s) out_acc[r][s] = 0.f;

    const float NEGINF = __int_as_float(0xff800000);

    for (int h = 0; h < NH; ++h) {
        // ---- alpha[i][j] = masked softmax over i ----
        {
            int w = tid >> 5, lane = tid & 31;
#pragma unroll
            for (int jj = 0; jj < 4; ++jj) {
                int j = w * 4 + jj;
                unsigned long long m = g_maskcol[b * NC + j];
                float adj = ad_s[h * NC + j];
                int i0 = lane, i1 = lane + 32;
                float e0 = as_s[h * NC + i0] + adj;
                float e1 = as_s[h * NC + i1] + adj;
                e0 = e0 > 0.f ? e0 : 0.2f * e0;   // leaky_relu(0.2)
                e1 = e1 > 0.f ? e1 : 0.2f * e1;
                bool m0 = (m >> i0) & 1ull;
                bool m1 = (m >> i1) & 1ull;
                float mx = fmaxf(m0 ? e0 : NEGINF, m1 ? e1 : NEGINF);
#pragma unroll
                for (int off = 16; off > 0; off >>= 1)
                    mx = fmaxf(mx, __shfl_xor_sync(0xffffffffu, mx, off));
                float p0 = m0 ? expf(e0 - mx) : 0.f;
                float p1 = m1 ? expf(e1 - mx) : 0.f;
                float ssum = p0 + p1;
#pragma unroll
                for (int off = 16; off > 0; off >>= 1)
                    ssum += __shfl_xor_sync(0xffffffffu, ssum, off);
                float invs = 1.0f / ssum;
                alpha_s[i0 * AS_STRIDE + j] = p0 * invs;
                alpha_s[i1 * AS_STRIDE + j] = p1 * invs;
            }
        }
        __syncthreads();

        // ---- z[j][d] = sum_i alpha[i][j] * x[i][d] ----
        {
            float z_acc[4][8];
#pragma unroll
            for (int r = 0; r < 4; ++r)
#pragma unroll
                for (int s = 0; s < 8; ++s) z_acc[r][s] = 0.f;
#pragma unroll 2
            for (int i = 0; i < NC; ++i) {
                float a[4];
#pragma unroll
                for (int r = 0; r < 4; ++r) a[r] = alpha_s[i * AS_STRIDE + tj + 16 * r];
                float xr[8];
#pragma unroll
                for (int s = 0; s < 8; ++s) xr[s] = x_s[i * XS_STRIDE + tf + 32 * s];
#pragma unroll
                for (int r = 0; r < 4; ++r)
#pragma unroll
                    for (int s = 0; s < 8; ++s) z_acc[r][s] += a[r] * xr[s];
            }
#pragma unroll
            for (int r = 0; r < 4; ++r)
#pragma unroll
                for (int s = 0; s < 8; ++s)
                    z_s[(tj + 16 * r) * XS_STRIDE + tf + 32 * s] = z_acc[r][s];
        }
        __syncthreads();

        // ---- out[j][f] += sum_d z[j][d] * G_h[f][d] ----
        const float* G = gat_lin + (size_t)h * ND * ND;
        for (int dt = 0; dt < ND; dt += 32) {
            for (int idx = tid; idx < ND * 32; idx += FTHREADS) {
                int f = idx >> 5, k = idx & 31;
                g_s[f * GS_STRIDE + k] = G[(size_t)f * ND + dt + k];
            }
            __syncthreads();
#pragma unroll 4
            for (int k = 0; k < 32; ++k) {
                float zr[4];
#pragma unroll
                for (int r = 0; r < 4; ++r) zr[r] = z_s[(tj + 16 * r) * XS_STRIDE + dt + k];
                float gr[8];
#pragma unroll
                for (int s = 0; s < 8; ++s) gr[s] = g_s[(tf + 32 * s) * GS_STRIDE + k];
#pragma unroll
                for (int r = 0; r < 4; ++r)
#pragma unroll
                    for (int s = 0; s < 8; ++s) out_acc[r][s] += zr[r] * gr[s];
            }
            __syncthreads();
        }
    }

    // epilogue: mean over heads + bias, write x_updated[b,j,t,f]
#pragma unroll
    for (int r = 0; r < 4; ++r) {
        int j = tj + 16 * r;
#pragma unroll
        for (int s = 0; s < 8; ++s) {
            int f = tf + 32 * s;
            float val = out_acc[r][s] * (1.0f / NH) + __ldg(gat_bias + f);
            out[(((size_t)b * NC + j) * NT + t) * ND + f] = val;
        }
    }
}

// ---------------- launch ----------------
extern "C" void kernel_launch(void* const* d_in, const int* in_sizes, int n_in,
                              void* d_out, int out_size) {
    const float* x          = (const float*)d_in[0];
    const float* static_adj = (const float*)d_in[1];
    const float* w_q        = (const float*)d_in[2];
    const float* w_k        = (const float*)d_in[3];
    const float* gat_lin    = (const float*)d_in[4];
    const float* att_src    = (const float*)d_in[5];
    const float* att_dst    = (const float*)d_in[6];
    const float* gat_bias   = (const float*)d_in[7];

    float* out = (float*)d_out;
    float* delta_out = out + (size_t)NB * NC * NT * ND;  // delta_a after x_updated

    cudaFuncSetAttribute(k_main, cudaFuncAttributeMaxDynamicSharedMemorySize, SMEM_BYTES);

    k_hmean<<<NB * NC, 256>>>(x);
    k_vsd<<<16, 256>>>(gat_lin, att_src, att_dst);
    k_adj<<<NB, 256>>>(static_adj, w_q, w_k, delta_out);
    k_topk<<<NB * NC, 32>>>();
    k_main<<<NB * NT, FTHREADS, SMEM_BYTES>>>(x, gat_lin, gat_bias, out);
}

// round 4
// speedup vs baseline: 1.6152x; 1.6152x over previous
#include <cuda_runtime.h>
#include <cuda_bf16.h>
#include <math.h>
#include <stdint.h>

#define NB 16
#define NC 64
#define NT 128
#define ND 256
#define NH 8
#define NKD 32
#define NTOPK 8

// ======================= helpers =======================
__device__ __forceinline__ uint32_t smem_to_u32(const void* p) {
    uint32_t a;
    asm("{ .reg .u64 t; cvta.to.shared.u64 t, %1; cvt.u32.u64 %0, t; }" : "=r"(a) : "l"(p));
    return a;
}
#define CP_ASYNC16(sa, gp) \
    asm volatile("cp.async.cg.shared.global [%0], [%1], 16;" :: "r"(sa), "l"(gp))
#define CP_COMMIT() asm volatile("cp.async.commit_group;")
#define CP_WAIT0()  asm volatile("cp.async.wait_group 0;")

__device__ __forceinline__ void ldsm_x4(uint32_t* r, uint32_t addr) {
    asm volatile("ldmatrix.sync.aligned.m8n8.x4.shared.b16 {%0,%1,%2,%3}, [%4];"
                 : "=r"(r[0]), "=r"(r[1]), "=r"(r[2]), "=r"(r[3]) : "r"(addr));
}
__device__ __forceinline__ void mma16816(float* d, const uint32_t* a, const uint32_t* b) {
    asm volatile(
        "mma.sync.aligned.m16n8k16.row.col.f32.bf16.bf16.f32 "
        "{%0,%1,%2,%3}, {%4,%5,%6,%7}, {%8,%9}, {%0,%1,%2,%3};"
        : "+f"(d[0]), "+f"(d[1]), "+f"(d[2]), "+f"(d[3])
        : "r"(a[0]), "r"(a[1]), "r"(a[2]), "r"(a[3]), "r"(b[0]), "r"(b[1]));
}

// ======================= device scratch =======================
__device__ float g_hmean[NB * NC * ND];
__device__ float g_adaptive[NB * NC * NC];
__device__ unsigned long long g_maskcol[NB * NC];
__device__ float g_vsrc[NH * ND];
__device__ float g_vdst[NH * ND];
__device__ __nv_bfloat16 g_xhi[NB * NC * NT * ND];     // 64MB
__device__ __nv_bfloat16 g_xlo[NB * NC * NT * ND];     // 64MB
__device__ __nv_bfloat16 g_ghi[NH * ND * ND];          // 1MB
__device__ __nv_bfloat16 g_glo[NH * ND * ND];          // 1MB
__device__ float g_wx[(size_t)NB * NC * NT * NH * ND]; // 1.07GB [row=(b*64+c)*128+t][2048]
__device__ float g_as[NB * NT * NH * NC];
__device__ float g_ad[NB * NT * NH * NC];

// ======================= kernel: bf16 hi/lo split =======================
#define NX_ELEMS 33554432u
#define NG_ELEMS 524288u
__global__ void k_split(const float* __restrict__ x, const float* __restrict__ g) {
    size_t i = (size_t)blockIdx.x * blockDim.x + threadIdx.x;
    if (i >= (size_t)NX_ELEMS + NG_ELEMS) return;
    float v;
    __nv_bfloat16 *hp, *lp;
    size_t off;
    if (i < NX_ELEMS) { v = x[i]; hp = g_xhi; lp = g_xlo; off = i; }
    else { off = i - NX_ELEMS; v = g[off]; hp = g_ghi; lp = g_glo; }
    __nv_bfloat16 hi = __float2bfloat16(v);
    float r = v - __bfloat162float(hi);
    hp[off] = hi;
    lp[off] = __float2bfloat16(r);
}

// ======================= kernel: temporal mean =======================
__global__ void k_hmean(const float* __restrict__ x) {
    int bc = blockIdx.x;
    int d = threadIdx.x;
    const float* p = x + (size_t)bc * NT * ND + d;
    float s = 0.f;
#pragma unroll 8
    for (int t = 0; t < NT; ++t) s += p[(size_t)t * ND];
    g_hmean[bc * ND + d] = s * (1.0f / NT);
}

// ======================= kernel: v_src/v_dst =======================
__global__ void k_vsd(const float* __restrict__ gat_lin,
                      const float* __restrict__ att_src,
                      const float* __restrict__ att_dst) {
    int h = blockIdx.x & 7;
    int isdst = blockIdx.x >> 3;
    int d = threadIdx.x;
    const float* att = isdst ? att_dst : att_src;
    float acc = 0.f;
#pragma unroll 4
    for (int f = 0; f < ND; ++f)
        acc += att[h * ND + f] * gat_lin[((size_t)(h * ND + f)) * ND + d];
    (isdst ? g_vdst : g_vsrc)[h * ND + d] = acc;
}

// ======================= kernel: adjacency =======================
__global__ void k_adj(const float* __restrict__ static_adj,
                      const float* __restrict__ w_q,
                      const float* __restrict__ w_k,
                      float* __restrict__ delta_out) {
    __shared__ float q_s[NC * NKD];
    __shared__ float k_s[NC * NKD];
    int b = blockIdx.x;
    int tid = threadIdx.x;
    if (tid < NC) g_maskcol[b * NC + tid] = 1ull << tid;

    for (int task = tid; task < 2 * NC * NKD; task += 256) {
        int which = task >= NC * NKD;
        int t2 = task - which * NC * NKD;
        int c = t2 / NKD, kd = t2 % NKD;
        const float* w = which ? w_k : w_q;
        const float* hrow = g_hmean + (size_t)(b * NC + c) * ND;
        const float* wrow = w + (size_t)kd * ND;
        float acc = 0.f;
#pragma unroll 4
        for (int d = 0; d < ND; ++d) acc += hrow[d] * wrow[d];
        (which ? k_s : q_s)[c * NKD + kd] = acc;
    }
    __syncthreads();
    const float inv = 0.17677669529663687f;
    for (int task = tid; task < NC * NC; task += 256) {
        int i = task / NC, j = task % NC;
        float acc = 0.f;
#pragma unroll
        for (int kd = 0; kd < NKD; ++kd) acc += q_s[i * NKD + kd] * k_s[j * NKD + kd];
        float delta = tanhf(acc * inv);
        delta_out[b * NC * NC + task] = delta;
        g_adaptive[b * NC * NC + task] = static_adj[task] + delta;
    }
}

// ======================= kernel: top-k =======================
__global__ void k_topk() {
    int b = blockIdx.x / NC, i = blockIdx.x % NC;
    int lane = threadIdx.x;
    const float* row = g_adaptive + (size_t)(b * NC + i) * NC;
    float v0 = fabsf(row[lane]);
    float v1 = fabsf(row[lane + 32]);
    for (int s = 0; s < NTOPK; ++s) {
        float bv; int bj;
        if (v0 >= v1) { bv = v0; bj = lane; } else { bv = v1; bj = lane + 32; }
#pragma unroll
        for (int off = 16; off > 0; off >>= 1) {
            float ov = __shfl_xor_sync(0xffffffffu, bv, off);
            int   oj = __shfl_xor_sync(0xffffffffu, bj, off);
            if (ov > bv || (ov == bv && oj < bj)) { bv = ov; bj = oj; }
        }
        if (lane == 0) atomicOr(&g_maskcol[b * NC + bj], 1ull << i);
        if (bj == lane)      v0 = -1.0f;
        if (bj == lane + 32) v1 = -1.0f;
    }
}

// ======================= kernel: a_src/a_dst =======================
#define ATT_SMEM (64 * 264 * 4)
__global__ __launch_bounds__(256)
void k_att(const float* __restrict__ x) {
    extern __shared__ float xs[];
    int bt = blockIdx.x, b = bt >> 7, t = bt & 127;
    int tid = threadIdx.x;
    const float4* x4 = (const float4*)x;
    for (int it = tid; it < 4096; it += 256) {
        int c = it >> 6, q = it & 63;
        float4 v = x4[(((size_t)(b * NC + c) * NT) + t) * 64 + q];
        *(float4*)&xs[c * 264 + q * 4] = v;
    }
    __syncthreads();
    for (int task = tid; task < 1024; task += 256) {
        int c = task >> 4;
        int hh = task & 15;
        int h = hh & 7, sd = hh >> 3;
        const float* v = (sd ? g_vdst : g_vsrc) + h * ND;
        const float* xr = xs + c * 264;
        float acc = 0.f;
#pragma unroll 8
        for (int d = 0; d < ND; ++d) acc += xr[d] * v[d];
        (sd ? g_ad : g_as)[((size_t)bt * NH + h) * NC + c] = acc;
    }
}

// ======================= kernel: split-bf16 GEMM via mma.sync (HMMA) =======================
// WX[131072,2048] = X[131072,256] @ G[2048,256]^T  as Xh*Gh + Xh*Gl + Xl*Gh
#define GEMM_THREADS 512
#define SMA_BYTES 131072               // A resident: [split2][kb4][128][128B] swizzled
#define SMB_BYTES 65536                // B double buf: [buf2][split2][128][128B]
#define SM_GEMM_TOTAL (SMA_BYTES + SMB_BYTES)

__global__ __launch_bounds__(GEMM_THREADS, 1)
void k_gemm() {
    extern __shared__ char smem[];
    uint32_t sbA = smem_to_u32(smem);
    uint32_t sbB = sbA + SMA_BYTES;
    const int tid = threadIdx.x;
    const int w = tid >> 5, l = tid & 31;
    const size_t mtile = blockIdx.x;

    // ---- issue A resident loads (cp.async): 8192 x 16B ----
    {
        const char* xh = (const char*)g_xhi;
        const char* xl = (const char*)g_xlo;
#pragma unroll
        for (int ii = 0; ii < 16; ++ii) {
            int it = tid + ii * GEMM_THREADS;
            int q = it & 7, r = (it >> 3) & 127, kb = (it >> 10) & 3, s = it >> 12;
            const char* gp = (s ? xl : xh) + ((mtile * 128 + r) * 512 + kb * 128 + q * 16);
            uint32_t sa = sbA + (uint32_t)((s * 4 + kb) * 16384 + r * 128 + ((q * 16) ^ ((r & 7) << 4)));
            CP_ASYNC16(sa, gp);
        }
    }
    // ---- issue first B chunk (nt=0, kb=0) into buf 0 ----
    {
        const char* gh = (const char*)g_ghi;
        const char* gl = (const char*)g_glo;
#pragma unroll
        for (int ii = 0; ii < 4; ++ii) {
            int it = tid + ii * GEMM_THREADS;
            int q = it & 7, r = (it >> 3) & 127, s = it >> 10;
            const char* gp = (s ? gl : gh) + ((size_t)r * 512 + q * 16);
            uint32_t sa = sbB + (uint32_t)(s * 16384 + r * 128 + ((q * 16) ^ ((r & 7) << 4)));
            CP_ASYNC16(sa, gp);
        }
    }
    CP_COMMIT();
    CP_WAIT0();
    __syncthreads();

    // ---- per-thread ldmatrix geometry ----
    const int mbase = (w & 3) * 32;
    const int nbase = (w >> 2) * 32;
    // A: lanes 0-15 -> 16 rows, lanes 16-31 repeat rows at k+8
    int aoff[2]; uint32_t akx[2];
#pragma unroll
    for (int mt = 0; mt < 2; ++mt) {
        int r = mbase + mt * 16 + (l & 15);
        aoff[mt] = r * 128;
        akx[mt] = (uint32_t)((r & 7) << 4);
    }
    const uint32_t akoff = (uint32_t)((l >> 4) * 16);
    // B: lanes 0-7 rows+0..7 k0 / 8-15 same rows k+16B / 16-23 rows+8 k0 / 24-31 rows+8 k+16B
    int boff[2]; uint32_t bkx[2];
#pragma unroll
    for (int p = 0; p < 2; ++p) {
        int r = nbase + p * 16 + (l & 7) + (l >> 4) * 8;
        boff[p] = r * 128;
        bkx[p] = (uint32_t)((r & 7) << 4);
    }
    const uint32_t bkoff = (uint32_t)(((l >> 3) & 1) * 16);

    float acc[2][4][4];
#pragma unroll
    for (int mt = 0; mt < 2; ++mt)
#pragma unroll
        for (int g = 0; g < 4; ++g)
#pragma unroll
            for (int q = 0; q < 4; ++q) acc[mt][g][q] = 0.f;

    const char* ghp = (const char*)g_ghi;
    const char* glp = (const char*)g_glo;
    int buf = 0;

    for (int nt = 0; nt < 16; ++nt) {
        for (int kb = 0; kb < 4; ++kb) {
            const int have_next = !(nt == 15 && kb == 3);
            if (have_next) {
                int nn = nt + (kb == 3);
                int nk = (kb + 1) & 3;
                int b2 = buf ^ 1;
#pragma unroll
                for (int ii = 0; ii < 4; ++ii) {
                    int it = tid + ii * GEMM_THREADS;
                    int q = it & 7, r = (it >> 3) & 127, s = it >> 10;
                    const char* gp = (s ? glp : ghp) + ((size_t)(nn * 128 + r) * 512 + nk * 128 + q * 16);
                    uint32_t sa = sbB + (uint32_t)((b2 * 2 + s) * 16384 + r * 128 + ((q * 16) ^ ((r & 7) << 4)));
                    CP_ASYNC16(sa, gp);
                }
                CP_COMMIT();
            }

            // ---- compute on current buf ----
            const uint32_t pAh = sbA + (uint32_t)((0 * 4 + kb) * 16384);
            const uint32_t pAl = sbA + (uint32_t)((1 * 4 + kb) * 16384);
            const uint32_t pBh = sbB + (uint32_t)((buf * 2 + 0) * 16384);
            const uint32_t pBl = sbB + (uint32_t)((buf * 2 + 1) * 16384);
#pragma unroll
            for (int ks = 0; ks < 4; ++ks) {
                uint32_t ah[2][4], al[2][4], bh[2][4], bl[2][4];
#pragma unroll
                for (int mt = 0; mt < 2; ++mt) {
                    uint32_t kbyte = ((uint32_t)(ks * 32) + akoff) ^ akx[mt];
                    ldsm_x4(ah[mt], pAh + aoff[mt] + kbyte);
                    ldsm_x4(al[mt], pAl + aoff[mt] + kbyte);
                }
#pragma unroll
                for (int p = 0; p < 2; ++p) {
                    uint32_t kbyte = ((uint32_t)(ks * 32) + bkoff) ^ bkx[p];
                    ldsm_x4(bh[p], pBh + boff[p] + kbyte);
                    ldsm_x4(bl[p], pBl + boff[p] + kbyte);
                }
#pragma unroll
                for (int mt = 0; mt < 2; ++mt)
#pragma unroll
                    for (int g = 0; g < 4; ++g) {
                        const int p = g >> 1, o = (g & 1) * 2;
                        mma16816(acc[mt][g], ah[mt], &bh[p][o]);
                        mma16816(acc[mt][g], ah[mt], &bl[p][o]);
                        mma16816(acc[mt][g], al[mt], &bh[p][o]);
                    }
            }

            if (have_next) CP_WAIT0();
            __syncthreads();
            buf ^= 1;
        }

        // ---- epilogue: write 128x128 D tile to g_wx ----
        {
            size_t r0 = mtile * 128 + mbase + (l >> 2);
            int c0 = nt * 128 + nbase + (l & 3) * 2;
#pragma unroll
            for (int mt = 0; mt < 2; ++mt) {
#pragma unroll
                for (int g = 0; g < 4; ++g) {
                    float* dst = g_wx + (r0 + mt * 16) * 2048 + c0 + g * 8;
                    float2 v0 = make_float2(acc[mt][g][0], acc[mt][g][1]);
                    float2 v1 = make_float2(acc[mt][g][2], acc[mt][g][3]);
                    *(float2*)dst = v0;
                    *(float2*)(dst + 8 * 2048) = v1;
                    acc[mt][g][0] = acc[mt][g][1] = acc[mt][g][2] = acc[mt][g][3] = 0.f;
                }
            }
        }
    }
}

// ======================= kernel: aggregation (softmax + alpha^T @ wx) =======================
#define ATHREADS 512
#define AWX_STR 264
#define AAL_STR 65
#define AGG_SMEM ((64 * AWX_STR + 64 * AAL_STR + 128) * 4)

__global__ __launch_bounds__(ATHREADS)
void k_agg(const float* __restrict__ gat_bias, float* __restrict__ out) {
    extern __shared__ float sm[];
    float* wx_s = sm;                          // [64][264]
    float* alpha_s = wx_s + 64 * AWX_STR;      // [64 i][65] col j
    float* as_s = alpha_s + 64 * AAL_STR;      // [64]
    float* ad_s = as_s + 64;                   // [64]

    int bt = blockIdx.x, b = bt >> 7, t = bt & 127;
    int tid = threadIdx.x;
    int w = tid >> 5, lane = tid & 31;
    int tf = tid & 31, tj = tid >> 5;

    unsigned long long msk[4];
#pragma unroll
    for (int jj = 0; jj < 4; ++jj) msk[jj] = g_maskcol[b * NC + w * 4 + jj];

    float out_acc[4][8];
#pragma unroll
    for (int r = 0; r < 4; ++r)
#pragma unroll
        for (int s = 0; s < 8; ++s) out_acc[r][s] = 0.f;

    const float NEGINF = __int_as_float(0xff800000);
    const float4* wx4 = (const float4*)g_wx;

    for (int h = 0; h < NH; ++h) {
        for (int it = tid; it < 4096; it += ATHREADS) {
            int c = it >> 6, q = it & 63;
            float4 v = wx4[(((size_t)(b * NC + c) * NT) + t) * 512 + h * 64 + q];
            *(float4*)&wx_s[c * AWX_STR + q * 4] = v;
        }
        if (tid < 64) as_s[tid] = g_as[((size_t)bt * NH + h) * NC + tid];
        else if (tid < 128) ad_s[tid - 64] = g_ad[((size_t)bt * NH + h) * NC + (tid - 64)];
        __syncthreads();

#pragma unroll
        for (int jj = 0; jj < 4; ++jj) {
            int j = w * 4 + jj;
            unsigned long long m = msk[jj];
            float adj = ad_s[j];
            int i0 = lane, i1 = lane + 32;
            float e0 = as_s[i0] + adj;
            float e1 = as_s[i1] + adj;
            e0 = e0 > 0.f ? e0 : 0.2f * e0;
            e1 = e1 > 0.f ? e1 : 0.2f * e1;
            bool m0 = (m >> i0) & 1ull;
            bool m1 = (m >> i1) & 1ull;
            float mx = fmaxf(m0 ? e0 : NEGINF, m1 ? e1 : NEGINF);
#pragma unroll
            for (int off = 16; off > 0; off >>= 1)
                mx = fmaxf(mx, __shfl_xor_sync(0xffffffffu, mx, off));
            float p0 = m0 ? expf(e0 - mx) : 0.f;
            float p1 = m1 ? expf(e1 - mx) : 0.f;
            float ssum = p0 + p1;
#pragma unroll
            for (int off = 16; off > 0; off >>= 1)
                ssum += __shfl_xor_sync(0xffffffffu, ssum, off);
            float invs = 1.0f / ssum;
            alpha_s[i0 * AAL_STR + j] = p0 * invs;
            alpha_s[i1 * AAL_STR + j] = p1 * invs;
        }
        __syncthreads();

#pragma unroll 2
        for (int i = 0; i < NC; ++i) {
            float a[4];
#pragma unroll
            for (int r = 0; r < 4; ++r) a[r] = alpha_s[i * AAL_STR + tj + 16 * r];
            float xr[8];
#pragma unroll
            for (int s = 0; s < 8; ++s) xr[s] = wx_s[i * AWX_STR + tf + 32 * s];
#pragma unroll
            for (int r = 0; r < 4; ++r)
#pragma unroll
                for (int s = 0; s < 8; ++s) out_acc[r][s] += a[r] * xr[s];
        }
        __syncthreads();
    }

#pragma unroll
    for (int r = 0; r < 4; ++r) {
        int j = tj + 16 * r;
#pragma unroll
        for (int s = 0; s < 8; ++s) {
            int f = tf + 32 * s;
            float val = out_acc[r][s] * (1.0f / NH) + __ldg(gat_bias + f);
            out[(((size_t)b * NC + j) * NT + t) * ND + f] = val;
        }
    }
}

// ======================= launch =======================
extern "C" void kernel_launch(void* const* d_in, const int* in_sizes, int n_in,
                              void* d_out, int out_size) {
    const float* x          = (const float*)d_in[0];
    const float* static_adj = (const float*)d_in[1];
    const float* w_q        = (const float*)d_in[2];
    const float* w_k        = (const float*)d_in[3];
    const float* gat_lin    = (const float*)d_in[4];
    const float* att_src    = (const float*)d_in[5];
    const float* att_dst    = (const float*)d_in[6];
    const float* gat_bias   = (const float*)d_in[7];

    float* out = (float*)d_out;
    float* delta_out = out + (size_t)NB * NC * NT * ND;

    cudaFuncSetAttribute(k_gemm, cudaFuncAttributeMaxDynamicSharedMemorySize, SM_GEMM_TOTAL);
    cudaFuncSetAttribute(k_agg,  cudaFuncAttributeMaxDynamicSharedMemorySize, AGG_SMEM);
    cudaFuncSetAttribute(k_att,  cudaFuncAttributeMaxDynamicSharedMemorySize, ATT_SMEM);

    k_split<<<(NX_ELEMS + NG_ELEMS + 255) / 256, 256>>>(x, gat_lin);
    k_hmean<<<NB * NC, 256>>>(x);
    k_vsd<<<16, 256>>>(gat_lin, att_src, att_dst);
    k_adj<<<NB, 256>>>(static_adj, w_q, w_k, delta_out);
    k_topk<<<NB * NC, 32>>>();
    k_att<<<NB * NT, 256, ATT_SMEM>>>(x);
    k_gemm<<<1024, GEMM_THREADS, SM_GEMM_TOTAL>>>();
    k_agg<<<NB * NT, ATHREADS, AGG_SMEM>>>(gat_bias, out);
}

// round 5
// speedup vs baseline: 2.2230x; 1.3763x over previous
#include <cuda_runtime.h>
#include <cuda_bf16.h>
#include <math.h>
#include <stdint.h>
#include <string.h>

#define NB 16
#define NC 64
#define NT 128
#define ND 256
#define NH 8
#define NKD 32
#define NTOPK 8

// ======================= helpers =======================
__device__ __forceinline__ uint32_t smem_to_u32(const void* p) {
    uint32_t a;
    asm("{ .reg .u64 t; cvta.to.shared.u64 t, %1; cvt.u32.u64 %0, t; }" : "=r"(a) : "l"(p));
    return a;
}
#define CP_ASYNC16(sa, gp) \
    asm volatile("cp.async.cg.shared.global [%0], [%1], 16;" :: "r"(sa), "l"(gp))
#define CP_COMMIT() asm volatile("cp.async.commit_group;")
#define CP_WAIT0()  asm volatile("cp.async.wait_group 0;")

__device__ __forceinline__ void ldsm_x4(uint32_t* r, uint32_t addr) {
    asm volatile("ldmatrix.sync.aligned.m8n8.x4.shared.b16 {%0,%1,%2,%3}, [%4];"
                 : "=r"(r[0]), "=r"(r[1]), "=r"(r[2]), "=r"(r[3]) : "r"(addr));
}
__device__ __forceinline__ void ldsm_x4_t(uint32_t* r, uint32_t addr) {
    asm volatile("ldmatrix.sync.aligned.m8n8.x4.trans.shared.b16 {%0,%1,%2,%3}, [%4];"
                 : "=r"(r[0]), "=r"(r[1]), "=r"(r[2]), "=r"(r[3]) : "r"(addr));
}
__device__ __forceinline__ void mma16816(float* d, const uint32_t* a, const uint32_t* b) {
    asm volatile(
        "mma.sync.aligned.m16n8k16.row.col.f32.bf16.bf16.f32 "
        "{%0,%1,%2,%3}, {%4,%5,%6,%7}, {%8,%9}, {%0,%1,%2,%3};"
        : "+f"(d[0]), "+f"(d[1]), "+f"(d[2]), "+f"(d[3])
        : "r"(a[0]), "r"(a[1]), "r"(a[2]), "r"(a[3]), "r"(b[0]), "r"(b[1]));
}
__device__ __forceinline__ uint32_t pack_split(float v) {
    __nv_bfloat16 h = __float2bfloat16(v);
    float r = v - __bfloat162float(h);
    __nv_bfloat16 lo = __float2bfloat16(r);
    uint16_t hb, lb;
    memcpy(&hb, &h, 2);
    memcpy(&lb, &lo, 2);
    return ((uint32_t)hb << 16) | lb;
}
__device__ __forceinline__ uint16_t bf16_bits(float v) {
    __nv_bfloat16 h = __float2bfloat16(v);
    uint16_t b; memcpy(&b, &h, 2);
    return b;
}
__device__ __forceinline__ float bf16_val(uint16_t b) {
    __nv_bfloat16 h; memcpy(&h, &b, 2);
    return __bfloat162float(h);
}

// ======================= device scratch =======================
__device__ float g_hmean[NB * NC * ND];
__device__ float g_q[NB * NC * NKD];
__device__ float g_k[NB * NC * NKD];
__device__ float g_adaptive[NB * NC * NC];
__device__ unsigned long long g_maskcol[NB * NC];
__device__ float g_vsrc[NH * ND];
__device__ float g_vdst[NH * ND];
__device__ __nv_bfloat16 g_xhi[NB * NC * NT * ND];
__device__ __nv_bfloat16 g_xlo[NB * NC * NT * ND];
__device__ __nv_bfloat16 g_ghi[NH * ND * ND];
__device__ __nv_bfloat16 g_glo[NH * ND * ND];
__device__ uint32_t g_wx[(size_t)NB * NC * NT * NH * ND]; // packed bf16 hi|lo
__device__ float g_as[NB * NT * NH * NC];
__device__ float g_ad[NB * NT * NH * NC];

// ======================= kernel: bf16 hi/lo split =======================
#define NX_ELEMS 33554432u
#define NG_ELEMS 524288u
__global__ void k_split(const float* __restrict__ x, const float* __restrict__ g) {
    size_t i = (size_t)blockIdx.x * blockDim.x + threadIdx.x;
    if (i >= (size_t)NX_ELEMS + NG_ELEMS) return;
    float v;
    __nv_bfloat16 *hp, *lp;
    size_t off;
    if (i < NX_ELEMS) { v = x[i]; hp = g_xhi; lp = g_xlo; off = i; }
    else { off = i - NX_ELEMS; v = g[off]; hp = g_ghi; lp = g_glo; }
    __nv_bfloat16 hi = __float2bfloat16(v);
    float r = v - __bfloat162float(hi);
    hp[off] = hi;
    lp[off] = __float2bfloat16(r);
}

// ======================= kernel: temporal mean =======================
__global__ void k_hmean(const float* __restrict__ x) {
    int bc = blockIdx.x;
    int d = threadIdx.x;
    const float* p = x + (size_t)bc * NT * ND + d;
    float s = 0.f;
#pragma unroll 8
    for (int t = 0; t < NT; ++t) s += p[(size_t)t * ND];
    g_hmean[bc * ND + d] = s * (1.0f / NT);
}

// ======================= kernel: v_src/v_dst =======================
__global__ void k_vsd(const float* __restrict__ gat_lin,
                      const float* __restrict__ att_src,
                      const float* __restrict__ att_dst) {
    int h = blockIdx.x & 7;
    int isdst = blockIdx.x >> 3;
    int d = threadIdx.x;
    const float* att = isdst ? att_dst : att_src;
    float acc = 0.f;
#pragma unroll 4
    for (int f = 0; f < ND; ++f)
        acc += att[h * ND + f] * gat_lin[((size_t)(h * ND + f)) * ND + d];
    (isdst ? g_vdst : g_vsrc)[h * ND + d] = acc;
}

// ======================= kernel: q/k projections (one block per (b,c)) =======================
__global__ __launch_bounds__(256)
void k_qk(const float* __restrict__ w_q, const float* __restrict__ w_k) {
    __shared__ float hs[ND];
    int blk = blockIdx.x;                 // b*64 + c
    int tid = threadIdx.x;
    hs[tid] = g_hmean[(size_t)blk * ND + tid];
    if (tid == 0) g_maskcol[blk] = 1ull << (blk & 63);  // self loop
    __syncthreads();
    int grp = tid >> 2, sub = tid & 3;    // 64 groups of 4
    int which = grp >> 5, kd = grp & 31;
    const float* w = (which ? w_k : w_q) + (size_t)kd * ND + sub * 64;
    const float* hr = hs + sub * 64;
    float acc = 0.f;
#pragma unroll
    for (int d = 0; d < 64; ++d) acc += hr[d] * w[d];
    acc += __shfl_xor_sync(0xffffffffu, acc, 1);
    acc += __shfl_xor_sync(0xffffffffu, acc, 2);
    if (sub == 0) (which ? g_k : g_q)[blk * NKD + kd] = acc;
}

// ======================= kernel: sim + tanh (64 blocks) =======================
__global__ __launch_bounds__(256)
void k_sim(const float* __restrict__ static_adj, float* __restrict__ delta_out) {
    __shared__ float qs[16 * NKD];
    __shared__ float ks_[NC * NKD];
    int b = blockIdx.x >> 2;
    int i0 = (blockIdx.x & 3) * 16;
    int tid = threadIdx.x;
    for (int it = tid; it < NC * NKD; it += 256) ks_[it] = g_k[b * NC * NKD + it];
    for (int it = tid; it < 16 * NKD; it += 256) qs[it] = g_q[b * NC * NKD + i0 * NKD + it];
    __syncthreads();
    const float inv = 0.17677669529663687f;
    for (int task = tid; task < 16 * NC; task += 256) {
        int i = task >> 6, j = task & 63;
        float acc = 0.f;
#pragma unroll
        for (int kd = 0; kd < NKD; ++kd) acc += qs[i * NKD + kd] * ks_[j * NKD + kd];
        float delta = tanhf(acc * inv);
        int gi = i0 + i;
        int idx = b * NC * NC + gi * NC + j;
        delta_out[idx] = delta;
        g_adaptive[idx] = static_adj[gi * NC + j] + delta;
    }
}

// ======================= kernel: top-k =======================
__global__ void k_topk() {
    int b = blockIdx.x / NC, i = blockIdx.x % NC;
    int lane = threadIdx.x;
    const float* row = g_adaptive + (size_t)(b * NC + i) * NC;
    float v0 = fabsf(row[lane]);
    float v1 = fabsf(row[lane + 32]);
    for (int s = 0; s < NTOPK; ++s) {
        float bv; int bj;
        if (v0 >= v1) { bv = v0; bj = lane; } else { bv = v1; bj = lane + 32; }
#pragma unroll
        for (int off = 16; off > 0; off >>= 1) {
            float ov = __shfl_xor_sync(0xffffffffu, bv, off);
            int   oj = __shfl_xor_sync(0xffffffffu, bj, off);
            if (ov > bv || (ov == bv && oj < bj)) { bv = ov; bj = oj; }
        }
        if (lane == 0) atomicOr(&g_maskcol[b * NC + bj], 1ull << i);
        if (bj == lane)      v0 = -1.0f;
        if (bj == lane + 32) v1 = -1.0f;
    }
}

// ======================= kernel: a_src/a_dst =======================
#define ATT_SMEM (64 * 264 * 4)
__global__ __launch_bounds__(256)
void k_att(const float* __restrict__ x) {
    extern __shared__ float xs[];
    int bt = blockIdx.x, b = bt >> 7, t = bt & 127;
    int tid = threadIdx.x;
    const float4* x4 = (const float4*)x;
    for (int it = tid; it < 4096; it += 256) {
        int c = it >> 6, q = it & 63;
        float4 v = x4[(((size_t)(b * NC + c) * NT) + t) * 64 + q];
        *(float4*)&xs[c * 264 + q * 4] = v;
    }
    __syncthreads();
    for (int task = tid; task < 1024; task += 256) {
        int c = task >> 4;
        int hh = task & 15;
        int h = hh & 7, sd = hh >> 3;
        const float* v = (sd ? g_vdst : g_vsrc) + h * ND;
        const float* xr = xs + c * 264;
        float acc = 0.f;
#pragma unroll 8
        for (int d = 0; d < ND; ++d) acc += xr[d] * v[d];
        (sd ? g_ad : g_as)[((size_t)bt * NH + h) * NC + c] = acc;
    }
}

// ======================= kernel: split-bf16 GEMM via mma.sync (HMMA) =======================
// WX[131072,2048] = X @ G^T as Xh*Gh + Xh*Gl + Xl*Gh ; output packed bf16 hi|lo
#define GEMM_THREADS 512
#define SMA_BYTES 131072
#define SMB_BYTES 65536
#define SM_GEMM_TOTAL (SMA_BYTES + SMB_BYTES)

__global__ __launch_bounds__(GEMM_THREADS, 1)
void k_gemm() {
    extern __shared__ char smem[];
    uint32_t sbA = smem_to_u32(smem);
    uint32_t sbB = sbA + SMA_BYTES;
    const int tid = threadIdx.x;
    const int w = tid >> 5, l = tid & 31;
    const size_t mtile = blockIdx.x;

    {
        const char* xh = (const char*)g_xhi;
        const char* xl = (const char*)g_xlo;
#pragma unroll
        for (int ii = 0; ii < 16; ++ii) {
            int it = tid + ii * GEMM_THREADS;
            int q = it & 7, r = (it >> 3) & 127, kb = (it >> 10) & 3, s = it >> 12;
            const char* gp = (s ? xl : xh) + ((mtile * 128 + r) * 512 + kb * 128 + q * 16);
            uint32_t sa = sbA + (uint32_t)((s * 4 + kb) * 16384 + r * 128 + ((q * 16) ^ ((r & 7) << 4)));
            CP_ASYNC16(sa, gp);
        }
    }
    {
        const char* gh = (const char*)g_ghi;
        const char* gl = (const char*)g_glo;
#pragma unroll
        for (int ii = 0; ii < 4; ++ii) {
            int it = tid + ii * GEMM_THREADS;
            int q = it & 7, r = (it >> 3) & 127, s = it >> 10;
            const char* gp = (s ? gl : gh) + ((size_t)r * 512 + q * 16);
            uint32_t sa = sbB + (uint32_t)(s * 16384 + r * 128 + ((q * 16) ^ ((r & 7) << 4)));
            CP_ASYNC16(sa, gp);
        }
    }
    CP_COMMIT();
    CP_WAIT0();
    __syncthreads();

    const int mbase = (w & 3) * 32;
    const int nbase = (w >> 2) * 32;
    int aoff[2]; uint32_t akx[2];
#pragma unroll
    for (int mt = 0; mt < 2; ++mt) {
        int r = mbase + mt * 16 + (l & 15);
        aoff[mt] = r * 128;
        akx[mt] = (uint32_t)((r & 7) << 4);
    }
    const uint32_t akoff = (uint32_t)((l >> 4) * 16);
    int boff[2]; uint32_t bkx[2];
#pragma unroll
    for (int p = 0; p < 2; ++p) {
        int r = nbase + p * 16 + (l & 7) + (l >> 4) * 8;
        boff[p] = r * 128;
        bkx[p] = (uint32_t)((r & 7) << 4);
    }
    const uint32_t bkoff = (uint32_t)(((l >> 3) & 1) * 16);

    float acc[2][4][4];
#pragma unroll
    for (int mt = 0; mt < 2; ++mt)
#pragma unroll
        for (int g = 0; g < 4; ++g)
#pragma unroll
            for (int q = 0; q < 4; ++q) acc[mt][g][q] = 0.f;

    const char* ghp = (const char*)g_ghi;
    const char* glp = (const char*)g_glo;
    int buf = 0;

    for (int nt = 0; nt < 16; ++nt) {
        for (int kb = 0; kb < 4; ++kb) {
            const int have_next = !(nt == 15 && kb == 3);
            if (have_next) {
                int nn = nt + (kb == 3);
                int nk = (kb + 1) & 3;
                int b2 = buf ^ 1;
#pragma unroll
                for (int ii = 0; ii < 4; ++ii) {
                    int it = tid + ii * GEMM_THREADS;
                    int q = it & 7, r = (it >> 3) & 127, s = it >> 10;
                    const char* gp = (s ? glp : ghp) + ((size_t)(nn * 128 + r) * 512 + nk * 128 + q * 16);
                    uint32_t sa = sbB + (uint32_t)((b2 * 2 + s) * 16384 + r * 128 + ((q * 16) ^ ((r & 7) << 4)));
                    CP_ASYNC16(sa, gp);
                }
                CP_COMMIT();
            }

            const uint32_t pAh = sbA + (uint32_t)((0 * 4 + kb) * 16384);
            const uint32_t pAl = sbA + (uint32_t)((1 * 4 + kb) * 16384);
            const uint32_t pBh = sbB + (uint32_t)((buf * 2 + 0) * 16384);
            const uint32_t pBl = sbB + (uint32_t)((buf * 2 + 1) * 16384);
#pragma unroll
            for (int ks = 0; ks < 4; ++ks) {
                uint32_t ah[2][4], al[2][4], bh[2][4], bl[2][4];
#pragma unroll
                for (int mt = 0; mt < 2; ++mt) {
                    uint32_t kbyte = ((uint32_t)(ks * 32) + akoff) ^ akx[mt];
                    ldsm_x4(ah[mt], pAh + aoff[mt] + kbyte);
                    ldsm_x4(al[mt], pAl + aoff[mt] + kbyte);
                }
#pragma unroll
                for (int p = 0; p < 2; ++p) {
                    uint32_t kbyte = ((uint32_t)(ks * 32) + bkoff) ^ bkx[p];
                    ldsm_x4(bh[p], pBh + boff[p] + kbyte);
                    ldsm_x4(bl[p], pBl + boff[p] + kbyte);
                }
#pragma unroll
                for (int mt = 0; mt < 2; ++mt)
#pragma unroll
                    for (int g = 0; g < 4; ++g) {
                        const int p = g >> 1, o = (g & 1) * 2;
                        mma16816(acc[mt][g], ah[mt], &bh[p][o]);
                        mma16816(acc[mt][g], ah[mt], &bl[p][o]);
                        mma16816(acc[mt][g], al[mt], &bh[p][o]);
                    }
            }

            if (have_next) CP_WAIT0();
            __syncthreads();
            buf ^= 1;
        }

        // ---- epilogue: pack bf16 hi/lo into g_wx ----
        {
            size_t r0 = mtile * 128 + mbase + (l >> 2);
            int c0 = nt * 128 + nbase + (l & 3) * 2;
#pragma unroll
            for (int mt = 0; mt < 2; ++mt) {
#pragma unroll
                for (int g = 0; g < 4; ++g) {
                    uint32_t* dst = g_wx + (r0 + mt * 16) * 2048 + c0 + g * 8;
                    uint2 v0 = make_uint2(pack_split(acc[mt][g][0]), pack_split(acc[mt][g][1]));
                    uint2 v1 = make_uint2(pack_split(acc[mt][g][2]), pack_split(acc[mt][g][3]));
                    *(uint2*)dst = v0;
                    *(uint2*)(dst + 8 * 2048) = v1;
                    acc[mt][g][0] = acc[mt][g][1] = acc[mt][g][2] = acc[mt][g][3] = 0.f;
                }
            }
        }
    }
}

// ======================= kernel: aggregation via HMMA =======================
// per (b,t): out[j,f] = (1/H) sum_h (alpha_h^T @ wx_h)[j,f] + bias[f]
#define ATHREADS 512
#define WXH_OFF 0
#define WXL_OFF 33792
#define ALH_OFF 67584
#define ALL_OFF 76800
#define AS_OFF  86016
#define AD_OFF  86272
#define AGG_SMEM 86528

__global__ __launch_bounds__(ATHREADS, 1)
void k_agg(const float* __restrict__ gat_bias, float* __restrict__ out) {
    extern __shared__ char smc[];
    uint32_t sb = smem_to_u32(smc);
    uint16_t* wxh = (uint16_t*)(smc + WXH_OFF);   // [i=64][f stride 264]
    uint16_t* wxl = (uint16_t*)(smc + WXL_OFF);
    uint16_t* alh = (uint16_t*)(smc + ALH_OFF);   // [j=64][i stride 72]
    uint16_t* allo = (uint16_t*)(smc + ALL_OFF);
    float* as_s = (float*)(smc + AS_OFF);
    float* ad_s = (float*)(smc + AD_OFF);

    int bt = blockIdx.x, b = bt >> 7, t = bt & 127;
    int tid = threadIdx.x;
    int w = tid >> 5, l = tid & 31;
    int mw = w & 1, nw = w >> 1;

    unsigned long long msk[4];
#pragma unroll
    for (int jj = 0; jj < 4; ++jj) msk[jj] = g_maskcol[b * NC + w * 4 + jj];

    // ldsm address invariants (bytes)
    const uint32_t aoffA = (uint32_t)(((mw * 32 + (l & 15)) * 72 + (l >> 4) * 8) * 2);
    const uint32_t boffB = (uint32_t)((((l & 7) + ((l >> 3) & 1) * 8) * 264 + nw * 32 + (l >> 4) * 8) * 2);

    float acc[2][4][4];
#pragma unroll
    for (int mt = 0; mt < 2; ++mt)
#pragma unroll
        for (int q = 0; q < 4; ++q)
#pragma unroll
            for (int r = 0; r < 4; ++r) acc[mt][q][r] = 0.f;

    const float NEGINF = __int_as_float(0xff800000);
    const uint4* wp = (const uint4*)g_wx;

    for (int h = 0; h < NH; ++h) {
        // ---- stage wx_h (packed hi|lo) into split smem buffers ----
        for (int it = tid; it < 4096; it += ATHREADS) {
            int c = it >> 6, q = it & 63;
            uint4 u = wp[(((size_t)(b * NC + c) * NT) + t) * 512 + h * 64 + q];
            uint32_t h01 = (u.x >> 16) | (u.y & 0xffff0000u);
            uint32_t l01 = (u.x & 0xffffu) | (u.y << 16);
            uint32_t h23 = (u.z >> 16) | (u.w & 0xffff0000u);
            uint32_t l23 = (u.z & 0xffffu) | (u.w << 16);
            *(uint2*)(wxh + c * 264 + q * 4) = make_uint2(h01, h23);
            *(uint2*)(wxl + c * 264 + q * 4) = make_uint2(l01, l23);
        }
        if (tid < 64) as_s[tid] = g_as[((size_t)bt * NH + h) * NC + tid];
        else if (tid < 128) ad_s[tid - 64] = g_ad[((size_t)bt * NH + h) * NC + (tid - 64)];
        __syncthreads();

        // ---- masked softmax, write alpha^T as bf16 hi/lo [j][i] ----
#pragma unroll
        for (int jj = 0; jj < 4; ++jj) {
            int j = w * 4 + jj;
            unsigned long long m = msk[jj];
            float adj = ad_s[j];
            int i0 = l, i1 = l + 32;
            float e0 = as_s[i0] + adj;
            float e1 = as_s[i1] + adj;
            e0 = e0 > 0.f ? e0 : 0.2f * e0;
            e1 = e1 > 0.f ? e1 : 0.2f * e1;
            bool m0 = (m >> i0) & 1ull;
            bool m1 = (m >> i1) & 1ull;
            float mx = fmaxf(m0 ? e0 : NEGINF, m1 ? e1 : NEGINF);
#pragma unroll
            for (int off = 16; off > 0; off >>= 1)
                mx = fmaxf(mx, __shfl_xor_sync(0xffffffffu, mx, off));
            float p0 = m0 ? expf(e0 - mx) : 0.f;
            float p1 = m1 ? expf(e1 - mx) : 0.f;
            float ssum = p0 + p1;
#pragma unroll
            for (int off = 16; off > 0; off >>= 1)
                ssum += __shfl_xor_sync(0xffffffffu, ssum, off);
            float invs = 1.0f / ssum;
            float a0 = p0 * invs, a1 = p1 * invs;
            uint16_t h0 = bf16_bits(a0);
            uint16_t h1 = bf16_bits(a1);
            alh[j * 72 + i0] = h0;
            alh[j * 72 + i1] = h1;
            allo[j * 72 + i0] = bf16_bits(a0 - bf16_val(h0));
            allo[j * 72 + i1] = bf16_bits(a1 - bf16_val(h1));
        }
        __syncthreads();

        // ---- HMMA: acc[j,f] += alpha^T @ wx (3 split terms) ----
#pragma unroll
        for (int ks = 0; ks < 4; ++ks) {
            uint32_t ah[2][4], al[2][4], bh[2][4], bl[2][4];
#pragma unroll
            for (int mt = 0; mt < 2; ++mt) {
                uint32_t ab = aoffA + (uint32_t)(mt * 2304 + ks * 32);
                ldsm_x4(ah[mt], sb + ALH_OFF + ab);
                ldsm_x4(al[mt], sb + ALL_OFF + ab);
            }
#pragma unroll
            for (int nt = 0; nt < 2; ++nt) {
                uint32_t bb = boffB + (uint32_t)(nt * 32 + ks * 8448);
                ldsm_x4_t(bh[nt], sb + WXH_OFF + bb);
                ldsm_x4_t(bl[nt], sb + WXL_OFF + bb);
            }
#pragma unroll
            for (int mt = 0; mt < 2; ++mt)
#pragma unroll
                for (int q = 0; q < 4; ++q) {
                    const int nt = q >> 1, o = (q & 1) * 2;
                    mma16816(acc[mt][q], ah[mt], &bh[nt][o]);
                    mma16816(acc[mt][q], ah[mt], &bl[nt][o]);
                    mma16816(acc[mt][q], al[mt], &bh[nt][o]);
                }
        }
        __syncthreads();
    }

    // ---- epilogue: mean heads + bias ----
    const float inv8 = 0.125f;
#pragma unroll
    for (int mt = 0; mt < 2; ++mt) {
        int j0 = mw * 32 + mt * 16 + (l >> 2);
#pragma unroll
        for (int q = 0; q < 4; ++q) {
            int f = nw * 32 + q * 8 + (l & 3) * 2;
            float b0 = __ldg(gat_bias + f), b1 = __ldg(gat_bias + f + 1);
            float2 v0 = make_float2(acc[mt][q][0] * inv8 + b0, acc[mt][q][1] * inv8 + b1);
            float2 v1 = make_float2(acc[mt][q][2] * inv8 + b0, acc[mt][q][3] * inv8 + b1);
            *(float2*)(out + (((size_t)b * NC + j0) * NT + t) * ND + f) = v0;
            *(float2*)(out + (((size_t)b * NC + j0 + 8) * NT + t) * ND + f) = v1;
        }
    }
}

// ======================= launch =======================
extern "C" void kernel_launch(void* const* d_in, const int* in_sizes, int n_in,
                              void* d_out, int out_size) {
    const float* x          = (const float*)d_in[0];
    const float* static_adj = (const float*)d_in[1];
    const float* w_q        = (const float*)d_in[2];
    const float* w_k        = (const float*)d_in[3];
    const float* gat_lin    = (const float*)d_in[4];
    const float* att_src    = (const float*)d_in[5];
    const float* att_dst    = (const float*)d_in[6];
    const float* gat_bias   = (const float*)d_in[7];

    float* out = (float*)d_out;
    float* delta_out = out + (size_t)NB * NC * NT * ND;

    cudaFuncSetAttribute(k_gemm, cudaFuncAttributeMaxDynamicSharedMemorySize, SM_GEMM_TOTAL);
    cudaFuncSetAttribute(k_agg,  cudaFuncAttributeMaxDynamicSharedMemorySize, AGG_SMEM);
    cudaFuncSetAttribute(k_att,  cudaFuncAttributeMaxDynamicSharedMemorySize, ATT_SMEM);

    k_split<<<(NX_ELEMS + NG_ELEMS + 255) / 256, 256>>>(x, gat_lin);
    k_hmean<<<NB * NC, 256>>>(x);
    k_vsd<<<16, 256>>>(gat_lin, att_src, att_dst);
    k_qk<<<NB * NC, 256>>>(w_q, w_k);
    k_sim<<<NB * 4, 256>>>(static_adj, delta_out);
    k_topk<<<NB * NC, 32>>>();
    k_att<<<NB * NT, 256, ATT_SMEM>>>(x);
    k_gemm<<<1024, GEMM_THREADS, SM_GEMM_TOTAL>>>();
    k_agg<<<NB * NT, ATHREADS, AGG_SMEM>>>(gat_bias, out);
}

// round 6
// speedup vs baseline: 2.3342x; 1.0500x over previous
#include <cuda_runtime.h>
#include <cuda_bf16.h>
#include <math.h>
#include <stdint.h>
#include <string.h>

#define NB 16
#define NC 64
#define NT 128
#define ND 256
#define NH 8
#define NKD 32
#define NTOPK 8

// ======================= helpers =======================
__device__ __forceinline__ uint32_t smem_to_u32(const void* p) {
    uint32_t a;
    asm("{ .reg .u64 t; cvta.to.shared.u64 t, %1; cvt.u32.u64 %0, t; }" : "=r"(a) : "l"(p));
    return a;
}
#define CP_ASYNC16(sa, gp) \
    asm volatile("cp.async.cg.shared.global [%0], [%1], 16;" :: "r"(sa), "l"(gp))
#define CP_COMMIT() asm volatile("cp.async.commit_group;")
#define CP_WAIT0()  asm volatile("cp.async.wait_group 0;")

__device__ __forceinline__ void ldsm_x4(uint32_t* r, uint32_t addr) {
    asm volatile("ldmatrix.sync.aligned.m8n8.x4.shared.b16 {%0,%1,%2,%3}, [%4];"
                 : "=r"(r[0]), "=r"(r[1]), "=r"(r[2]), "=r"(r[3]) : "r"(addr));
}
__device__ __forceinline__ void ldsm_x4_t(uint32_t* r, uint32_t addr) {
    asm volatile("ldmatrix.sync.aligned.m8n8.x4.trans.shared.b16 {%0,%1,%2,%3}, [%4];"
                 : "=r"(r[0]), "=r"(r[1]), "=r"(r[2]), "=r"(r[3]) : "r"(addr));
}
__device__ __forceinline__ void mma16816(float* d, const uint32_t* a, const uint32_t* b) {
    asm volatile(
        "mma.sync.aligned.m16n8k16.row.col.f32.bf16.bf16.f32 "
        "{%0,%1,%2,%3}, {%4,%5,%6,%7}, {%8,%9}, {%0,%1,%2,%3};"
        : "+f"(d[0]), "+f"(d[1]), "+f"(d[2]), "+f"(d[3])
        : "r"(a[0]), "r"(a[1]), "r"(a[2]), "r"(a[3]), "r"(b[0]), "r"(b[1]));
}
__device__ __forceinline__ uint32_t pack_split(float v) {
    __nv_bfloat16 h = __float2bfloat16(v);
    float r = v - __bfloat162float(h);
    __nv_bfloat16 lo = __float2bfloat16(r);
    uint16_t hb, lb;
    memcpy(&hb, &h, 2);
    memcpy(&lb, &lo, 2);
    return ((uint32_t)hb << 16) | lb;
}
__device__ __forceinline__ uint16_t bf16_bits(float v) {
    __nv_bfloat16 h = __float2bfloat16(v);
    uint16_t b; memcpy(&b, &h, 2);
    return b;
}
__device__ __forceinline__ float bf16_val(uint16_t b) {
    __nv_bfloat16 h; memcpy(&h, &b, 2);
    return __bfloat162float(h);
}

// ======================= device scratch =======================
__device__ float g_hmean[NB * NC * ND];
__device__ float g_q[NB * NC * NKD];
__device__ float g_k[NB * NC * NKD];
__device__ float g_adaptive[NB * NC * NC];
__device__ unsigned long long g_maskcol[NB * NC];
__device__ float g_vsrc[NH * ND];
__device__ float g_vdst[NH * ND];
__device__ __nv_bfloat16 g_ghi[NH * ND * ND];
__device__ __nv_bfloat16 g_glo[NH * ND * ND];
__device__ uint32_t g_wx[(size_t)NB * NT * NC * NH * ND]; // [b][t][c][2048] packed bf16 hi|lo
__device__ float g_as[NB * NT * NH * NC];
__device__ float g_ad[NB * NT * NH * NC];

// ======================= kernel: G hi/lo split (G only) =======================
#define NG_ELEMS 524288u
__global__ void k_splitG(const float* __restrict__ g) {
    uint32_t i = blockIdx.x * blockDim.x + threadIdx.x;
    if (i >= NG_ELEMS) return;
    float v = g[i];
    __nv_bfloat16 hi = __float2bfloat16(v);
    float r = v - __bfloat162float(hi);
    g_ghi[i] = hi;
    g_glo[i] = __float2bfloat16(r);
}

// ======================= kernel: temporal mean =======================
__global__ void k_hmean(const float* __restrict__ x) {
    int bc = blockIdx.x;
    int d = threadIdx.x;
    const float* p = x + (size_t)bc * NT * ND + d;
    float s = 0.f;
#pragma unroll 8
    for (int t = 0; t < NT; ++t) s += p[(size_t)t * ND];
    g_hmean[bc * ND + d] = s * (1.0f / NT);
}

// ======================= kernel: v_src/v_dst =======================
__global__ void k_vsd(const float* __restrict__ gat_lin,
                      const float* __restrict__ att_src,
                      const float* __restrict__ att_dst) {
    int h = blockIdx.x & 7;
    int isdst = blockIdx.x >> 3;
    int d = threadIdx.x;
    const float* att = isdst ? att_dst : att_src;
    float acc = 0.f;
#pragma unroll 4
    for (int f = 0; f < ND; ++f)
        acc += att[h * ND + f] * gat_lin[((size_t)(h * ND + f)) * ND + d];
    (isdst ? g_vdst : g_vsrc)[h * ND + d] = acc;
}

// ======================= kernel: q/k projections (8 bc rows per block) =======================
__global__ __launch_bounds__(256)
void k_qk(const float* __restrict__ w_q, const float* __restrict__ w_k) {
    __shared__ float hs[8 * ND];
    int blk = blockIdx.x;               // 128 blocks
    int tid = threadIdx.x;
    for (int it = tid; it < 8 * ND; it += 256) hs[it] = g_hmean[(size_t)blk * 8 * ND + it];
    if (tid < 8) g_maskcol[blk * 8 + tid] = 1ull << ((blk * 8 + tid) & 63);
    __syncthreads();
#pragma unroll
    for (int k = 0; k < 2; ++k) {
        int o = tid + k * 256;          // 0..511
        int bcL = o >> 6, rem = o & 63;
        int which = rem >> 5, kd = rem & 31;
        const float4* w4 = (const float4*)((which ? w_k : w_q) + (size_t)kd * ND);
        const float* hr = hs + bcL * ND;
        float acc = 0.f;
#pragma unroll 8
        for (int d4 = 0; d4 < 64; ++d4) {
            float4 wv = __ldg(w4 + d4);
            acc += hr[d4 * 4] * wv.x + hr[d4 * 4 + 1] * wv.y
                 + hr[d4 * 4 + 2] * wv.z + hr[d4 * 4 + 3] * wv.w;
        }
        (which ? g_k : g_q)[(blk * 8 + bcL) * NKD + kd] = acc;
    }
}

// ======================= kernel: sim + tanh =======================
__global__ __launch_bounds__(256)
void k_sim(const float* __restrict__ static_adj, float* __restrict__ delta_out) {
    __shared__ float qs[16 * NKD];
    __shared__ float ks_[NC * NKD];
    int b = blockIdx.x >> 2;
    int i0 = (blockIdx.x & 3) * 16;
    int tid = threadIdx.x;
    for (int it = tid; it < NC * NKD; it += 256) ks_[it] = g_k[b * NC * NKD + it];
    for (int it = tid; it < 16 * NKD; it += 256) qs[it] = g_q[b * NC * NKD + i0 * NKD + it];
    __syncthreads();
    const float inv = 0.17677669529663687f;
    for (int task = tid; task < 16 * NC; task += 256) {
        int i = task >> 6, j = task & 63;
        float acc = 0.f;
#pragma unroll
        for (int kd = 0; kd < NKD; ++kd) acc += qs[i * NKD + kd] * ks_[j * NKD + kd];
        float delta = tanhf(acc * inv);
        int gi = i0 + i;
        int idx = b * NC * NC + gi * NC + j;
        delta_out[idx] = delta;
        g_adaptive[idx] = static_adj[gi * NC + j] + delta;
    }
}

// ======================= kernel: top-k =======================
__global__ void k_topk() {
    int b = blockIdx.x / NC, i = blockIdx.x % NC;
    int lane = threadIdx.x;
    const float* row = g_adaptive + (size_t)(b * NC + i) * NC;
    float v0 = fabsf(row[lane]);
    float v1 = fabsf(row[lane + 32]);
    for (int s = 0; s < NTOPK; ++s) {
        float bv; int bj;
        if (v0 >= v1) { bv = v0; bj = lane; } else { bv = v1; bj = lane + 32; }
#pragma unroll
        for (int off = 16; off > 0; off >>= 1) {
            float ov = __shfl_xor_sync(0xffffffffu, bv, off);
            int   oj = __shfl_xor_sync(0xffffffffu, bj, off);
            if (ov > bv || (ov == bv && oj < bj)) { bv = ov; bj = oj; }
        }
        if (lane == 0) atomicOr(&g_maskcol[b * NC + bj], 1ull << i);
        if (bj == lane)      v0 = -1.0f;
        if (bj == lane + 32) v1 = -1.0f;
    }
}

// ======================= kernel: a_src/a_dst =======================
#define ATT_SMEM (64 * 264 * 4)
__global__ __launch_bounds__(256)
void k_att(const float* __restrict__ x) {
    extern __shared__ float xs[];
    int bt = blockIdx.x, b = bt >> 7, t = bt & 127;
    int tid = threadIdx.x;
    const float4* x4 = (const float4*)x;
    for (int it = tid; it < 4096; it += 256) {
        int c = it >> 6, q = it & 63;
        float4 v = x4[(((size_t)(b * NC + c) * NT) + t) * 64 + q];
        *(float4*)&xs[c * 264 + q * 4] = v;
    }
    __syncthreads();
    for (int task = tid; task < 1024; task += 256) {
        int c = task >> 4;
        int hh = task & 15;
        int h = hh & 7, sd = hh >> 3;
        const float* v = (sd ? g_vdst : g_vsrc) + h * ND;
        const float* xr = xs + c * 264;
        float acc = 0.f;
#pragma unroll 8
        for (int d = 0; d < ND; ++d) acc += xr[d] * v[d];
        (sd ? g_ad : g_as)[((size_t)bt * NH + h) * NC + c] = acc;
    }
}

// ======================= kernel: split-bf16 GEMM via mma.sync (HMMA) =======================
// WX = X @ G^T as Xh*Gh + Xh*Gl + Xl*Gh ; X split done in-kernel; out packed bf16 hi|lo
#define GEMM_THREADS 512
#define SMA_BYTES 131072
#define SMB_BYTES 65536
#define SM_GEMM_TOTAL (SMA_BYTES + SMB_BYTES)

__global__ __launch_bounds__(GEMM_THREADS, 1)
void k_gemm(const float* __restrict__ x) {
    extern __shared__ char smem[];
    uint32_t sbA = smem_to_u32(smem);
    uint32_t sbB = sbA + SMA_BYTES;
    const int tid = threadIdx.x;
    const int w = tid >> 5, l = tid & 31;
    const size_t mtile = blockIdx.x;

    // ---- prologue: stage fp32 X chunks and split to bf16 hi/lo in A region ----
    for (int kb2 = 0; kb2 < 4; ++kb2) {
        char* stg = smem + SMA_BYTES + (kb2 & 1) * 32768;
        uint32_t stg_u = sbB + (uint32_t)((kb2 & 1) * 32768);
        // cp.async 32KB fp32: 128 rows x 64 floats
#pragma unroll
        for (int ii = 0; ii < 4; ++ii) {
            int it = tid + ii * GEMM_THREADS;   // 0..2047
            int r = it >> 4, q = it & 15;
            const float* gp = x + ((mtile * 128 + r) * 256 + kb2 * 64 + q * 4);
            CP_ASYNC16(stg_u + (uint32_t)(r * 256 + q * 16), gp);
        }
        CP_COMMIT();
        CP_WAIT0();
        __syncthreads();
        // convert: 1024 granules of 8 floats -> 16B hi + 16B lo (swizzled)
#pragma unroll
        for (int k = 0; k < 2; ++k) {
            int it = tid + k * GEMM_THREADS;    // 0..1023
            int r = it >> 3, gnum = it & 7;
            const float* src = (const float*)(stg + r * 256 + gnum * 32);
            uint32_t hw[4], lw[4];
#pragma unroll
            for (int p = 0; p < 4; ++p) {
                float v0 = src[2 * p], v1 = src[2 * p + 1];
                uint16_t h0 = bf16_bits(v0), h1 = bf16_bits(v1);
                uint16_t l0 = bf16_bits(v0 - bf16_val(h0));
                uint16_t l1 = bf16_bits(v1 - bf16_val(h1));
                hw[p] = (uint32_t)h0 | ((uint32_t)h1 << 16);
                lw[p] = (uint32_t)l0 | ((uint32_t)l1 << 16);
            }
            uint32_t off = (uint32_t)(r * 128 + ((gnum * 16) ^ ((r & 7) << 4)));
            *(uint4*)(smem + (0 * 4 + kb2) * 16384 + off) = make_uint4(hw[0], hw[1], hw[2], hw[3]);
            *(uint4*)(smem + (1 * 4 + kb2) * 16384 + off) = make_uint4(lw[0], lw[1], lw[2], lw[3]);
        }
        __syncthreads();
    }

    // ---- first B chunk (nt=0, kb=0) into buf 0 ----
    {
        const char* gh = (const char*)g_ghi;
        const char* gl = (const char*)g_glo;
#pragma unroll
        for (int ii = 0; ii < 4; ++ii) {
            int it = tid + ii * GEMM_THREADS;
            int q = it & 7, r = (it >> 3) & 127, s = it >> 10;
            const char* gp = (s ? gl : gh) + ((size_t)r * 512 + q * 16);
            uint32_t sa = sbB + (uint32_t)(s * 16384 + r * 128 + ((q * 16) ^ ((r & 7) << 4)));
            CP_ASYNC16(sa, gp);
        }
    }
    CP_COMMIT();
    CP_WAIT0();
    __syncthreads();

    const int mbase = (w & 3) * 32;
    const int nbase = (w >> 2) * 32;
    int aoff[2]; uint32_t akx[2];
#pragma unroll
    for (int mt = 0; mt < 2; ++mt) {
        int r = mbase + mt * 16 + (l & 15);
        aoff[mt] = r * 128;
        akx[mt] = (uint32_t)((r & 7) << 4);
    }
    const uint32_t akoff = (uint32_t)((l >> 4) * 16);
    int boff[2]; uint32_t bkx[2];
#pragma unroll
    for (int p = 0; p < 2; ++p) {
        int r = nbase + p * 16 + (l & 7) + (l >> 4) * 8;
        boff[p] = r * 128;
        bkx[p] = (uint32_t)((r & 7) << 4);
    }
    const uint32_t bkoff = (uint32_t)(((l >> 3) & 1) * 16);

    float acc[2][4][4];
#pragma unroll
    for (int mt = 0; mt < 2; ++mt)
#pragma unroll
        for (int g = 0; g < 4; ++g)
#pragma unroll
            for (int q = 0; q < 4; ++q) acc[mt][g][q] = 0.f;

    const char* ghp = (const char*)g_ghi;
    const char* glp = (const char*)g_glo;
    int buf = 0;

    for (int nt = 0; nt < 16; ++nt) {
        for (int kb = 0; kb < 4; ++kb) {
            const int have_next = !(nt == 15 && kb == 3);
            if (have_next) {
                int nn = nt + (kb == 3);
                int nk = (kb + 1) & 3;
                int b2 = buf ^ 1;
#pragma unroll
                for (int ii = 0; ii < 4; ++ii) {
                    int it = tid + ii * GEMM_THREADS;
                    int q = it & 7, r = (it >> 3) & 127, s = it >> 10;
                    const char* gp = (s ? glp : ghp) + ((size_t)(nn * 128 + r) * 512 + nk * 128 + q * 16);
                    uint32_t sa = sbB + (uint32_t)((b2 * 2 + s) * 16384 + r * 128 + ((q * 16) ^ ((r & 7) << 4)));
                    CP_ASYNC16(sa, gp);
                }
                CP_COMMIT();
            }

            const uint32_t pAh = sbA + (uint32_t)((0 * 4 + kb) * 16384);
            const uint32_t pAl = sbA + (uint32_t)((1 * 4 + kb) * 16384);
            const uint32_t pBh = sbB + (uint32_t)((buf * 2 + 0) * 16384);
            const uint32_t pBl = sbB + (uint32_t)((buf * 2 + 1) * 16384);
#pragma unroll
            for (int ks = 0; ks < 4; ++ks) {
                uint32_t ah[2][4], al[2][4], bh[2][4], bl[2][4];
#pragma unroll
                for (int mt = 0; mt < 2; ++mt) {
                    uint32_t kbyte = ((uint32_t)(ks * 32) + akoff) ^ akx[mt];
                    ldsm_x4(ah[mt], pAh + aoff[mt] + kbyte);
                    ldsm_x4(al[mt], pAl + aoff[mt] + kbyte);
                }
#pragma unroll
                for (int p = 0; p < 2; ++p) {
                    uint32_t kbyte = ((uint32_t)(ks * 32) + bkoff) ^ bkx[p];
                    ldsm_x4(bh[p], pBh + boff[p] + kbyte);
                    ldsm_x4(bl[p], pBl + boff[p] + kbyte);
                }
#pragma unroll
                for (int mt = 0; mt < 2; ++mt)
#pragma unroll
                    for (int g = 0; g < 4; ++g) {
                        const int p = g >> 1, o = (g & 1) * 2;
                        mma16816(acc[mt][g], ah[mt], &bh[p][o]);
                        mma16816(acc[mt][g], ah[mt], &bl[p][o]);
                        mma16816(acc[mt][g], al[mt], &bh[p][o]);
                    }
            }

            if (have_next) CP_WAIT0();
            __syncthreads();
            buf ^= 1;
        }

        // ---- epilogue: pack bf16 hi/lo into g_wx [b][t][c][2048] ----
        {
            size_t r0 = mtile * 128 + mbase + (l >> 2);
            int c0 = nt * 128 + nbase + (l & 3) * 2;
#pragma unroll
            for (int mt = 0; mt < 2; ++mt) {
                size_t rr = r0 + mt * 16;   // X row = (b*64+c)*128 + t
                size_t wxrow = ((rr >> 13) * 128 + (rr & 127)) * 64 + ((rr >> 7) & 63);
                uint32_t* dst = g_wx + wxrow * 2048 + c0;
#pragma unroll
                for (int g = 0; g < 4; ++g) {
                    uint2 v0 = make_uint2(pack_split(acc[mt][g][0]), pack_split(acc[mt][g][1]));
                    uint2 v1 = make_uint2(pack_split(acc[mt][g][2]), pack_split(acc[mt][g][3]));
                    *(uint2*)(dst + g * 8) = v0;
                    *(uint2*)(dst + 512 * 2048 + g * 8) = v1;   // t+8 -> +8*64 rows
                    acc[mt][g][0] = acc[mt][g][1] = acc[mt][g][2] = acc[mt][g][3] = 0.f;
                }
            }
        }
    }
}

// ======================= kernel: aggregation via HMMA =======================
#define ATHREADS 512
#define WXH_OFF 0
#define WXL_OFF 33792
#define ALH_OFF 67584
#define ALL_OFF 76800
#define AS_OFF  86016
#define AD_OFF  86272
#define AGG_SMEM 86528

__global__ __launch_bounds__(ATHREADS, 1)
void k_agg(const float* __restrict__ gat_bias, float* __restrict__ out) {
    extern __shared__ char smc[];
    uint32_t sb = smem_to_u32(smc);
    uint16_t* wxh = (uint16_t*)(smc + WXH_OFF);   // [i=64][f stride 264]
    uint16_t* wxl = (uint16_t*)(smc + WXL_OFF);
    uint16_t* alh = (uint16_t*)(smc + ALH_OFF);   // [j=64][i stride 72]
    uint16_t* allo = (uint16_t*)(smc + ALL_OFF);
    float* as_s = (float*)(smc + AS_OFF);
    float* ad_s = (float*)(smc + AD_OFF);

    int bt = blockIdx.x, b = bt >> 7, t = bt & 127;
    int tid = threadIdx.x;
    int w = tid >> 5, l = tid & 31;
    int mw = w & 1, nw = w >> 1;

    unsigned long long msk[4];
#pragma unroll
    for (int jj = 0; jj < 4; ++jj) msk[jj] = g_maskcol[b * NC + w * 4 + jj];

    const uint32_t aoffA = (uint32_t)(((mw * 32 + (l & 15)) * 72 + (l >> 4) * 8) * 2);
    const uint32_t boffB = (uint32_t)((((l & 7) + ((l >> 3) & 1) * 8) * 264 + nw * 32 + (l >> 4) * 8) * 2);

    float acc[2][4][4];
#pragma unroll
    for (int mt = 0; mt < 2; ++mt)
#pragma unroll
        for (int q = 0; q < 4; ++q)
#pragma unroll
            for (int r = 0; r < 4; ++r) acc[mt][q][r] = 0.f;

    const float NEGINF = __int_as_float(0xff800000);
    const uint4* wp = (const uint4*)g_wx + (size_t)bt * 64 * 512;  // contiguous block

    for (int h = 0; h < NH; ++h) {
        for (int it = tid; it < 4096; it += ATHREADS) {
            int c = it >> 6, q = it & 63;
            uint4 u = wp[c * 512 + h * 64 + q];
            uint32_t h01 = (u.x >> 16) | (u.y & 0xffff0000u);
            uint32_t l01 = (u.x & 0xffffu) | (u.y << 16);
            uint32_t h23 = (u.z >> 16) | (u.w & 0xffff0000u);
            uint32_t l23 = (u.z & 0xffffu) | (u.w << 16);
            *(uint2*)(wxh + c * 264 + q * 4) = make_uint2(h01, h23);
            *(uint2*)(wxl + c * 264 + q * 4) = make_uint2(l01, l23);
        }
        if (tid < 64) as_s[tid] = g_as[((size_t)bt * NH + h) * NC + tid];
        else if (tid < 128) ad_s[tid - 64] = g_ad[((size_t)bt * NH + h) * NC + (tid - 64)];
        __syncthreads();

#pragma unroll
        for (int jj = 0; jj < 4; ++jj) {
            int j = w * 4 + jj;
            unsigned long long m = msk[jj];
            float adj = ad_s[j];
            int i0 = l, i1 = l + 32;
            float e0 = as_s[i0] + adj;
            float e1 = as_s[i1] + adj;
            e0 = e0 > 0.f ? e0 : 0.2f * e0;
            e1 = e1 > 0.f ? e1 : 0.2f * e1;
            bool m0 = (m >> i0) & 1ull;
            bool m1 = (m >> i1) & 1ull;
            float mx = fmaxf(m0 ? e0 : NEGINF, m1 ? e1 : NEGINF);
#pragma unroll
            for (int off = 16; off > 0; off >>= 1)
                mx = fmaxf(mx, __shfl_xor_sync(0xffffffffu, mx, off));
            float p0 = m0 ? expf(e0 - mx) : 0.f;
            float p1 = m1 ? expf(e1 - mx) : 0.f;
            float ssum = p0 + p1;
#pragma unroll
            for (int off = 16; off > 0; off >>= 1)
                ssum += __shfl_xor_sync(0xffffffffu, ssum, off);
            float invs = 1.0f / ssum;
            float a0 = p0 * invs, a1 = p1 * invs;
            uint16_t h0 = bf16_bits(a0);
            uint16_t h1 = bf16_bits(a1);
            alh[j * 72 + i0] = h0;
            alh[j * 72 + i1] = h1;
            allo[j * 72 + i0] = bf16_bits(a0 - bf16_val(h0));
            allo[j * 72 + i1] = bf16_bits(a1 - bf16_val(h1));
        }
        __syncthreads();

#pragma unroll
        for (int ks = 0; ks < 4; ++ks) {
            uint32_t ah[2][4], al[2][4], bh[2][4], bl[2][4];
#pragma unroll
            for (int mt = 0; mt < 2; ++mt) {
                uint32_t ab = aoffA + (uint32_t)(mt * 2304 + ks * 32);
                ldsm_x4(ah[mt], sb + ALH_OFF + ab);
                ldsm_x4(al[mt], sb + ALL_OFF + ab);
            }
#pragma unroll
            for (int nt = 0; nt < 2; ++nt) {
                uint32_t bb = boffB + (uint32_t)(nt * 32 + ks * 8448);
                ldsm_x4_t(bh[nt], sb + WXH_OFF + bb);
                ldsm_x4_t(bl[nt], sb + WXL_OFF + bb);
            }
#pragma unroll
            for (int mt = 0; mt < 2; ++mt)
#pragma unroll
                for (int q = 0; q < 4; ++q) {
                    const int nt = q >> 1, o = (q & 1) * 2;
                    mma16816(acc[mt][q], ah[mt], &bh[nt][o]);
                    mma16816(acc[mt][q], ah[mt], &bl[nt][o]);
                    mma16816(acc[mt][q], al[mt], &bh[nt][o]);
                }
        }
        __syncthreads();
    }

    const float inv8 = 0.125f;
#pragma unroll
    for (int mt = 0; mt < 2; ++mt) {
        int j0 = mw * 32 + mt * 16 + (l >> 2);
#pragma unroll
        for (int q = 0; q < 4; ++q) {
            int f = nw * 32 + q * 8 + (l & 3) * 2;
            float b0 = __ldg(gat_bias + f), b1 = __ldg(gat_bias + f + 1);
            float2 v0 = make_float2(acc[mt][q][0] * inv8 + b0, acc[mt][q][1] * inv8 + b1);
            float2 v1 = make_float2(acc[mt][q][2] * inv8 + b0, acc[mt][q][3] * inv8 + b1);
            *(float2*)(out + (((size_t)b * NC + j0) * NT + t) * ND + f) = v0;
            *(float2*)(out + (((size_t)b * NC + j0 + 8) * NT + t) * ND + f) = v1;
        }
    }
}

// ======================= launch =======================
extern "C" void kernel_launch(void* const* d_in, const int* in_sizes, int n_in,
                              void* d_out, int out_size) {
    const float* x          = (const float*)d_in[0];
    const float* static_adj = (const float*)d_in[1];
    const float* w_q        = (const float*)d_in[2];
    const float* w_k        = (const float*)d_in[3];
    const float* gat_lin    = (const float*)d_in[4];
    const float* att_src    = (const float*)d_in[5];
    const float* att_dst    = (const float*)d_in[6];
    const float* gat_bias   = (const float*)d_in[7];

    float* out = (float*)d_out;
    float* delta_out = out + (size_t)NB * NC * NT * ND;

    cudaFuncSetAttribute(k_gemm, cudaFuncAttributeMaxDynamicSharedMemorySize, SM_GEMM_TOTAL);
    cudaFuncSetAttribute(k_agg,  cudaFuncAttributeMaxDynamicSharedMemorySize, AGG_SMEM);
    cudaFuncSetAttribute(k_att,  cudaFuncAttributeMaxDynamicSharedMemorySize, ATT_SMEM);

    // order chosen so ncu (-s 5 -c 1) profiles k_gemm (6th launch)
    k_hmean<<<NB * NC, 256>>>(x);                              // 1
    k_vsd<<<16, 256>>>(gat_lin, att_src, att_dst);             // 2
    k_qk<<<NB * NC / 8, 256>>>(w_q, w_k);                      // 3
    k_sim<<<NB * 4, 256>>>(static_adj, delta_out);             // 4
    k_splitG<<<(NG_ELEMS + 255) / 256, 256>>>(gat_lin);        // 5
    k_gemm<<<1024, GEMM_THREADS, SM_GEMM_TOTAL>>>(x);          // 6
    k_topk<<<NB * NC, 32>>>();                                 // 7
    k_att<<<NB * NT, 256, ATT_SMEM>>>(x);                      // 8
    k_agg<<<NB * NT, ATHREADS, AGG_SMEM>>>(gat_bias, out);     // 9
}

// round 7
// speedup vs baseline: 3.1607x; 1.3541x over previous
#include <cuda_runtime.h>
#include <cuda_bf16.h>
#include <math.h>
#include <stdint.h>
#include <string.h>

#define NB 16
#define NC 64
#define NT 128
#define ND 256
#define NH 8
#define NKD 32
#define NTOPK 8

// ======================= helpers =======================
__device__ __forceinline__ uint32_t smem_to_u32(const void* p) {
    uint32_t a;
    asm("{ .reg .u64 t; cvta.to.shared.u64 t, %1; cvt.u32.u64 %0, t; }" : "=r"(a) : "l"(p));
    return a;
}
#define CP_ASYNC16(sa, gp) \
    asm volatile("cp.async.cg.shared.global [%0], [%1], 16;" :: "r"(sa), "l"(gp))
#define CP_COMMIT() asm volatile("cp.async.commit_group;")
#define CP_WAIT0()  asm volatile("cp.async.wait_group 0;")
#define CP_WAIT1()  asm volatile("cp.async.wait_group 1;")

__device__ __forceinline__ void ldsm_x4(uint32_t* r, uint32_t addr) {
    asm volatile("ldmatrix.sync.aligned.m8n8.x4.shared.b16 {%0,%1,%2,%3}, [%4];"
                 : "=r"(r[0]), "=r"(r[1]), "=r"(r[2]), "=r"(r[3]) : "r"(addr));
}
__device__ __forceinline__ void ldsm_x4_t(uint32_t* r, uint32_t addr) {
    asm volatile("ldmatrix.sync.aligned.m8n8.x4.trans.shared.b16 {%0,%1,%2,%3}, [%4];"
                 : "=r"(r[0]), "=r"(r[1]), "=r"(r[2]), "=r"(r[3]) : "r"(addr));
}
__device__ __forceinline__ void mma16816(float* d, const uint32_t* a, const uint32_t* b) {
    asm volatile(
        "mma.sync.aligned.m16n8k16.row.col.f32.bf16.bf16.f32 "
        "{%0,%1,%2,%3}, {%4,%5,%6,%7}, {%8,%9}, {%0,%1,%2,%3};"
        : "+f"(d[0]), "+f"(d[1]), "+f"(d[2]), "+f"(d[3])
        : "r"(a[0]), "r"(a[1]), "r"(a[2]), "r"(a[3]), "r"(b[0]), "r"(b[1]));
}
__device__ __forceinline__ uint16_t bf16_bits(float v) {
    __nv_bfloat16 h = __float2bfloat16(v);
    uint16_t b; memcpy(&b, &h, 2);
    return b;
}
__device__ __forceinline__ float bf16_val(uint16_t b) {
    __nv_bfloat16 h; memcpy(&h, &b, 2);
    return __bfloat162float(h);
}

// ======================= device scratch =======================
__device__ float g_hmean[NB * NC * ND];
__device__ float g_q[NB * NC * NKD];
__device__ float g_k[NB * NC * NKD];
__device__ float g_adaptive[NB * NC * NC];
__device__ unsigned long long g_maskcol[NB * NC];
__device__ float g_vsrc[NH * ND];
__device__ float g_vdst[NH * ND];
__device__ __nv_bfloat16 g_ghi[NH * ND * ND];
__device__ __nv_bfloat16 g_glo[NH * ND * ND];
__device__ uint16_t g_wxh[(size_t)NB * NT * NC * NH * ND]; // [b][t][c][2048] bf16 hi
__device__ uint16_t g_wxl[(size_t)NB * NT * NC * NH * ND]; // bf16 lo
__device__ float g_as[NB * NT * NH * NC];
__device__ float g_ad[NB * NT * NH * NC];

// ======================= kernel: G hi/lo split =======================
#define NG_ELEMS 524288u
__global__ void k_splitG(const float* __restrict__ g) {
    uint32_t i = blockIdx.x * blockDim.x + threadIdx.x;
    if (i >= NG_ELEMS) return;
    float v = g[i];
    __nv_bfloat16 hi = __float2bfloat16(v);
    float r = v - __bfloat162float(hi);
    g_ghi[i] = hi;
    g_glo[i] = __float2bfloat16(r);
}

// ======================= kernel: temporal mean =======================
__global__ void k_hmean(const float* __restrict__ x) {
    int bc = blockIdx.x;
    int d = threadIdx.x;
    const float* p = x + (size_t)bc * NT * ND + d;
    float s = 0.f;
#pragma unroll 8
    for (int t = 0; t < NT; ++t) s += p[(size_t)t * ND];
    g_hmean[bc * ND + d] = s * (1.0f / NT);
}

// ======================= kernel: v_src/v_dst =======================
__global__ void k_vsd(const float* __restrict__ gat_lin,
                      const float* __restrict__ att_src,
                      const float* __restrict__ att_dst) {
    int h = blockIdx.x & 7;
    int isdst = blockIdx.x >> 3;
    int d = threadIdx.x;
    const float* att = isdst ? att_dst : att_src;
    float acc = 0.f;
#pragma unroll 4
    for (int f = 0; f < ND; ++f)
        acc += att[h * ND + f] * gat_lin[((size_t)(h * ND + f)) * ND + d];
    (isdst ? g_vdst : g_vsrc)[h * ND + d] = acc;
}

// ======================= kernel: q/k projections =======================
__global__ __launch_bounds__(256)
void k_qk(const float* __restrict__ w_q, const float* __restrict__ w_k) {
    __shared__ float hs[8 * ND];
    int blk = blockIdx.x;
    int tid = threadIdx.x;
    for (int it = tid; it < 8 * ND; it += 256) hs[it] = g_hmean[(size_t)blk * 8 * ND + it];
    if (tid < 8) g_maskcol[blk * 8 + tid] = 1ull << ((blk * 8 + tid) & 63);
    __syncthreads();
#pragma unroll
    for (int k = 0; k < 2; ++k) {
        int o = tid + k * 256;
        int bcL = o >> 6, rem = o & 63;
        int which = rem >> 5, kd = rem & 31;
        const float4* w4 = (const float4*)((which ? w_k : w_q) + (size_t)kd * ND);
        const float* hr = hs + bcL * ND;
        float acc = 0.f;
#pragma unroll 8
        for (int d4 = 0; d4 < 64; ++d4) {
            float4 wv = __ldg(w4 + d4);
            acc += hr[d4 * 4] * wv.x + hr[d4 * 4 + 1] * wv.y
                 + hr[d4 * 4 + 2] * wv.z + hr[d4 * 4 + 3] * wv.w;
        }
        (which ? g_k : g_q)[(blk * 8 + bcL) * NKD + kd] = acc;
    }
}

// ======================= kernel: sim + tanh =======================
__global__ __launch_bounds__(256)
void k_sim(const float* __restrict__ static_adj, float* __restrict__ delta_out) {
    __shared__ float qs[16 * NKD];
    __shared__ float ks_[NC * NKD];
    int b = blockIdx.x >> 2;
    int i0 = (blockIdx.x & 3) * 16;
    int tid = threadIdx.x;
    for (int it = tid; it < NC * NKD; it += 256) ks_[it] = g_k[b * NC * NKD + it];
    for (int it = tid; it < 16 * NKD; it += 256) qs[it] = g_q[b * NC * NKD + i0 * NKD + it];
    __syncthreads();
    const float inv = 0.17677669529663687f;
    for (int task = tid; task < 16 * NC; task += 256) {
        int i = task >> 6, j = task & 63;
        float acc = 0.f;
#pragma unroll
        for (int kd = 0; kd < NKD; ++kd) acc += qs[i * NKD + kd] * ks_[j * NKD + kd];
        float delta = tanhf(acc * inv);
        int gi = i0 + i;
        int idx = b * NC * NC + gi * NC + j;
        delta_out[idx] = delta;
        g_adaptive[idx] = static_adj[gi * NC + j] + delta;
    }
}

// ======================= kernel: top-k =======================
__global__ void k_topk() {
    int b = blockIdx.x / NC, i = blockIdx.x % NC;
    int lane = threadIdx.x;
    const float* row = g_adaptive + (size_t)(b * NC + i) * NC;
    float v0 = fabsf(row[lane]);
    float v1 = fabsf(row[lane + 32]);
    for (int s = 0; s < NTOPK; ++s) {
        float bv; int bj;
        if (v0 >= v1) { bv = v0; bj = lane; } else { bv = v1; bj = lane + 32; }
#pragma unroll
        for (int off = 16; off > 0; off >>= 1) {
            float ov = __shfl_xor_sync(0xffffffffu, bv, off);
            int   oj = __shfl_xor_sync(0xffffffffu, bj, off);
            if (ov > bv || (ov == bv && oj < bj)) { bv = ov; bj = oj; }
        }
        if (lane == 0) atomicOr(&g_maskcol[b * NC + bj], 1ull << i);
        if (bj == lane)      v0 = -1.0f;
        if (bj == lane + 32) v1 = -1.0f;
    }
}

// ======================= kernel: split-bf16 GEMM (HMMA) + fused att dots =======================
#define GEMM_THREADS 512
#define SMA_BYTES 131072
#define SMB_BYTES 65536
#define SM_V (SMA_BYTES + SMB_BYTES)
#define SM_GEMM_TOTAL (SM_V + 17472)   // vt: (256*17+16) floats

__global__ __launch_bounds__(GEMM_THREADS, 1)
void k_gemm(const float* __restrict__ x) {
    extern __shared__ char smem[];
    uint32_t sbA = smem_to_u32(smem);
    uint32_t sbB = sbA + SMA_BYTES;
    const int tid = threadIdx.x;
    const int w = tid >> 5, l = tid & 31;
    const size_t mtile = blockIdx.x;   // = b*64 + c

    float* vt = (float*)(smem + SM_V);   // [d=256][hv=16] stride 17
    for (int it = tid; it < 2048; it += GEMM_THREADS) {
        int h = it >> 8, d = it & 255;
        vt[d * 17 + h]     = g_vsrc[it];
        vt[d * 17 + 8 + h] = g_vdst[it];
    }

    float att_acc[4] = {0.f, 0.f, 0.f, 0.f};

    // ---- prologue: double-buffered fp32 staging, split to bf16 hi/lo + att dots ----
    {
#pragma unroll
        for (int ii = 0; ii < 4; ++ii) {   // issue chunk 0
            int it = tid + ii * GEMM_THREADS;
            int r = it >> 4, q = it & 15;
            CP_ASYNC16(sbB + (uint32_t)(r * 256 + q * 16),
                       x + (mtile * 128 + r) * 256 + q * 4);
        }
        CP_COMMIT();
        for (int kb2 = 0; kb2 < 4; ++kb2) {
            if (kb2 < 3) {
                uint32_t stg_u = sbB + (uint32_t)(((kb2 + 1) & 1) * 32768);
#pragma unroll
                for (int ii = 0; ii < 4; ++ii) {
                    int it = tid + ii * GEMM_THREADS;
                    int r = it >> 4, q = it & 15;
                    CP_ASYNC16(stg_u + (uint32_t)(r * 256 + q * 16),
                               x + (mtile * 128 + r) * 256 + (kb2 + 1) * 64 + q * 4);
                }
                CP_COMMIT();
                CP_WAIT1();
            } else {
                CP_WAIT0();
            }
            __syncthreads();
            const float* stg_f = (const float*)(smem + SMA_BYTES + (kb2 & 1) * 32768);
            // convert 128x64 fp32 -> bf16 hi/lo into A region (swizzled)
#pragma unroll
            for (int k = 0; k < 2; ++k) {
                int it = tid + k * GEMM_THREADS;
                int r = it >> 3, gnum = it & 7;
                const float* src = stg_f + r * 64 + gnum * 8;
                uint32_t hw[4], lw[4];
#pragma unroll
                for (int p = 0; p < 4; ++p) {
                    float v0 = src[2 * p], v1 = src[2 * p + 1];
                    uint16_t h0 = bf16_bits(v0), h1 = bf16_bits(v1);
                    uint16_t l0 = bf16_bits(v0 - bf16_val(h0));
                    uint16_t l1 = bf16_bits(v1 - bf16_val(h1));
                    hw[p] = (uint32_t)h0 | ((uint32_t)h1 << 16);
                    lw[p] = (uint32_t)l0 | ((uint32_t)l1 << 16);
                }
                uint32_t off = (uint32_t)(r * 128 + ((gnum * 16) ^ ((r & 7) << 4)));
                *(uint4*)(smem + (0 * 4 + kb2) * 16384 + off) = make_uint4(hw[0], hw[1], hw[2], hw[3]);
                *(uint4*)(smem + (1 * 4 + kb2) * 16384 + off) = make_uint4(lw[0], lw[1], lw[2], lw[3]);
            }
            // att partial dots: task = (t, hv)
#pragma unroll
            for (int k = 0; k < 4; ++k) {
                int task = tid + k * GEMM_THREADS;
                int t = task >> 4, hv = task & 15;
                const float* sr = stg_f + t * 64;
                const float* vr = vt + (kb2 * 64) * 17 + hv;
                float a = att_acc[k];
#pragma unroll 16
                for (int d = 0; d < 64; ++d) a += sr[d] * vr[d * 17];
                att_acc[k] = a;
            }
            __syncthreads();
        }
    }
    // write att results: g_as/g_ad[((b*128+t)*8+h)*64 + c]
    {
        int b = (int)(mtile >> 6), c = (int)(mtile & 63);
#pragma unroll
        for (int k = 0; k < 4; ++k) {
            int task = tid + k * GEMM_THREADS;
            int t = task >> 4, hv = task & 15, h = hv & 7, sd = hv >> 3;
            (sd ? g_ad : g_as)[(((size_t)(b * 128 + t)) * 8 + h) * 64 + c] = att_acc[k];
        }
    }

    // ---- first B chunk (nt=0, kb=0) into buf 0 ----
    {
        const char* gh = (const char*)g_ghi;
        const char* gl = (const char*)g_glo;
#pragma unroll
        for (int ii = 0; ii < 4; ++ii) {
            int it = tid + ii * GEMM_THREADS;
            int q = it & 7, r = (it >> 3) & 127, s = it >> 10;
            const char* gp = (s ? gl : gh) + ((size_t)r * 512 + q * 16);
            uint32_t sa = sbB + (uint32_t)(s * 16384 + r * 128 + ((q * 16) ^ ((r & 7) << 4)));
            CP_ASYNC16(sa, gp);
        }
    }
    CP_COMMIT();
    CP_WAIT0();
    __syncthreads();

    const int mbase = (w & 3) * 32;
    const int nbase = (w >> 2) * 32;
    int aoff[2]; uint32_t akx[2];
#pragma unroll
    for (int mt = 0; mt < 2; ++mt) {
        int r = mbase + mt * 16 + (l & 15);
        aoff[mt] = r * 128;
        akx[mt] = (uint32_t)((r & 7) << 4);
    }
    const uint32_t akoff = (uint32_t)((l >> 4) * 16);
    int boff[2]; uint32_t bkx[2];
#pragma unroll
    for (int p = 0; p < 2; ++p) {
        int r = nbase + p * 16 + (l & 7) + (l >> 4) * 8;
        boff[p] = r * 128;
        bkx[p] = (uint32_t)((r & 7) << 4);
    }
    const uint32_t bkoff = (uint32_t)(((l >> 3) & 1) * 16);

    float acc[2][4][4];
#pragma unroll
    for (int mt = 0; mt < 2; ++mt)
#pragma unroll
        for (int g = 0; g < 4; ++g)
#pragma unroll
            for (int q = 0; q < 4; ++q) acc[mt][g][q] = 0.f;

    const char* ghp = (const char*)g_ghi;
    const char* glp = (const char*)g_glo;
    int buf = 0;

    for (int nt = 0; nt < 16; ++nt) {
        for (int kb = 0; kb < 4; ++kb) {
            const int have_next = !(nt == 15 && kb == 3);
            if (have_next) {
                int nn = nt + (kb == 3);
                int nk = (kb + 1) & 3;
                int b2 = buf ^ 1;
#pragma unroll
                for (int ii = 0; ii < 4; ++ii) {
                    int it = tid + ii * GEMM_THREADS;
                    int q = it & 7, r = (it >> 3) & 127, s = it >> 10;
                    const char* gp = (s ? glp : ghp) + ((size_t)(nn * 128 + r) * 512 + nk * 128 + q * 16);
                    uint32_t sa = sbB + (uint32_t)((b2 * 2 + s) * 16384 + r * 128 + ((q * 16) ^ ((r & 7) << 4)));
                    CP_ASYNC16(sa, gp);
                }
                CP_COMMIT();
            }

            const uint32_t pAh = sbA + (uint32_t)((0 * 4 + kb) * 16384);
            const uint32_t pAl = sbA + (uint32_t)((1 * 4 + kb) * 16384);
            const uint32_t pBh = sbB + (uint32_t)((buf * 2 + 0) * 16384);
            const uint32_t pBl = sbB + (uint32_t)((buf * 2 + 1) * 16384);
#pragma unroll
            for (int ks = 0; ks < 4; ++ks) {
                uint32_t ah[2][4], al[2][4], bh[2][4], bl[2][4];
#pragma unroll
                for (int mt = 0; mt < 2; ++mt) {
                    uint32_t kbyte = ((uint32_t)(ks * 32) + akoff) ^ akx[mt];
                    ldsm_x4(ah[mt], pAh + aoff[mt] + kbyte);
                    ldsm_x4(al[mt], pAl + aoff[mt] + kbyte);
                }
#pragma unroll
                for (int p = 0; p < 2; ++p) {
                    uint32_t kbyte = ((uint32_t)(ks * 32) + bkoff) ^ bkx[p];
                    ldsm_x4(bh[p], pBh + boff[p] + kbyte);
                    ldsm_x4(bl[p], pBl + boff[p] + kbyte);
                }
#pragma unroll
                for (int mt = 0; mt < 2; ++mt)
#pragma unroll
                    for (int g = 0; g < 4; ++g) {
                        const int p = g >> 1, o = (g & 1) * 2;
                        mma16816(acc[mt][g], ah[mt], &bh[p][o]);
                        mma16816(acc[mt][g], ah[mt], &bl[p][o]);
                        mma16816(acc[mt][g], al[mt], &bh[p][o]);
                    }
            }

            if (have_next) CP_WAIT0();
            __syncthreads();
            buf ^= 1;
        }

        // ---- epilogue: store bf16 hi/lo to separate arrays, [b][t][c][2048] ----
        {
            size_t r0 = mtile * 128 + mbase + (l >> 2);
            int c0 = nt * 128 + nbase + (l & 3) * 2;
#pragma unroll
            for (int mt = 0; mt < 2; ++mt) {
                size_t rr = r0 + mt * 16;   // X row = (b*64+c)*128 + t
                size_t wxrow = ((rr >> 13) * 128 + (rr & 127)) * 64 + ((rr >> 7) & 63);
                uint16_t* dh = g_wxh + wxrow * 2048 + c0;
                uint16_t* dl = g_wxl + wxrow * 2048 + c0;
#pragma unroll
                for (int g = 0; g < 4; ++g) {
                    float a0 = acc[mt][g][0], a1 = acc[mt][g][1];
                    float a2 = acc[mt][g][2], a3 = acc[mt][g][3];
                    uint16_t h0 = bf16_bits(a0), h1 = bf16_bits(a1);
                    uint16_t h2 = bf16_bits(a2), h3 = bf16_bits(a3);
                    uint16_t l0 = bf16_bits(a0 - bf16_val(h0));
                    uint16_t l1 = bf16_bits(a1 - bf16_val(h1));
                    uint16_t l2 = bf16_bits(a2 - bf16_val(h2));
                    uint16_t l3 = bf16_bits(a3 - bf16_val(h3));
                    *(uint32_t*)(dh + g * 8)              = (uint32_t)h0 | ((uint32_t)h1 << 16);
                    *(uint32_t*)(dl + g * 8)              = (uint32_t)l0 | ((uint32_t)l1 << 16);
                    *(uint32_t*)(dh + 512 * 2048 + g * 8) = (uint32_t)h2 | ((uint32_t)h3 << 16);
                    *(uint32_t*)(dl + 512 * 2048 + g * 8) = (uint32_t)l2 | ((uint32_t)l3 << 16);
                    acc[mt][g][0] = acc[mt][g][1] = acc[mt][g][2] = acc[mt][g][3] = 0.f;
                }
            }
        }
    }
}

// ======================= kernel: aggregation via HMMA, cp.async double-buffered =======================
#define ATHREADS 512
#define AG_BUF 33792
#define WXH_OFF 0
#define WXL_OFF (2 * AG_BUF)           // 67584
#define ALH_OFF (4 * AG_BUF)           // 135168
#define ALL_OFF (ALH_OFF + 9216)       // 144384
#define AS8_OFF (ALL_OFF + 9216)       // 153600
#define AD8_OFF (AS8_OFF + 2048)       // 155648
#define AGG_SMEM (AD8_OFF + 2048)      // 157696

__global__ __launch_bounds__(ATHREADS, 1)
void k_agg(const float* __restrict__ gat_bias, float* __restrict__ out) {
    extern __shared__ char smc[];
    uint32_t sb = smem_to_u32(smc);
    uint16_t* alh = (uint16_t*)(smc + ALH_OFF);   // [j=64][i stride 72]
    uint16_t* allo = (uint16_t*)(smc + ALL_OFF);
    float* as8 = (float*)(smc + AS8_OFF);         // [h=8][c=64]
    float* ad8 = (float*)(smc + AD8_OFF);

    int bt = blockIdx.x, b = bt >> 7;
    int t = bt & 127;
    int tid = threadIdx.x;
    int w = tid >> 5, l = tid & 31;
    int mw = w & 1, nw = w >> 1;

    unsigned long long msk[4];
#pragma unroll
    for (int jj = 0; jj < 4; ++jj) msk[jj] = g_maskcol[b * NC + w * 4 + jj];

    const uint32_t aoffA = (uint32_t)(((mw * 32 + (l & 15)) * 72 + (l >> 4) * 8) * 2);
    const uint32_t boffB = (uint32_t)((((l & 7) + ((l >> 3) & 1) * 8) * 264 + nw * 32 + (l >> 4) * 8) * 2);

    float acc[2][4][4];
#pragma unroll
    for (int mt = 0; mt < 2; ++mt)
#pragma unroll
        for (int q = 0; q < 4; ++q)
#pragma unroll
            for (int r = 0; r < 4; ++r) acc[mt][q][r] = 0.f;

    const float NEGINF = __int_as_float(0xff800000);
    const size_t wxbase = (size_t)bt * 64 * 2048;

    // stage h=0 into buf 0
#pragma unroll
    for (int ii = 0; ii < 8; ++ii) {
        int it = tid + ii * ATHREADS;
        int s = it >> 11, rem = it & 2047;
        int c = rem >> 5, q = rem & 31;
        const uint16_t* src = (s ? g_wxl : g_wxh) + wxbase + (size_t)c * 2048 + q * 8;
        CP_ASYNC16(sb + (uint32_t)((s ? WXL_OFF : WXH_OFF) + c * 528 + q * 16), src);
    }
    CP_COMMIT();
    // preload as/ad for all heads
    for (int it = tid; it < 512; it += ATHREADS) {
        as8[it] = g_as[(size_t)bt * 512 + it];
        ad8[it] = g_ad[(size_t)bt * 512 + it];
    }
    __syncthreads();

    for (int h = 0; h < NH; ++h) {
        int bi = h & 1;
        if (h < 7) {
            int b2 = (h + 1) & 1;
#pragma unroll
            for (int ii = 0; ii < 8; ++ii) {
                int it = tid + ii * ATHREADS;
                int s = it >> 11, rem = it & 2047;
                int c = rem >> 5, q = rem & 31;
                const uint16_t* src = (s ? g_wxl : g_wxh) + wxbase + (size_t)c * 2048 + (h + 1) * 256 + q * 8;
                CP_ASYNC16(sb + (uint32_t)((s ? WXL_OFF : WXH_OFF) + b2 * AG_BUF + c * 528 + q * 16), src);
            }
            CP_COMMIT();
        }

        // masked softmax -> alpha^T bf16 hi/lo [j][i]
#pragma unroll
        for (int jj = 0; jj < 4; ++jj) {
            int j = w * 4 + jj;
            unsigned long long m = msk[jj];
            float adj = ad8[h * 64 + j];
            int i0 = l, i1 = l + 32;
            float e0 = as8[h * 64 + i0] + adj;
            float e1 = as8[h * 64 + i1] + adj;
            e0 = e0 > 0.f ? e0 : 0.2f * e0;
            e1 = e1 > 0.f ? e1 : 0.2f * e1;
            bool m0 = (m >> i0) & 1ull;
            bool m1 = (m >> i1) & 1ull;
            float mx = fmaxf(m0 ? e0 : NEGINF, m1 ? e1 : NEGINF);
#pragma unroll
            for (int off = 16; off > 0; off >>= 1)
                mx = fmaxf(mx, __shfl_xor_sync(0xffffffffu, mx, off));
            float p0 = m0 ? expf(e0 - mx) : 0.f;
            float p1 = m1 ? expf(e1 - mx) : 0.f;
            float ssum = p0 + p1;
#pragma unroll
            for (int off = 16; off > 0; off >>= 1)
                ssum += __shfl_xor_sync(0xffffffffu, ssum, off);
            float invs = 1.0f / ssum;
            float a0 = p0 * invs, a1 = p1 * invs;
            uint16_t h0 = bf16_bits(a0);
            uint16_t h1 = bf16_bits(a1);
            alh[j * 72 + i0] = h0;
            alh[j * 72 + i1] = h1;
            allo[j * 72 + i0] = bf16_bits(a0 - bf16_val(h0));
            allo[j * 72 + i1] = bf16_bits(a1 - bf16_val(h1));
        }
        if (h < 7) CP_WAIT1(); else CP_WAIT0();
        __syncthreads();

        const uint32_t pBh = sb + (uint32_t)(WXH_OFF + bi * AG_BUF);
        const uint32_t pBl = sb + (uint32_t)(WXL_OFF + bi * AG_BUF);
#pragma unroll
        for (int ks = 0; ks < 4; ++ks) {
            uint32_t ah[2][4], al[2][4], bh[2][4], bl[2][4];
#pragma unroll
            for (int mt = 0; mt < 2; ++mt) {
                uint32_t ab = aoffA + (uint32_t)(mt * 2304 + ks * 32);
                ldsm_x4(ah[mt], sb + ALH_OFF + ab);
                ldsm_x4(al[mt], sb + ALL_OFF + ab);
            }
#pragma unroll
            for (int nt = 0; nt < 2; ++nt) {
                uint32_t bb = boffB + (uint32_t)(nt * 32 + ks * 8448);
                ldsm_x4_t(bh[nt], pBh + bb);
                ldsm_x4_t(bl[nt], pBl + bb);
            }
#pragma unroll
            for (int mt = 0; mt < 2; ++mt)
#pragma unroll
                for (int q = 0; q < 4; ++q) {
                    const int nt = q >> 1, o = (q & 1) * 2;
                    mma16816(acc[mt][q], ah[mt], &bh[nt][o]);
                    mma16816(acc[mt][q], ah[mt], &bl[nt][o]);
                    mma16816(acc[mt][q], al[mt], &bh[nt][o]);
                }
        }
        __syncthreads();
    }

    const float inv8 = 0.125f;
#pragma unroll
    for (int mt = 0; mt < 2; ++mt) {
        int j0 = mw * 32 + mt * 16 + (l >> 2);
#pragma unroll
        for (int q = 0; q < 4; ++q) {
            int f = nw * 32 + q * 8 + (l & 3) * 2;
            float b0 = __ldg(gat_bias + f), b1 = __ldg(gat_bias + f + 1);
            float2 v0 = make_float2(acc[mt][q][0] * inv8 + b0, acc[mt][q][1] * inv8 + b1);
            float2 v1 = make_float2(acc[mt][q][2] * inv8 + b0, acc[mt][q][3] * inv8 + b1);
            *(float2*)(out + (((size_t)b * NC + j0) * NT + t) * ND + f) = v0;
            *(float2*)(out + (((size_t)b * NC + j0 + 8) * NT + t) * ND + f) = v1;
        }
    }
}

// ======================= launch =======================
extern "C" void kernel_launch(void* const* d_in, const int* in_sizes, int n_in,
                              void* d_out, int out_size) {
    const float* x          = (const float*)d_in[0];
    const float* static_adj = (const float*)d_in[1];
    const float* w_q        = (const float*)d_in[2];
    const float* w_k        = (const float*)d_in[3];
    const float* gat_lin    = (const float*)d_in[4];
    const float* att_src    = (const float*)d_in[5];
    const float* att_dst    = (const float*)d_in[6];
    const float* gat_bias   = (const float*)d_in[7];

    float* out = (float*)d_out;
    float* delta_out = out + (size_t)NB * NC * NT * ND;

    cudaFuncSetAttribute(k_gemm, cudaFuncAttributeMaxDynamicSharedMemorySize, SM_GEMM_TOTAL);
    cudaFuncSetAttribute(k_agg,  cudaFuncAttributeMaxDynamicSharedMemorySize, AGG_SMEM);

    // k_gemm is the 6th launch so ncu (-s 5 -c 1) profiles it
    k_hmean<<<NB * NC, 256>>>(x);                              // 1
    k_vsd<<<16, 256>>>(gat_lin, att_src, att_dst);             // 2
    k_splitG<<<(NG_ELEMS + 255) / 256, 256>>>(gat_lin);        // 3
    k_qk<<<NB * NC / 8, 256>>>(w_q, w_k);                      // 4
    k_sim<<<NB * 4, 256>>>(static_adj, delta_out);             // 5
    k_gemm<<<1024, GEMM_THREADS, SM_GEMM_TOTAL>>>(x);          // 6
    k_topk<<<NB * NC, 32>>>();                                 // 7
    k_agg<<<NB * NT, ATHREADS, AGG_SMEM>>>(gat_bias, out);     // 8
}

// round 8
// speedup vs baseline: 3.3215x; 1.0509x over previous
#include <cuda_runtime.h>
#include <cuda_bf16.h>
#include <math.h>
#include <stdint.h>
#include <string.h>

#define NB 16
#define NC 64
#define NT 128
#define ND 256
#define NH 8
#define NKD 32
#define NTOPK 8

// ======================= helpers =======================
__device__ __forceinline__ uint32_t smem_to_u32(const void* p) {
    uint32_t a;
    asm("{ .reg .u64 t; cvta.to.shared.u64 t, %1; cvt.u32.u64 %0, t; }" : "=r"(a) : "l"(p));
    return a;
}
#define CP_ASYNC16(sa, gp) \
    asm volatile("cp.async.cg.shared.global [%0], [%1], 16;" :: "r"(sa), "l"(gp))
#define CP_COMMIT() asm volatile("cp.async.commit_group;")
#define CP_WAIT0()  asm volatile("cp.async.wait_group 0;")
#define CP_WAIT1()  asm volatile("cp.async.wait_group 1;")

__device__ __forceinline__ void ldsm_x4(uint32_t* r, uint32_t addr) {
    asm volatile("ldmatrix.sync.aligned.m8n8.x4.shared.b16 {%0,%1,%2,%3}, [%4];"
                 : "=r"(r[0]), "=r"(r[1]), "=r"(r[2]), "=r"(r[3]) : "r"(addr));
}
__device__ __forceinline__ void ldsm_x4_t(uint32_t* r, uint32_t addr) {
    asm volatile("ldmatrix.sync.aligned.m8n8.x4.trans.shared.b16 {%0,%1,%2,%3}, [%4];"
                 : "=r"(r[0]), "=r"(r[1]), "=r"(r[2]), "=r"(r[3]) : "r"(addr));
}
__device__ __forceinline__ void mma16816(float* d, const uint32_t* a, const uint32_t* b) {
    asm volatile(
        "mma.sync.aligned.m16n8k16.row.col.f32.bf16.bf16.f32 "
        "{%0,%1,%2,%3}, {%4,%5,%6,%7}, {%8,%9}, {%0,%1,%2,%3};"
        : "+f"(d[0]), "+f"(d[1]), "+f"(d[2]), "+f"(d[3])
        : "r"(a[0]), "r"(a[1]), "r"(a[2]), "r"(a[3]), "r"(b[0]), "r"(b[1]));
}
__device__ __forceinline__ uint16_t bf16_bits(float v) {
    __nv_bfloat16 h = __float2bfloat16(v);
    uint16_t b; memcpy(&b, &h, 2);
    return b;
}
__device__ __forceinline__ float bf16_val(uint16_t b) {
    __nv_bfloat16 h; memcpy(&h, &b, 2);
    return __bfloat162float(h);
}

// ======================= device scratch =======================
__device__ float g_hmean[NB * NC * ND];
__device__ float g_q[NB * NC * NKD];
__device__ float g_k[NB * NC * NKD];
__device__ unsigned long long g_maskcol[NB * NC];
__device__ float g_vsrc[NH * ND];
__device__ float g_vdst[NH * ND];
__device__ __nv_bfloat16 g_ghi[NH * ND * ND];
__device__ __nv_bfloat16 g_glo[NH * ND * ND];

// ======================= kernel: G hi/lo split =======================
#define NG_ELEMS 524288u
__global__ void k_splitG(const float* __restrict__ g) {
    uint32_t i = blockIdx.x * blockDim.x + threadIdx.x;
    if (i >= NG_ELEMS) return;
    float v = g[i];
    __nv_bfloat16 hi = __float2bfloat16(v);
    float r = v - __bfloat162float(hi);
    g_ghi[i] = hi;
    g_glo[i] = __float2bfloat16(r);
}

// ======================= kernel: temporal mean =======================
__global__ void k_hmean(const float* __restrict__ x) {
    int bc = blockIdx.x;
    int d = threadIdx.x;
    const float* p = x + (size_t)bc * NT * ND + d;
    float s = 0.f;
#pragma unroll 8
    for (int t = 0; t < NT; ++t) s += p[(size_t)t * ND];
    g_hmean[bc * ND + d] = s * (1.0f / NT);
}

// ======================= kernel: v_src/v_dst =======================
__global__ void k_vsd(const float* __restrict__ gat_lin,
                      const float* __restrict__ att_src,
                      const float* __restrict__ att_dst) {
    int h = blockIdx.x & 7;
    int isdst = blockIdx.x >> 3;
    int d = threadIdx.x;
    const float* att = isdst ? att_dst : att_src;
    float acc = 0.f;
#pragma unroll 4
    for (int f = 0; f < ND; ++f)
        acc += att[h * ND + f] * gat_lin[((size_t)(h * ND + f)) * ND + d];
    (isdst ? g_vdst : g_vsrc)[h * ND + d] = acc;
}

// ======================= kernel: q/k projections + self-loop init =======================
__global__ __launch_bounds__(256)
void k_qk(const float* __restrict__ w_q, const float* __restrict__ w_k) {
    __shared__ float hs[8 * ND];
    int blk = blockIdx.x;
    int tid = threadIdx.x;
    for (int it = tid; it < 8 * ND; it += 256) hs[it] = g_hmean[(size_t)blk * 8 * ND + it];
    if (tid < 8) g_maskcol[blk * 8 + tid] = 1ull << ((blk * 8 + tid) & 63);
    __syncthreads();
#pragma unroll
    for (int k = 0; k < 2; ++k) {
        int o = tid + k * 256;
        int bcL = o >> 6, rem = o & 63;
        int which = rem >> 5, kd = rem & 31;
        const float4* w4 = (const float4*)((which ? w_k : w_q) + (size_t)kd * ND);
        const float* hr = hs + bcL * ND;
        float acc = 0.f;
#pragma unroll 8
        for (int d4 = 0; d4 < 64; ++d4) {
            float4 wv = __ldg(w4 + d4);
            acc += hr[d4 * 4] * wv.x + hr[d4 * 4 + 1] * wv.y
                 + hr[d4 * 4 + 2] * wv.z + hr[d4 * 4 + 3] * wv.w;
        }
        (which ? g_k : g_q)[(blk * 8 + bcL) * NKD + kd] = acc;
    }
}

// ======================= kernel: sim + tanh + top-k (merged) =======================
__global__ __launch_bounds__(256)
void k_simtopk(const float* __restrict__ static_adj, float* __restrict__ delta_out) {
    __shared__ float qs[16 * NKD];
    __shared__ float ks_[NC * NKD];
    __shared__ float arow[16 * NC];
    int b = blockIdx.x >> 2;
    int i0 = (blockIdx.x & 3) * 16;
    int tid = threadIdx.x;
    for (int it = tid; it < NC * NKD; it += 256) ks_[it] = g_k[b * NC * NKD + it];
    for (int it = tid; it < 16 * NKD; it += 256) qs[it] = g_q[b * NC * NKD + i0 * NKD + it];
    __syncthreads();
    const float inv = 0.17677669529663687f;
    for (int task = tid; task < 16 * NC; task += 256) {
        int i = task >> 6, j = task & 63;
        float acc = 0.f;
#pragma unroll
        for (int kd = 0; kd < NKD; ++kd) acc += qs[i * NKD + kd] * ks_[j * NKD + kd];
        float delta = tanhf(acc * inv);
        int gi = i0 + i;
        delta_out[b * NC * NC + gi * NC + j] = delta;
        arow[task] = static_adj[gi * NC + j] + delta;
    }
    __syncthreads();
    // top-8 per row: warp w handles local rows w*2, w*2+1
    int w = tid >> 5, lane = tid & 31;
#pragma unroll
    for (int rr = 0; rr < 2; ++rr) {
        int i = w * 2 + rr;
        int gi = i0 + i;
        float v0 = fabsf(arow[i * NC + lane]);
        float v1 = fabsf(arow[i * NC + lane + 32]);
        for (int s = 0; s < NTOPK; ++s) {
            float bv; int bj;
            if (v0 >= v1) { bv = v0; bj = lane; } else { bv = v1; bj = lane + 32; }
#pragma unroll
            for (int off = 16; off > 0; off >>= 1) {
                float ov = __shfl_xor_sync(0xffffffffu, bv, off);
                int   oj = __shfl_xor_sync(0xffffffffu, bj, off);
                if (ov > bv || (ov == bv && oj < bj)) { bv = ov; bj = oj; }
            }
            if (lane == 0) atomicOr(&g_maskcol[b * NC + bj], 1ull << gi);
            if (bj == lane)      v0 = -1.0f;
            if (bj == lane + 32) v1 = -1.0f;
        }
    }
}

// ======================= kernel: FUSED gemm + softmax + aggregation =======================
// CTA = (b, t). A = X[b, :, t, :] (64 x 256) split to bf16 hi/lo, resident.
// Loop 16 n-tiles of G: wx_tile(64x128) = A @ G_nt^T (3-term HMMA) -> SMEM bf16 hi/lo
// -> out_acc += alpha_h^T @ wx_tile (3-term HMMA). Never touch HBM for wx.
#define MTHREADS 512
#define SM_A 0                       // 65536: [split2][kb4][64 r][128B] swizzled
#define SM_B 65536                   // 65536: [buf2][split2][128 r][128B] swizzled
#define SM_WX 131072                 // 32768: [split2][64 r x 2 half][128B] swizzled
#define SM_ALPHA 163840              // 18432: alh[64][72] + allo (vt overlay in prologue)
#define SM_ASAD 182272               // 4096: a_s[8][64], a_d[8][64]
#define SM_MAIN (SM_ASAD + 4096)     // 186368

__global__ __launch_bounds__(MTHREADS, 1)
void k_main(const float* __restrict__ x,
            const float* __restrict__ gat_bias,
            float* __restrict__ out) {
    extern __shared__ char smem[];
    uint32_t sb = smem_to_u32(smem);
    const int tid = threadIdx.x;
    const int w = tid >> 5, l = tid & 31;
    const int bx = blockIdx.x;
    const int b = bx >> 7, t = bx & 127;

    // ---------------- prologue ----------------
    // vt overlay in alpha region: [d=256][17]
    float* vt = (float*)(smem + SM_ALPHA);
    for (int it = tid; it < 2048; it += MTHREADS) {
        int h = it >> 8, d = it & 255;
        vt[d * 17 + h]     = g_vsrc[it];
        vt[d * 17 + 8 + h] = g_vdst[it];
    }
    // stage X rows (c=0..63) fp32, row stride 264 floats (in B region + 2KB of WX)
#pragma unroll
    for (int ii = 0; ii < 8; ++ii) {
        int it = tid + ii * MTHREADS;
        int c = it >> 6, q = it & 63;
        CP_ASYNC16(sb + SM_B + (uint32_t)(c * 1056 + q * 16),
                   x + (((size_t)(b * 64 + c) * 128) + t) * 256 + q * 4);
    }
    CP_COMMIT();
    CP_WAIT0();
    __syncthreads();

    const float* stgf = (const float*)(smem + SM_B);
    // convert to A hi/lo (swizzled)
#pragma unroll
    for (int k = 0; k < 4; ++k) {
        int it = tid + k * MTHREADS;
        int c = it >> 5, kb = (it >> 3) & 3, gn = it & 7;
        const float* src = stgf + c * 264 + kb * 64 + gn * 8;
        uint32_t hw[4], lw[4];
#pragma unroll
        for (int p = 0; p < 4; ++p) {
            float v0 = src[2 * p], v1 = src[2 * p + 1];
            uint16_t h0 = bf16_bits(v0), h1 = bf16_bits(v1);
            uint16_t l0 = bf16_bits(v0 - bf16_val(h0));
            uint16_t l1 = bf16_bits(v1 - bf16_val(h1));
            hw[p] = (uint32_t)h0 | ((uint32_t)h1 << 16);
            lw[p] = (uint32_t)l0 | ((uint32_t)l1 << 16);
        }
        uint32_t off = (uint32_t)(c * 128 + ((gn * 16) ^ ((c & 7) << 4)));
        *(uint4*)(smem + SM_A + kb * 8192 + off)         = make_uint4(hw[0], hw[1], hw[2], hw[3]);
        *(uint4*)(smem + SM_A + 32768 + kb * 8192 + off) = make_uint4(lw[0], lw[1], lw[2], lw[3]);
    }
    // att dots: a_s[c,h], a_d[c,h]
    float* as_s = (float*)(smem + SM_ASAD);
    float* ad_s = (float*)(smem + SM_ASAD + 2048);
#pragma unroll
    for (int k = 0; k < 2; ++k) {
        int task = tid + k * MTHREADS;
        int c = task >> 4, hv = task & 15, h = hv & 7, sd = hv >> 3;
        const float* sr = stgf + c * 264;
        const float* vr = vt + hv;
        float acc = 0.f;
#pragma unroll 8
        for (int d = 0; d < 256; ++d) acc += sr[d] * vr[d * 17];
        (sd ? ad_s : as_s)[h * 64 + c] = acc;
    }
    __syncthreads();   // staging & vt dead after this

    // issue first B chunk (nt=0, kb=0) into buf 0
    {
        const char* gh = (const char*)g_ghi;
        const char* gl = (const char*)g_glo;
#pragma unroll
        for (int ii = 0; ii < 4; ++ii) {
            int it = tid + ii * MTHREADS;
            int s = it >> 10, r = (it >> 3) & 127, q = it & 7;
            CP_ASYNC16(sb + SM_B + (uint32_t)(s * 16384 + r * 128 + ((q * 16) ^ ((r & 7) << 4))),
                       (s ? gl : gh) + ((size_t)r * 512 + q * 16));
        }
        CP_COMMIT();
    }

    // ---------------- frag geometry ----------------
    const int mw2 = w & 3, nw2 = w >> 2;   // gemm: 4m x 4n (M64 N128)
    const int arow_g = mw2 * 16 + (l & 15);
    const uint32_t aoff = (uint32_t)(arow_g * 128);
    const uint32_t akx = (uint32_t)((arow_g & 7) << 4);
    const uint32_t akoff = (uint32_t)((l >> 4) * 16);
    int boff[2]; uint32_t bkx[2];
#pragma unroll
    for (int p = 0; p < 2; ++p) {
        int r = nw2 * 32 + p * 16 + (l & 7) + (l >> 4) * 8;
        boff[p] = r * 128;
        bkx[p] = (uint32_t)((r & 7) << 4);
    }
    const uint32_t bkoff = (uint32_t)(((l >> 3) & 1) * 16);
    // agg: alpha (non-trans) + wx (trans)
    const uint32_t aoffA = (uint32_t)(((mw2 * 16 + (l & 15)) * 72 + (l >> 4) * 8) * 2);
    const int aggI = (l & 7) + ((l >> 3) & 1) * 8;
    const int aggF = nw2 * 32 + (l >> 4) * 8;

    uint16_t* alh = (uint16_t*)(smem + SM_ALPHA);
    uint16_t* allo = (uint16_t*)(smem + SM_ALPHA + 9216);

    unsigned long long msk[4];
#pragma unroll
    for (int jj = 0; jj < 4; ++jj) msk[jj] = g_maskcol[b * NC + w * 4 + jj];

    float wx_acc[4][4];
#pragma unroll
    for (int g = 0; g < 4; ++g)
#pragma unroll
        for (int q = 0; q < 4; ++q) wx_acc[g][q] = 0.f;
    float out_acc[2][4][4];
#pragma unroll
    for (int hh = 0; hh < 2; ++hh)
#pragma unroll
        for (int g = 0; g < 4; ++g)
#pragma unroll
            for (int q = 0; q < 4; ++q) out_acc[hh][g][q] = 0.f;

    const float NEGINF = __int_as_float(0xff800000);
    const char* ghp = (const char*)g_ghi;
    const char* glp = (const char*)g_glo;
    int buf = 0;

    // ---------------- main loop ----------------
    for (int nt = 0; nt < 16; ++nt) {
        const int hh = nt & 1;
        for (int kb = 0; kb < 4; ++kb) {
            const int have_next = !(nt == 15 && kb == 3);
            if (have_next) {
                int nn = nt + (kb == 3);
                int nk = (kb + 1) & 3;
                int b2 = buf ^ 1;
#pragma unroll
                for (int ii = 0; ii < 4; ++ii) {
                    int it = tid + ii * MTHREADS;
                    int s = it >> 10, r = (it >> 3) & 127, q = it & 7;
                    CP_ASYNC16(sb + SM_B + (uint32_t)(b2 * 32768 + s * 16384 + r * 128 + ((q * 16) ^ ((r & 7) << 4))),
                               (s ? glp : ghp) + ((size_t)(nn * 128 + r) * 512 + nk * 128 + q * 16));
                }
                CP_COMMIT();
                CP_WAIT1();
            } else {
                CP_WAIT0();
            }
            __syncthreads();

            // gemm mma on buf
            const uint32_t pAh = sb + SM_A + (uint32_t)(kb * 8192);
            const uint32_t pAl = pAh + 32768;
            const uint32_t pBh = sb + SM_B + (uint32_t)(buf * 32768);
            const uint32_t pBl = pBh + 16384;
#pragma unroll
            for (int ks = 0; ks < 4; ++ks) {
                uint32_t ah[4], al[4], bh[2][4], bl[2][4];
                uint32_t akb = ((uint32_t)(ks * 32) + akoff) ^ akx;
                ldsm_x4(ah, pAh + aoff + akb);
                ldsm_x4(al, pAl + aoff + akb);
#pragma unroll
                for (int p = 0; p < 2; ++p) {
                    uint32_t kbyte = ((uint32_t)(ks * 32) + bkoff) ^ bkx[p];
                    ldsm_x4(bh[p], pBh + boff[p] + kbyte);
                    ldsm_x4(bl[p], pBl + boff[p] + kbyte);
                }
#pragma unroll
                for (int g = 0; g < 4; ++g) {
                    const int p = g >> 1, o = (g & 1) * 2;
                    mma16816(wx_acc[g], ah, &bh[p][o]);
                    mma16816(wx_acc[g], ah, &bl[p][o]);
                    mma16816(wx_acc[g], al, &bh[p][o]);
                }
            }

            if (kb == 3) {
                // ---- store wx tile (bf16 hi/lo, swizzled) ----
                int r1 = mw2 * 16 + (l >> 2);
#pragma unroll
                for (int g = 0; g < 4; ++g) {
                    int f = nw2 * 32 + g * 8 + (l & 3) * 2;
                    int fh = f >> 6, fb = (f & 63) * 2;
#pragma unroll
                    for (int half = 0; half < 2; ++half) {
                        int r = r1 + half * 8;
                        float a0 = wx_acc[g][half * 2], a1 = wx_acc[g][half * 2 + 1];
                        uint16_t h0 = bf16_bits(a0), h1 = bf16_bits(a1);
                        uint16_t l0 = bf16_bits(a0 - bf16_val(h0));
                        uint16_t l1 = bf16_bits(a1 - bf16_val(h1));
                        uint32_t off = (uint32_t)((r * 2 + fh) * 128 + (fb ^ ((r & 7) << 4)));
                        *(uint32_t*)(smem + SM_WX + off)         = (uint32_t)h0 | ((uint32_t)h1 << 16);
                        *(uint32_t*)(smem + SM_WX + 16384 + off) = (uint32_t)l0 | ((uint32_t)l1 << 16);
                    }
                    wx_acc[g][0] = wx_acc[g][1] = wx_acc[g][2] = wx_acc[g][3] = 0.f;
                }
                // ---- softmax (once per head, when hh==0) ----
                if (hh == 0) {
                    int h = nt >> 1;
#pragma unroll
                    for (int jj = 0; jj < 4; ++jj) {
                        int j = w * 4 + jj;
                        unsigned long long m = msk[jj];
                        float adj = ad_s[h * 64 + j];
                        int i0 = l, i1 = l + 32;
                        float e0 = as_s[h * 64 + i0] + adj;
                        float e1 = as_s[h * 64 + i1] + adj;
                        e0 = e0 > 0.f ? e0 : 0.2f * e0;
                        e1 = e1 > 0.f ? e1 : 0.2f * e1;
                        bool m0 = (m >> i0) & 1ull;
                        bool m1 = (m >> i1) & 1ull;
                        float mx = fmaxf(m0 ? e0 : NEGINF, m1 ? e1 : NEGINF);
#pragma unroll
                        for (int off = 16; off > 0; off >>= 1)
                            mx = fmaxf(mx, __shfl_xor_sync(0xffffffffu, mx, off));
                        float p0 = m0 ? expf(e0 - mx) : 0.f;
                        float p1 = m1 ? expf(e1 - mx) : 0.f;
                        float ssum = p0 + p1;
#pragma unroll
                        for (int off = 16; off > 0; off >>= 1)
                            ssum += __shfl_xor_sync(0xffffffffu, ssum, off);
                        float invs = 1.0f / ssum;
                        float a0 = p0 * invs, a1 = p1 * invs;
                        uint16_t h0 = bf16_bits(a0);
                        uint16_t h1 = bf16_bits(a1);
                        alh[j * 72 + i0] = h0;
                        alh[j * 72 + i1] = h1;
                        allo[j * 72 + i0] = bf16_bits(a0 - bf16_val(h0));
                        allo[j * 72 + i1] = bf16_bits(a1 - bf16_val(h1));
                    }
                }
                __syncthreads();

                // ---- agg mma: out_acc[hh] += alpha^T @ wx ----
#pragma unroll
                for (int ks = 0; ks < 4; ++ks) {
                    uint32_t aah[4], aal[4], wbh[2][4], wbl[2][4];
                    uint32_t ab = aoffA + (uint32_t)(ks * 32);
                    ldsm_x4(aah, sb + SM_ALPHA + ab);
                    ldsm_x4(aal, sb + SM_ALPHA + 9216 + ab);
#pragma unroll
                    for (int nt2 = 0; nt2 < 2; ++nt2) {
                        int i = ks * 16 + aggI;
                        int f = aggF + nt2 * 16;
                        uint32_t off = (uint32_t)((i * 2 + (f >> 6)) * 128 + (((f & 63) * 2) ^ ((i & 7) << 4)));
                        ldsm_x4_t(wbh[nt2], sb + SM_WX + off);
                        ldsm_x4_t(wbl[nt2], sb + SM_WX + 16384 + off);
                    }
#pragma unroll
                    for (int q = 0; q < 4; ++q) {
                        const int nt2 = q >> 1, o = (q & 1) * 2;
                        mma16816(out_acc[hh][q], aah, &wbh[nt2][o]);
                        mma16816(out_acc[hh][q], aah, &wbl[nt2][o]);
                        mma16816(out_acc[hh][q], aal, &wbh[nt2][o]);
                    }
                }
            }
            __syncthreads();
            buf ^= 1;
        }
    }

    // ---------------- epilogue: mean heads + bias ----------------
    const float inv8 = 0.125f;
    int j0 = mw2 * 16 + (l >> 2);
#pragma unroll
    for (int hh = 0; hh < 2; ++hh) {
#pragma unroll
        for (int q = 0; q < 4; ++q) {
            int f = hh * 128 + nw2 * 32 + q * 8 + (l & 3) * 2;
            float b0 = __ldg(gat_bias + f), b1 = __ldg(gat_bias + f + 1);
            float2 v0 = make_float2(out_acc[hh][q][0] * inv8 + b0, out_acc[hh][q][1] * inv8 + b1);
            float2 v1 = make_float2(out_acc[hh][q][2] * inv8 + b0, out_acc[hh][q][3] * inv8 + b1);
            *(float2*)(out + (((size_t)b * NC + j0) * NT + t) * ND + f) = v0;
            *(float2*)(out + (((size_t)b * NC + j0 + 8) * NT + t) * ND + f) = v1;
        }
    }
}

// ======================= launch =======================
extern "C" void kernel_launch(void* const* d_in, const int* in_sizes, int n_in,
                              void* d_out, int out_size) {
    const float* x          = (const float*)d_in[0];
    const float* static_adj = (const float*)d_in[1];
    const float* w_q        = (const float*)d_in[2];
    const float* w_k        = (const float*)d_in[3];
    const float* gat_lin    = (const float*)d_in[4];
    const float* att_src    = (const float*)d_in[5];
    const float* att_dst    = (const float*)d_in[6];
    const float* gat_bias   = (const float*)d_in[7];

    float* out = (float*)d_out;
    float* delta_out = out + (size_t)NB * NC * NT * ND;

    cudaFuncSetAttribute(k_main, cudaFuncAttributeMaxDynamicSharedMemorySize, SM_MAIN);

    // k_main is the 6th launch so ncu (-s 5 -c 1) profiles it
    k_vsd<<<16, 256>>>(gat_lin, att_src, att_dst);             // 1
    k_splitG<<<(NG_ELEMS + 255) / 256, 256>>>(gat_lin);        // 2
    k_hmean<<<NB * NC, 256>>>(x);                              // 3
    k_qk<<<NB * NC / 8, 256>>>(w_q, w_k);                      // 4
    k_simtopk<<<NB * 4, 256>>>(static_adj, delta_out);         // 5
    k_main<<<NB * NT, MTHREADS, SM_MAIN>>>(x, gat_bias, out);  // 6
}

// round 9
// speedup vs baseline: 3.3517x; 1.0091x over previous
#include <cuda_runtime.h>
#include <cuda_bf16.h>
#include <math.h>
#include <stdint.h>
#include <string.h>

#define NB 16
#define NC 64
#define NT 128
#define ND 256
#define NH 8
#define NKD 32
#define NTOPK 8

// ======================= helpers =======================
__device__ __forceinline__ uint32_t smem_to_u32(const void* p) {
    uint32_t a;
    asm("{ .reg .u64 t; cvta.to.shared.u64 t, %1; cvt.u32.u64 %0, t; }" : "=r"(a) : "l"(p));
    return a;
}
#define CP_ASYNC16(sa, gp) \
    asm volatile("cp.async.cg.shared.global [%0], [%1], 16;" :: "r"(sa), "l"(gp))
#define CP_COMMIT() asm volatile("cp.async.commit_group;")
#define CP_WAIT0()  asm volatile("cp.async.wait_group 0;")
#define CP_WAIT1()  asm volatile("cp.async.wait_group 1;")
#define CP_WAIT2()  asm volatile("cp.async.wait_group 2;")

__device__ __forceinline__ void ldsm_x4(uint32_t* r, uint32_t addr) {
    asm volatile("ldmatrix.sync.aligned.m8n8.x4.shared.b16 {%0,%1,%2,%3}, [%4];"
                 : "=r"(r[0]), "=r"(r[1]), "=r"(r[2]), "=r"(r[3]) : "r"(addr));
}
__device__ __forceinline__ void ldsm_x4_t(uint32_t* r, uint32_t addr) {
    asm volatile("ldmatrix.sync.aligned.m8n8.x4.trans.shared.b16 {%0,%1,%2,%3}, [%4];"
                 : "=r"(r[0]), "=r"(r[1]), "=r"(r[2]), "=r"(r[3]) : "r"(addr));
}
__device__ __forceinline__ void mma16816(float* d, const uint32_t* a, const uint32_t* b) {
    asm volatile(
        "mma.sync.aligned.m16n8k16.row.col.f32.bf16.bf16.f32 "
        "{%0,%1,%2,%3}, {%4,%5,%6,%7}, {%8,%9}, {%0,%1,%2,%3};"
        : "+f"(d[0]), "+f"(d[1]), "+f"(d[2]), "+f"(d[3])
        : "r"(a[0]), "r"(a[1]), "r"(a[2]), "r"(a[3]), "r"(b[0]), "r"(b[1]));
}
__device__ __forceinline__ uint16_t bf16_bits(float v) {
    __nv_bfloat16 h = __float2bfloat16(v);
    uint16_t b; memcpy(&b, &h, 2);
    return b;
}
__device__ __forceinline__ float bf16_val(uint16_t b) {
    __nv_bfloat16 h; memcpy(&h, &b, 2);
    return __bfloat162float(h);
}

// ======================= device scratch =======================
__device__ float g_hmean[NB * NC * ND];
__device__ float g_q[NB * NC * NKD];
__device__ float g_k[NB * NC * NKD];
__device__ unsigned long long g_maskcol[NB * NC];
__device__ float g_vsrc[NH * ND];
__device__ float g_vdst[NH * ND];
__device__ __nv_bfloat16 g_ghi[NH * ND * ND];
__device__ __nv_bfloat16 g_glo[NH * ND * ND];

// ======================= kernel: G hi/lo split =======================
#define NG_ELEMS 524288u
__global__ void k_splitG(const float* __restrict__ g) {
    uint32_t i = blockIdx.x * blockDim.x + threadIdx.x;
    if (i >= NG_ELEMS) return;
    float v = g[i];
    __nv_bfloat16 hi = __float2bfloat16(v);
    float r = v - __bfloat162float(hi);
    g_ghi[i] = hi;
    g_glo[i] = __float2bfloat16(r);
}

// ======================= kernel: temporal mean =======================
__global__ void k_hmean(const float* __restrict__ x) {
    int bc = blockIdx.x;
    int d = threadIdx.x;
    const float* p = x + (size_t)bc * NT * ND + d;
    float s = 0.f;
#pragma unroll 8
    for (int t = 0; t < NT; ++t) s += p[(size_t)t * ND];
    g_hmean[bc * ND + d] = s * (1.0f / NT);
}

// ======================= kernel: v_src/v_dst =======================
__global__ void k_vsd(const float* __restrict__ gat_lin,
                      const float* __restrict__ att_src,
                      const float* __restrict__ att_dst) {
    int h = blockIdx.x & 7;
    int isdst = blockIdx.x >> 3;
    int d = threadIdx.x;
    const float* att = isdst ? att_dst : att_src;
    float acc = 0.f;
#pragma unroll 4
    for (int f = 0; f < ND; ++f)
        acc += att[h * ND + f] * gat_lin[((size_t)(h * ND + f)) * ND + d];
    (isdst ? g_vdst : g_vsrc)[h * ND + d] = acc;
}

// ======================= kernel: q/k projections + self-loop init =======================
__global__ __launch_bounds__(256)
void k_qk(const float* __restrict__ w_q, const float* __restrict__ w_k) {
    __shared__ float hs[8 * ND];
    int blk = blockIdx.x;
    int tid = threadIdx.x;
    for (int it = tid; it < 8 * ND; it += 256) hs[it] = g_hmean[(size_t)blk * 8 * ND + it];
    if (tid < 8) g_maskcol[blk * 8 + tid] = 1ull << ((blk * 8 + tid) & 63);
    __syncthreads();
#pragma unroll
    for (int k = 0; k < 2; ++k) {
        int o = tid + k * 256;
        int bcL = o >> 6, rem = o & 63;
        int which = rem >> 5, kd = rem & 31;
        const float4* w4 = (const float4*)((which ? w_k : w_q) + (size_t)kd * ND);
        const float* hr = hs + bcL * ND;
        float acc = 0.f;
#pragma unroll 8
        for (int d4 = 0; d4 < 64; ++d4) {
            float4 wv = __ldg(w4 + d4);
            acc += hr[d4 * 4] * wv.x + hr[d4 * 4 + 1] * wv.y
                 + hr[d4 * 4 + 2] * wv.z + hr[d4 * 4 + 3] * wv.w;
        }
        (which ? g_k : g_q)[(blk * 8 + bcL) * NKD + kd] = acc;
    }
}

// ======================= kernel: sim + tanh + top-k (merged) =======================
__global__ __launch_bounds__(256)
void k_simtopk(const float* __restrict__ static_adj, float* __restrict__ delta_out) {
    __shared__ float qs[16 * NKD];
    __shared__ float ks_[NC * NKD];
    __shared__ float arow[16 * NC];
    int b = blockIdx.x >> 2;
    int i0 = (blockIdx.x & 3) * 16;
    int tid = threadIdx.x;
    for (int it = tid; it < NC * NKD; it += 256) ks_[it] = g_k[b * NC * NKD + it];
    for (int it = tid; it < 16 * NKD; it += 256) qs[it] = g_q[b * NC * NKD + i0 * NKD + it];
    __syncthreads();
    const float inv = 0.17677669529663687f;
    for (int task = tid; task < 16 * NC; task += 256) {
        int i = task >> 6, j = task & 63;
        float acc = 0.f;
#pragma unroll
        for (int kd = 0; kd < NKD; ++kd) acc += qs[i * NKD + kd] * ks_[j * NKD + kd];
        float delta = tanhf(acc * inv);
        int gi = i0 + i;
        delta_out[b * NC * NC + gi * NC + j] = delta;
        arow[task] = static_adj[gi * NC + j] + delta;
    }
    __syncthreads();
    int w = tid >> 5, lane = tid & 31;
#pragma unroll
    for (int rr = 0; rr < 2; ++rr) {
        int i = w * 2 + rr;
        int gi = i0 + i;
        float v0 = fabsf(arow[i * NC + lane]);
        float v1 = fabsf(arow[i * NC + lane + 32]);
        for (int s = 0; s < NTOPK; ++s) {
            float bv; int bj;
            if (v0 >= v1) { bv = v0; bj = lane; } else { bv = v1; bj = lane + 32; }
#pragma unroll
            for (int off = 16; off > 0; off >>= 1) {
                float ov = __shfl_xor_sync(0xffffffffu, bv, off);
                int   oj = __shfl_xor_sync(0xffffffffu, bj, off);
                if (ov > bv || (ov == bv && oj < bj)) { bv = ov; bj = oj; }
            }
            if (lane == 0) atomicOr(&g_maskcol[b * NC + bj], 1ull << gi);
            if (bj == lane)      v0 = -1.0f;
            if (bj == lane + 32) v1 = -1.0f;
        }
    }
}

// ======================= kernel: FUSED gemm + softmax + aggregation =======================
// CTA = (b, t). 3-stage cp.async pipeline on B (G) with 2-compute-phase flight.
#define MTHREADS 512
#define SM_A 0                       // 65536: fp32 staging, then [split2][kb4][64 r][128B]
#define SM_B 65536                   // 98304: 3 stages x ([split2][128 r][128B])
#define SM_WX 163840                 // 32768
#define SM_ALPHA 196608              // 18432 (vt overlay in prologue)
#define SM_ASAD 215040               // 4096
#define SM_MAIN (SM_ASAD + 4096)     // 219136

__global__ __launch_bounds__(MTHREADS, 1)
void k_main(const float* __restrict__ x,
            const float* __restrict__ gat_bias,
            float* __restrict__ out) {
    extern __shared__ char smem[];
    uint32_t sb = smem_to_u32(smem);
    const int tid = threadIdx.x;
    const int w = tid >> 5, l = tid & 31;
    const int bx = blockIdx.x;
    const int b = bx >> 7, t = bx & 127;

    const char* ghp = (const char*)g_ghi;
    const char* glp = (const char*)g_glo;

    // ---------------- prologue ----------------
    // 1) X (fp32) -> A region via cp.async (group 0)
#pragma unroll
    for (int ii = 0; ii < 8; ++ii) {
        int it = tid + ii * MTHREADS;          // 0..4095
        int c = it >> 6, q = it & 63;
        CP_ASYNC16(sb + SM_A + (uint32_t)(c * 1024 + q * 16),
                   x + (((size_t)(b * 64 + c) * 128) + t) * 256 + q * 4);
    }
    CP_COMMIT();
    // 2) B stages for steps 0 and 1 (groups 1, 2)
#pragma unroll
    for (int st = 0; st < 2; ++st) {
#pragma unroll
        for (int ii = 0; ii < 4; ++ii) {
            int it = tid + ii * MTHREADS;
            int s = it >> 10, r = (it >> 3) & 127, q = it & 7;
            CP_ASYNC16(sb + SM_B + (uint32_t)(st * 32768 + s * 16384 + r * 128 + ((q * 16) ^ ((r & 7) << 4))),
                       (s ? glp : ghp) + ((size_t)r * 512 + st * 128 + q * 16));
        }
        CP_COMMIT();
    }
    // 3) vt into ALPHA overlay (regular loads)
    float* vt = (float*)(smem + SM_ALPHA);
    for (int it = tid; it < 2048; it += MTHREADS) {
        int h = it >> 8, d = it & 255;
        vt[d * 17 + h]     = g_vsrc[it];
        vt[d * 17 + 8 + h] = g_vdst[it];
    }
    CP_WAIT2();          // X landed (B0, B1 may pend)
    __syncthreads();

    // 4) att dots from fp32 X in A region
    const float* stgf = (const float*)smem;   // [c][256]
    float* as_s = (float*)(smem + SM_ASAD);
    float* ad_s = (float*)(smem + SM_ASAD + 2048);
#pragma unroll
    for (int k = 0; k < 2; ++k) {
        int task = tid + k * MTHREADS;
        int c = task >> 4, hv = task & 15, h = hv & 7, sd = hv >> 3;
        const float* sr = stgf + c * 256;
        const float* vr = vt + hv;
        float acc = 0.f;
#pragma unroll 8
        for (int d = 0; d < 256; ++d) acc += sr[d] * vr[d * 17];
        (sd ? ad_s : as_s)[h * 64 + c] = acc;
    }
    // 5) in-place bf16 split: read all to regs, sync, write
    float xr[4][8];
#pragma unroll
    for (int k = 0; k < 4; ++k) {
        int it = tid + k * MTHREADS;           // 0..2047
        int c = it >> 5, kb = (it >> 3) & 3, gn = it & 7;
        const float* src = stgf + c * 256 + kb * 64 + gn * 8;
#pragma unroll
        for (int p = 0; p < 8; ++p) xr[k][p] = src[p];
    }
    __syncthreads();
#pragma unroll
    for (int k = 0; k < 4; ++k) {
        int it = tid + k * MTHREADS;
        int c = it >> 5, kb = (it >> 3) & 3, gn = it & 7;
        uint32_t hw[4], lw[4];
#pragma unroll
        for (int p = 0; p < 4; ++p) {
            float v0 = xr[k][2 * p], v1 = xr[k][2 * p + 1];
            uint16_t h0 = bf16_bits(v0), h1 = bf16_bits(v1);
            uint16_t l0 = bf16_bits(v0 - bf16_val(h0));
            uint16_t l1 = bf16_bits(v1 - bf16_val(h1));
            hw[p] = (uint32_t)h0 | ((uint32_t)h1 << 16);
            lw[p] = (uint32_t)l0 | ((uint32_t)l1 << 16);
        }
        uint32_t off = (uint32_t)(c * 128 + ((gn * 16) ^ ((c & 7) << 4)));
        *(uint4*)(smem + SM_A + kb * 8192 + off)         = make_uint4(hw[0], hw[1], hw[2], hw[3]);
        *(uint4*)(smem + SM_A + 32768 + kb * 8192 + off) = make_uint4(lw[0], lw[1], lw[2], lw[3]);
    }
    // NOTE: no sync here; loop-top sync covers convert-writes before first ldsm.

    // ---------------- frag geometry ----------------
    const int mw2 = w & 3, nw2 = w >> 2;
    const int arow_g = mw2 * 16 + (l & 15);
    const uint32_t aoff = (uint32_t)(arow_g * 128);
    const uint32_t akx = (uint32_t)((arow_g & 7) << 4);
    const uint32_t akoff = (uint32_t)((l >> 4) * 16);
    int boff[2]; uint32_t bkx[2];
#pragma unroll
    for (int p = 0; p < 2; ++p) {
        int r = nw2 * 32 + p * 16 + (l & 7) + (l >> 4) * 8;
        boff[p] = r * 128;
        bkx[p] = (uint32_t)((r & 7) << 4);
    }
    const uint32_t bkoff = (uint32_t)(((l >> 3) & 1) * 16);
    const uint32_t aoffA = (uint32_t)(((mw2 * 16 + (l & 15)) * 72 + (l >> 4) * 8) * 2);
    const int aggI = (l & 7) + ((l >> 3) & 1) * 8;
    const int aggF = nw2 * 32 + (l >> 4) * 8;

    uint16_t* alh = (uint16_t*)(smem + SM_ALPHA);
    uint16_t* allo = (uint16_t*)(smem + SM_ALPHA + 9216);

    unsigned long long msk[4];
#pragma unroll
    for (int jj = 0; jj < 4; ++jj) msk[jj] = g_maskcol[b * NC + w * 4 + jj];

    float wx_acc[4][4];
#pragma unroll
    for (int g = 0; g < 4; ++g)
#pragma unroll
        for (int q = 0; q < 4; ++q) wx_acc[g][q] = 0.f;
    float out_acc[2][4][4];
#pragma unroll
    for (int hh = 0; hh < 2; ++hh)
#pragma unroll
        for (int g = 0; g < 4; ++g)
#pragma unroll
            for (int q = 0; q < 4; ++q) out_acc[hh][g][q] = 0.f;

    const float NEGINF = __int_as_float(0xff800000);

    // ---------------- main loop: 64 steps, 3-stage pipeline ----------------
    for (int step = 0; step < 64; ++step) {
        const int nt = step >> 2, kb = step & 3;
        CP_WAIT1();          // group for this step landed (next one may pend)
        __syncthreads();     // visibility + all warps done with step-1

        // issue group step+2 into stage (step+2)%3 (dummy reload at tail)
        {
            int is = step + 2;
            int nn, nk;
            if (is < 64) { nn = is >> 2; nk = is & 3; } else { nn = 15; nk = 3; }
            int bs = is % 3;
#pragma unroll
            for (int ii = 0; ii < 4; ++ii) {
                int it = tid + ii * MTHREADS;
                int s = it >> 10, r = (it >> 3) & 127, q = it & 7;
                CP_ASYNC16(sb + SM_B + (uint32_t)(bs * 32768 + s * 16384 + r * 128 + ((q * 16) ^ ((r & 7) << 4))),
                           (s ? glp : ghp) + ((size_t)(nn * 128 + r) * 512 + nk * 128 + q * 16));
            }
            CP_COMMIT();
        }

        // gemm mma on stage step%3
        const int bs0 = step % 3;
        const uint32_t pAh = sb + SM_A + (uint32_t)(kb * 8192);
        const uint32_t pAl = pAh + 32768;
        const uint32_t pBh = sb + SM_B + (uint32_t)(bs0 * 32768);
        const uint32_t pBl = pBh + 16384;
#pragma unroll
        for (int ks = 0; ks < 4; ++ks) {
            uint32_t ah[4], al[4], bh[2][4], bl[2][4];
            uint32_t akb = ((uint32_t)(ks * 32) + akoff) ^ akx;
            ldsm_x4(ah, pAh + aoff + akb);
            ldsm_x4(al, pAl + aoff + akb);
#pragma unroll
            for (int p = 0; p < 2; ++p) {
                uint32_t kbyte = ((uint32_t)(ks * 32) + bkoff) ^ bkx[p];
                ldsm_x4(bh[p], pBh + boff[p] + kbyte);
                ldsm_x4(bl[p], pBl + boff[p] + kbyte);
            }
#pragma unroll
            for (int g = 0; g < 4; ++g) {
                const int p = g >> 1, o = (g & 1) * 2;
                mma16816(wx_acc[g], ah, &bh[p][o]);
                mma16816(wx_acc[g], ah, &bl[p][o]);
                mma16816(wx_acc[g], al, &bh[p][o]);
            }
        }

        if (kb == 3) {
            const int hh = nt & 1;
            // store wx tile (bf16 hi/lo, swizzled)
            int r1 = mw2 * 16 + (l >> 2);
#pragma unroll
            for (int g = 0; g < 4; ++g) {
                int f = nw2 * 32 + g * 8 + (l & 3) * 2;
                int fh = f >> 6, fb = (f & 63) * 2;
#pragma unroll
                for (int half = 0; half < 2; ++half) {
                    int r = r1 + half * 8;
                    float a0 = wx_acc[g][half * 2], a1 = wx_acc[g][half * 2 + 1];
                    uint16_t h0 = bf16_bits(a0), h1 = bf16_bits(a1);
                    uint16_t l0 = bf16_bits(a0 - bf16_val(h0));
                    uint16_t l1 = bf16_bits(a1 - bf16_val(h1));
                    uint32_t off = (uint32_t)((r * 2 + fh) * 128 + (fb ^ ((r & 7) << 4)));
                    *(uint32_t*)(smem + SM_WX + off)         = (uint32_t)h0 | ((uint32_t)h1 << 16);
                    *(uint32_t*)(smem + SM_WX + 16384 + off) = (uint32_t)l0 | ((uint32_t)l1 << 16);
                }
                wx_acc[g][0] = wx_acc[g][1] = wx_acc[g][2] = wx_acc[g][3] = 0.f;
            }
            // softmax once per head
            if (hh == 0) {
                int h = nt >> 1;
#pragma unroll
                for (int jj = 0; jj < 4; ++jj) {
                    int j = w * 4 + jj;
                    unsigned long long m = msk[jj];
                    float adj = ad_s[h * 64 + j];
                    int i0 = l, i1 = l + 32;
                    float e0 = as_s[h * 64 + i0] + adj;
                    float e1 = as_s[h * 64 + i1] + adj;
                    e0 = e0 > 0.f ? e0 : 0.2f * e0;
                    e1 = e1 > 0.f ? e1 : 0.2f * e1;
                    bool m0 = (m >> i0) & 1ull;
                    bool m1 = (m >> i1) & 1ull;
                    float mx = fmaxf(m0 ? e0 : NEGINF, m1 ? e1 : NEGINF);
#pragma unroll
                    for (int off = 16; off > 0; off >>= 1)
                        mx = fmaxf(mx, __shfl_xor_sync(0xffffffffu, mx, off));
                    float p0 = m0 ? expf(e0 - mx) : 0.f;
                    float p1 = m1 ? expf(e1 - mx) : 0.f;
                    float ssum = p0 + p1;
#pragma unroll
                    for (int off = 16; off > 0; off >>= 1)
                        ssum += __shfl_xor_sync(0xffffffffu, ssum, off);
                    float invs = 1.0f / ssum;
                    float a0 = p0 * invs, a1 = p1 * invs;
                    uint16_t h0 = bf16_bits(a0);
                    uint16_t h1 = bf16_bits(a1);
                    alh[j * 72 + i0] = h0;
                    alh[j * 72 + i1] = h1;
                    allo[j * 72 + i0] = bf16_bits(a0 - bf16_val(h0));
                    allo[j * 72 + i1] = bf16_bits(a1 - bf16_val(h1));
                }
            }
            __syncthreads();

            // agg mma: out_acc[hh] += alpha^T @ wx
#pragma unroll
            for (int ks = 0; ks < 4; ++ks) {
                uint32_t aah[4], aal[4], wbh[2][4], wbl[2][4];
                uint32_t ab = aoffA + (uint32_t)(ks * 32);
                ldsm_x4(aah, sb + SM_ALPHA + ab);
                ldsm_x4(aal, sb + SM_ALPHA + 9216 + ab);
#pragma unroll
                for (int nt2 = 0; nt2 < 2; ++nt2) {
                    int i = ks * 16 + aggI;
                    int f = aggF + nt2 * 16;
                    uint32_t off = (uint32_t)((i * 2 + (f >> 6)) * 128 + (((f & 63) * 2) ^ ((i & 7) << 4)));
                    ldsm_x4_t(wbh[nt2], sb + SM_WX + off);
                    ldsm_x4_t(wbl[nt2], sb + SM_WX + 16384 + off);
                }
#pragma unroll
                for (int q = 0; q < 4; ++q) {
                    const int nt2 = q >> 1, o = (q & 1) * 2;
                    mma16816(out_acc[hh][q], aah, &wbh[nt2][o]);
                    mma16816(out_acc[hh][q], aah, &wbl[nt2][o]);
                    mma16816(out_acc[hh][q], aal, &wbh[nt2][o]);
                }
            }
        }
    }

    // ---------------- epilogue: mean heads + bias ----------------
    const float inv8 = 0.125f;
    int j0 = mw2 * 16 + (l >> 2);
#pragma unroll
    for (int hh = 0; hh < 2; ++hh) {
#pragma unroll
        for (int q = 0; q < 4; ++q) {
            int f = hh * 128 + nw2 * 32 + q * 8 + (l & 3) * 2;
            float b0 = __ldg(gat_bias + f), b1 = __ldg(gat_bias + f + 1);
            float2 v0 = make_float2(out_acc[hh][q][0] * inv8 + b0, out_acc[hh][q][1] * inv8 + b1);
            float2 v1 = make_float2(out_acc[hh][q][2] * inv8 + b0, out_acc[hh][q][3] * inv8 + b1);
            *(float2*)(out + (((size_t)b * NC + j0) * NT + t) * ND + f) = v0;
            *(float2*)(out + (((size_t)b * NC + j0 + 8) * NT + t) * ND + f) = v1;
        }
    }
}

// ======================= launch =======================
extern "C" void kernel_launch(void* const* d_in, const int* in_sizes, int n_in,
                              void* d_out, int out_size) {
    const float* x          = (const float*)d_in[0];
    const float* static_adj = (const float*)d_in[1];
    const float* w_q        = (const float*)d_in[2];
    const float* w_k        = (const float*)d_in[3];
    const float* gat_lin    = (const float*)d_in[4];
    const float* att_src    = (const float*)d_in[5];
    const float* att_dst    = (const float*)d_in[6];
    const float* gat_bias   = (const float*)d_in[7];

    float* out = (float*)d_out;
    float* delta_out = out + (size_t)NB * NC * NT * ND;

    cudaFuncSetAttribute(k_main, cudaFuncAttributeMaxDynamicSharedMemorySize, SM_MAIN);

    k_vsd<<<16, 256>>>(gat_lin, att_src, att_dst);
    k_splitG<<<(NG_ELEMS + 255) / 256, 256>>>(gat_lin);
    k_hmean<<<NB * NC, 256>>>(x);
    k_qk<<<NB * NC / 8, 256>>>(w_q, w_k);
    k_simtopk<<<NB * 4, 256>>>(static_adj, delta_out);
    k_main<<<NB * NT, MTHREADS, SM_MAIN>>>(x, gat_bias, out);
}

// round 10
// speedup vs baseline: 4.5687x; 1.3631x over previous
#include <cuda_runtime.h>
#include <cuda_bf16.h>
#include <math.h>
#include <stdint.h>
#include <string.h>

#define NB 16
#define NC 64
#define NT 128
#define ND 256
#define NH 8
#define NKD 32
#define NTOPK 8

// ======================= helpers =======================
__device__ __forceinline__ uint32_t smem_to_u32(const void* p) {
    uint32_t a;
    asm("{ .reg .u64 t; cvta.to.shared.u64 t, %1; cvt.u32.u64 %0, t; }" : "=r"(a) : "l"(p));
    return a;
}
#define CP_ASYNC16(sa, gp) \
    asm volatile("cp.async.cg.shared.global [%0], [%1], 16;" :: "r"(sa), "l"(gp))
#define CP_COMMIT() asm volatile("cp.async.commit_group;")
#define CP_WAIT0()  asm volatile("cp.async.wait_group 0;")
#define CP_WAIT1()  asm volatile("cp.async.wait_group 1;")
#define CP_WAIT2()  asm volatile("cp.async.wait_group 2;")

__device__ __forceinline__ void ldsm_x4(uint32_t* r, uint32_t addr) {
    asm volatile("ldmatrix.sync.aligned.m8n8.x4.shared.b16 {%0,%1,%2,%3}, [%4];"
                 : "=r"(r[0]), "=r"(r[1]), "=r"(r[2]), "=r"(r[3]) : "r"(addr));
}
__device__ __forceinline__ void ldsm_x4_t(uint32_t* r, uint32_t addr) {
    asm volatile("ldmatrix.sync.aligned.m8n8.x4.trans.shared.b16 {%0,%1,%2,%3}, [%4];"
                 : "=r"(r[0]), "=r"(r[1]), "=r"(r[2]), "=r"(r[3]) : "r"(addr));
}
__device__ __forceinline__ void mma16816(float* d, const uint32_t* a, const uint32_t* b) {
    asm volatile(
        "mma.sync.aligned.m16n8k16.row.col.f32.bf16.bf16.f32 "
        "{%0,%1,%2,%3}, {%4,%5,%6,%7}, {%8,%9}, {%0,%1,%2,%3};"
        : "+f"(d[0]), "+f"(d[1]), "+f"(d[2]), "+f"(d[3])
        : "r"(a[0]), "r"(a[1]), "r"(a[2]), "r"(a[3]), "r"(b[0]), "r"(b[1]));
}
__device__ __forceinline__ void mma16832s8(int* d, const uint32_t* a, const uint32_t* b) {
    asm volatile(
        "mma.sync.aligned.m16n8k32.row.col.s32.s8.s8.s32 "
        "{%0,%1,%2,%3}, {%4,%5,%6,%7}, {%8,%9}, {%0,%1,%2,%3};"
        : "+r"(d[0]), "+r"(d[1]), "+r"(d[2]), "+r"(d[3])
        : "r"(a[0]), "r"(a[1]), "r"(a[2]), "r"(a[3]), "r"(b[0]), "r"(b[1]));
}
__device__ __forceinline__ uint16_t bf16_bits(float v) {
    __nv_bfloat16 h = __float2bfloat16(v);
    uint16_t b; memcpy(&b, &h, 2);
    return b;
}
__device__ __forceinline__ float bf16_val(uint16_t b) {
    __nv_bfloat16 h; memcpy(&h, &b, 2);
    return __bfloat162float(h);
}

// ======================= device scratch =======================
__device__ float g_hmean[NB * NC * ND];
__device__ float g_q[NB * NC * NKD];
__device__ float g_k[NB * NC * NKD];
__device__ unsigned long long g_maskcol[NB * NC];
__device__ float g_vsrc[NH * ND];
__device__ float g_vdst[NH * ND];
__device__ int8_t g_gh8[NH * ND * ND];   // G16 hi limbs [2048][256]
__device__ int8_t g_gl8[NH * ND * ND];   // G16 lo limbs

// ======================= kernel: G int16 quant + limb split =======================
__global__ void k_quantG(const float* __restrict__ g) {
    uint32_t i = blockIdx.x * 256 + threadIdx.x;   // 2048 blocks x 256
    float v = g[i] * 65536.f;
    int q = __float2int_rn(v);
    q = max(-32639, min(32639, q));
    int lo = ((q + 128) & 255) - 128;
    int hi = (q - lo) >> 8;
    g_gh8[i] = (int8_t)hi;
    g_gl8[i] = (int8_t)lo;
}

// ======================= kernel: temporal mean =======================
__global__ void k_hmean(const float* __restrict__ x) {
    int bc = blockIdx.x;
    int d = threadIdx.x;
    const float* p = x + (size_t)bc * NT * ND + d;
    float s = 0.f;
#pragma unroll 8
    for (int t = 0; t < NT; ++t) s += p[(size_t)t * ND];
    g_hmean[bc * ND + d] = s * (1.0f / NT);
}

// ======================= kernel: v_src/v_dst =======================
__global__ void k_vsd(const float* __restrict__ gat_lin,
                      const float* __restrict__ att_src,
                      const float* __restrict__ att_dst) {
    int h = blockIdx.x & 7;
    int isdst = blockIdx.x >> 3;
    int d = threadIdx.x;
    const float* att = isdst ? att_dst : att_src;
    float acc = 0.f;
#pragma unroll 4
    for (int f = 0; f < ND; ++f)
        acc += att[h * ND + f] * gat_lin[((size_t)(h * ND + f)) * ND + d];
    (isdst ? g_vdst : g_vsrc)[h * ND + d] = acc;
}

// ======================= kernel: q/k projections + self-loop init =======================
__global__ __launch_bounds__(256)
void k_qk(const float* __restrict__ w_q, const float* __restrict__ w_k) {
    __shared__ float hs[8 * ND];
    int blk = blockIdx.x;
    int tid = threadIdx.x;
    for (int it = tid; it < 8 * ND; it += 256) hs[it] = g_hmean[(size_t)blk * 8 * ND + it];
    if (tid < 8) g_maskcol[blk * 8 + tid] = 1ull << ((blk * 8 + tid) & 63);
    __syncthreads();
#pragma unroll
    for (int k = 0; k < 2; ++k) {
        int o = tid + k * 256;
        int bcL = o >> 6, rem = o & 63;
        int which = rem >> 5, kd = rem & 31;
        const float4* w4 = (const float4*)((which ? w_k : w_q) + (size_t)kd * ND);
        const float* hr = hs + bcL * ND;
        float acc = 0.f;
#pragma unroll 8
        for (int d4 = 0; d4 < 64; ++d4) {
            float4 wv = __ldg(w4 + d4);
            acc += hr[d4 * 4] * wv.x + hr[d4 * 4 + 1] * wv.y
                 + hr[d4 * 4 + 2] * wv.z + hr[d4 * 4 + 3] * wv.w;
        }
        (which ? g_k : g_q)[(blk * 8 + bcL) * NKD + kd] = acc;
    }
}

// ======================= kernel: sim + tanh + top-k (merged) =======================
__global__ __launch_bounds__(256)
void k_simtopk(const float* __restrict__ static_adj, float* __restrict__ delta_out) {
    __shared__ float qs[16 * NKD];
    __shared__ float ks_[NC * NKD];
    __shared__ float arow[16 * NC];
    int b = blockIdx.x >> 2;
    int i0 = (blockIdx.x & 3) * 16;
    int tid = threadIdx.x;
    for (int it = tid; it < NC * NKD; it += 256) ks_[it] = g_k[b * NC * NKD + it];
    for (int it = tid; it < 16 * NKD; it += 256) qs[it] = g_q[b * NC * NKD + i0 * NKD + it];
    __syncthreads();
    const float inv = 0.17677669529663687f;
    for (int task = tid; task < 16 * NC; task += 256) {
        int i = task >> 6, j = task & 63;
        float acc = 0.f;
#pragma unroll
        for (int kd = 0; kd < NKD; ++kd) acc += qs[i * NKD + kd] * ks_[j * NKD + kd];
        float delta = tanhf(acc * inv);
        int gi = i0 + i;
        delta_out[b * NC * NC + gi * NC + j] = delta;
        arow[task] = static_adj[gi * NC + j] + delta;
    }
    __syncthreads();
    int w = tid >> 5, lane = tid & 31;
#pragma unroll
    for (int rr = 0; rr < 2; ++rr) {
        int i = w * 2 + rr;
        int gi = i0 + i;
        float v0 = fabsf(arow[i * NC + lane]);
        float v1 = fabsf(arow[i * NC + lane + 32]);
        for (int s = 0; s < NTOPK; ++s) {
            float bv; int bj;
            if (v0 >= v1) { bv = v0; bj = lane; } else { bv = v1; bj = lane + 32; }
#pragma unroll
            for (int off = 16; off > 0; off >>= 1) {
                float ov = __shfl_xor_sync(0xffffffffu, bv, off);
                int   oj = __shfl_xor_sync(0xffffffffu, bj, off);
                if (ov > bv || (ov == bv && oj < bj)) { bv = ov; bj = oj; }
            }
            if (lane == 0) atomicOr(&g_maskcol[b * NC + bj], 1ull << gi);
            if (bj == lane)      v0 = -1.0f;
            if (bj == lane + 32) v1 = -1.0f;
        }
    }
}

// ======================= kernel: FUSED int8 gemm + softmax + bf16 aggregation =======================
// CTA = (b,t). GEMM in s8 IMMA (limb split, 3 terms, XlGl dropped), agg in bf16 HMMA.
#define MTHREADS 512
#define SM_A 0                       // 32768: [limb2][kb2][64 r][128B] int8, swizzled
#define SM_B 32768                   // 98304: 3 stages x [limb2][128 r][128B] int8
#define SM_WX 131072                 // 32768: wx bf16 hi/lo
#define SM_ALPHA 163840              // 18432 (vt overlay in prologue)
#define SM_ASAD 182272               // 4096
#define SM_MAIN (SM_ASAD + 4096)     // 186368
#define XSTG 98304                   // 64KB fp32 X staging (B stage2 + WX, dead zones in prologue)

__global__ __launch_bounds__(MTHREADS, 1)
void k_main(const float* __restrict__ x,
            const float* __restrict__ gat_bias,
            float* __restrict__ out) {
    extern __shared__ char smem[];
    uint32_t sb = smem_to_u32(smem);
    const int tid = threadIdx.x;
    const int w = tid >> 5, l = tid & 31;
    const int bx = blockIdx.x;
    const int b = bx >> 7, t = bx & 127;

    const char* ghp = (const char*)g_gh8;
    const char* glp = (const char*)g_gl8;

    // ---------------- prologue ----------------
    // 1) X (fp32) -> staging via cp.async (group 0)
#pragma unroll
    for (int ii = 0; ii < 8; ++ii) {
        int it = tid + ii * MTHREADS;          // 0..4095
        int c = it >> 6, q = it & 63;
        CP_ASYNC16(sb + XSTG + (uint32_t)(c * 1024 + q * 16),
                   x + (((size_t)(b * 64 + c) * 128) + t) * 256 + q * 4);
    }
    CP_COMMIT();
    // 2) B stages for steps 0,1 (groups 1,2): step = (nt, kb), kb in {0,1}, 128B per row-chunk
#pragma unroll
    for (int st = 0; st < 2; ++st) {           // (nt=0,kb=0), (nt=0,kb=1)
#pragma unroll
        for (int ii = 0; ii < 4; ++ii) {
            int it = tid + ii * MTHREADS;
            int s = it >> 10, r = (it >> 3) & 127, q = it & 7;
            CP_ASYNC16(sb + SM_B + (uint32_t)(st * 32768 + s * 16384 + r * 128 + ((q * 16) ^ ((r & 7) << 4))),
                       (s ? glp : ghp) + ((size_t)r * 256 + st * 128 + q * 16));
        }
        CP_COMMIT();
    }
    // 3) vt into ALPHA overlay
    float* vt = (float*)(smem + SM_ALPHA);
    for (int it = tid; it < 2048; it += MTHREADS) {
        int h = it >> 8, d = it & 255;
        vt[d * 17 + h]     = g_vsrc[it];
        vt[d * 17 + 8 + h] = g_vdst[it];
    }
    CP_WAIT2();
    __syncthreads();

    // 4) att dots from fp32 X staging
    const float* stgf = (const float*)(smem + XSTG);
    float* as_s = (float*)(smem + SM_ASAD);
    float* ad_s = (float*)(smem + SM_ASAD + 2048);
#pragma unroll
    for (int k = 0; k < 2; ++k) {
        int task = tid + k * MTHREADS;
        int c = task >> 4, hv = task & 15, h = hv & 7, sd = hv >> 3;
        const float* sr = stgf + c * 256;
        const float* vr = vt + hv;
        float acc = 0.f;
#pragma unroll 8
        for (int d = 0; d < 256; ++d) acc += sr[d] * vr[d * 17];
        (sd ? ad_s : as_s)[h * 64 + c] = acc;
    }
    // 5) X quantization: fp32 -> int16 -> int8 limbs into A region
#pragma unroll
    for (int k = 0; k < 2; ++k) {
        int it = tid + k * MTHREADS;           // 0..1023 groups of 16 elems
        int c = it >> 4, kb = (it >> 3) & 1, gn = it & 7;
        const float* src = stgf + c * 256 + kb * 128 + gn * 16;
        uint32_t hw[4], lw[4];
#pragma unroll
        for (int p = 0; p < 4; ++p) {
            uint32_t hpack = 0, lpack = 0;
#pragma unroll
            for (int e = 0; e < 4; ++e) {
                int q = __float2int_rn(src[p * 4 + e] * 4096.f);
                q = max(-32639, min(32639, q));
                int lo = ((q + 128) & 255) - 128;
                int hi = (q - lo) >> 8;
                hpack |= ((uint32_t)(uint8_t)(int8_t)hi) << (8 * e);
                lpack |= ((uint32_t)(uint8_t)(int8_t)lo) << (8 * e);
            }
            hw[p] = hpack; lw[p] = lpack;
        }
        uint32_t off = (uint32_t)(c * 128 + ((gn * 16) ^ ((c & 7) << 4)));
        *(uint4*)(smem + SM_A + kb * 8192 + off)         = make_uint4(hw[0], hw[1], hw[2], hw[3]);
        *(uint4*)(smem + SM_A + 16384 + kb * 8192 + off) = make_uint4(lw[0], lw[1], lw[2], lw[3]);
    }
    // loop-top sync covers these writes before first ldsm

    // ---------------- frag geometry ----------------
    const int mw2 = w & 3, nw2 = w >> 2;
    const int arow_g = mw2 * 16 + (l & 15);
    const uint32_t aoff = (uint32_t)(arow_g * 128);
    const uint32_t akx = (uint32_t)((arow_g & 7) << 4);
    const uint32_t akoff = (uint32_t)((l >> 4) * 16);
    int boff[2]; uint32_t bkx[2];
#pragma unroll
    for (int p = 0; p < 2; ++p) {
        int r = nw2 * 32 + p * 16 + (l & 7) + (l >> 4) * 8;
        boff[p] = r * 128;
        bkx[p] = (uint32_t)((r & 7) << 4);
    }
    const uint32_t bkoff = (uint32_t)(((l >> 3) & 1) * 16);
    const uint32_t aoffA = (uint32_t)(((mw2 * 16 + (l & 15)) * 72 + (l >> 4) * 8) * 2);
    const int aggI = (l & 7) + ((l >> 3) & 1) * 8;
    const int aggF = nw2 * 32 + (l >> 4) * 8;

    uint16_t* alh = (uint16_t*)(smem + SM_ALPHA);
    uint16_t* allo = (uint16_t*)(smem + SM_ALPHA + 9216);

    unsigned long long msk[4];
#pragma unroll
    for (int jj = 0; jj < 4; ++jj) msk[jj] = g_maskcol[b * NC + w * 4 + jj];

    int acc_hi[4][4], acc_mid[4][4];
#pragma unroll
    for (int g = 0; g < 4; ++g)
#pragma unroll
        for (int q = 0; q < 4; ++q) { acc_hi[g][q] = 0; acc_mid[g][q] = 0; }
    float out_acc[2][4][4];
#pragma unroll
    for (int hh = 0; hh < 2; ++hh)
#pragma unroll
        for (int g = 0; g < 4; ++g)
#pragma unroll
            for (int q = 0; q < 4; ++q) out_acc[hh][g][q] = 0.f;

    const float NEGINF = __int_as_float(0xff800000);
    const float COMB = 1.f / 268435456.f;   // 2^-28

    // ---------------- main loop: 32 steps (nt 16 x kb 2), 3-stage pipeline ----------------
    for (int step = 0; step < 32; ++step) {
        const int nt = step >> 1, kb = step & 1;
        CP_WAIT1();
        __syncthreads();

        // issue group step+2 into stage (step+2)%3
        {
            int is = step + 2;
            int nn, nk;
            if (is < 32) { nn = is >> 1; nk = is & 1; } else { nn = 15; nk = 1; }
            int bs = is % 3;
#pragma unroll
            for (int ii = 0; ii < 4; ++ii) {
                int it = tid + ii * MTHREADS;
                int s = it >> 10, r = (it >> 3) & 127, q = it & 7;
                CP_ASYNC16(sb + SM_B + (uint32_t)(bs * 32768 + s * 16384 + r * 128 + ((q * 16) ^ ((r & 7) << 4))),
                           (s ? glp : ghp) + ((size_t)(nn * 128 + r) * 256 + nk * 128 + q * 16));
            }
            CP_COMMIT();
        }

        // s8 IMMA on stage step%3
        const int bs0 = step % 3;
        const uint32_t pAh = sb + SM_A + (uint32_t)(kb * 8192);
        const uint32_t pAl = pAh + 16384;
        const uint32_t pBh = sb + SM_B + (uint32_t)(bs0 * 32768);
        const uint32_t pBl = pBh + 16384;
#pragma unroll
        for (int ks = 0; ks < 4; ++ks) {
            uint32_t ah[4], al[4], bh[2][4], bl[2][4];
            uint32_t akb = ((uint32_t)(ks * 32) + akoff) ^ akx;
            ldsm_x4(ah, pAh + aoff + akb);
            ldsm_x4(al, pAl + aoff + akb);
#pragma unroll
            for (int p = 0; p < 2; ++p) {
                uint32_t kbyte = ((uint32_t)(ks * 32) + bkoff) ^ bkx[p];
                ldsm_x4(bh[p], pBh + boff[p] + kbyte);
                ldsm_x4(bl[p], pBl + boff[p] + kbyte);
            }
#pragma unroll
            for (int g = 0; g < 4; ++g) {
                const int p = g >> 1, o = (g & 1) * 2;
                mma16832s8(acc_hi[g],  ah, &bh[p][o]);
                mma16832s8(acc_mid[g], ah, &bl[p][o]);
                mma16832s8(acc_mid[g], al, &bh[p][o]);
            }
        }

        if (kb == 1) {
            const int hh = nt & 1;
            // combine limb accumulators -> wx fp32 -> bf16 hi/lo smem tile
            int r1 = mw2 * 16 + (l >> 2);
#pragma unroll
            for (int g = 0; g < 4; ++g) {
                float wf[4];
#pragma unroll
                for (int q = 0; q < 4; ++q) {
                    wf[q] = ((float)acc_hi[g][q] * 65536.f + (float)acc_mid[g][q] * 256.f) * COMB;
                    acc_hi[g][q] = 0; acc_mid[g][q] = 0;
                }
                int f = nw2 * 32 + g * 8 + (l & 3) * 2;
                int fh = f >> 6, fb = (f & 63) * 2;
#pragma unroll
                for (int half = 0; half < 2; ++half) {
                    int r = r1 + half * 8;
                    float a0 = wf[half * 2], a1 = wf[half * 2 + 1];
                    uint16_t h0 = bf16_bits(a0), h1 = bf16_bits(a1);
                    uint16_t l0 = bf16_bits(a0 - bf16_val(h0));
                    uint16_t l1 = bf16_bits(a1 - bf16_val(h1));
                    uint32_t off = (uint32_t)((r * 2 + fh) * 128 + (fb ^ ((r & 7) << 4)));
                    *(uint32_t*)(smem + SM_WX + off)         = (uint32_t)h0 | ((uint32_t)h1 << 16);
                    *(uint32_t*)(smem + SM_WX + 16384 + off) = (uint32_t)l0 | ((uint32_t)l1 << 16);
                }
            }
            // softmax once per head
            if (hh == 0) {
                int h = nt >> 1;
#pragma unroll
                for (int jj = 0; jj < 4; ++jj) {
                    int j = w * 4 + jj;
                    unsigned long long m = msk[jj];
                    float adj = ad_s[h * 64 + j];
                    int i0 = l, i1 = l + 32;
                    float e0 = as_s[h * 64 + i0] + adj;
                    float e1 = as_s[h * 64 + i1] + adj;
                    e0 = e0 > 0.f ? e0 : 0.2f * e0;
                    e1 = e1 > 0.f ? e1 : 0.2f * e1;
                    bool m0 = (m >> i0) & 1ull;
                    bool m1 = (m >> i1) & 1ull;
                    float mx = fmaxf(m0 ? e0 : NEGINF, m1 ? e1 : NEGINF);
#pragma unroll
                    for (int off = 16; off > 0; off >>= 1)
                        mx = fmaxf(mx, __shfl_xor_sync(0xffffffffu, mx, off));
                    float p0 = m0 ? expf(e0 - mx) : 0.f;
                    float p1 = m1 ? expf(e1 - mx) : 0.f;
                    float ssum = p0 + p1;
#pragma unroll
                    for (int off = 16; off > 0; off >>= 1)
                        ssum += __shfl_xor_sync(0xffffffffu, ssum, off);
                    float invs = 1.0f / ssum;
                    float a0 = p0 * invs, a1 = p1 * invs;
                    uint16_t h0 = bf16_bits(a0);
                    uint16_t h1 = bf16_bits(a1);
                    alh[j * 72 + i0] = h0;
                    alh[j * 72 + i1] = h1;
                    allo[j * 72 + i0] = bf16_bits(a0 - bf16_val(h0));
                    allo[j * 72 + i1] = bf16_bits(a1 - bf16_val(h1));
                }
            }
            __syncthreads();

            // agg HMMA: out_acc[hh] += alpha^T @ wx (bf16, 3 terms)
#pragma unroll
            for (int ks = 0; ks < 4; ++ks) {
                uint32_t aah[4], aal[4], wbh[2][4], wbl[2][4];
                uint32_t ab = aoffA + (uint32_t)(ks * 32);
                ldsm_x4(aah, sb + SM_ALPHA + ab);
                ldsm_x4(aal, sb + SM_ALPHA + 9216 + ab);
#pragma unroll
                for (int nt2 = 0; nt2 < 2; ++nt2) {
                    int i = ks * 16 + aggI;
                    int f = aggF + nt2 * 16;
                    uint32_t off = (uint32_t)((i * 2 + (f >> 6)) * 128 + (((f & 63) * 2) ^ ((i & 7) << 4)));
                    ldsm_x4_t(wbh[nt2], sb + SM_WX + off);
                    ldsm_x4_t(wbl[nt2], sb + SM_WX + 16384 + off);
                }
#pragma unroll
                for (int q = 0; q < 4; ++q) {
                    const int nt2 = q >> 1, o = (q & 1) * 2;
                    mma16816(out_acc[hh][q], aah, &wbh[nt2][o]);
                    mma16816(out_acc[hh][q], aah, &wbl[nt2][o]);
                    mma16816(out_acc[hh][q], aal, &wbh[nt2][o]);
                }
            }
        }
    }

    // ---------------- epilogue: mean heads + bias ----------------
    const float inv8 = 0.125f;
    int j0 = mw2 * 16 + (l >> 2);
#pragma unroll
    for (int hh = 0; hh < 2; ++hh) {
#pragma unroll
        for (int q = 0; q < 4; ++q) {
            int f = hh * 128 + nw2 * 32 + q * 8 + (l & 3) * 2;
            float b0 = __ldg(gat_bias + f), b1 = __ldg(gat_bias + f + 1);
            float2 v0 = make_float2(out_acc[hh][q][0] * inv8 + b0, out_acc[hh][q][1] * inv8 + b1);
            float2 v1 = make_float2(out_acc[hh][q][2] * inv8 + b0, out_acc[hh][q][3] * inv8 + b1);
            *(float2*)(out + (((size_t)b * NC + j0) * NT + t) * ND + f) = v0;
            *(float2*)(out + (((size_t)b * NC + j0 + 8) * NT + t) * ND + f) = v1;
        }
    }
}

// ======================= launch =======================
extern "C" void kernel_launch(void* const* d_in, const int* in_sizes, int n_in,
                              void* d_out, int out_size) {
    const float* x          = (const float*)d_in[0];
    const float* static_adj = (const float*)d_in[1];
    const float* w_q        = (const float*)d_in[2];
    const float* w_k        = (const float*)d_in[3];
    const float* gat_lin    = (const float*)d_in[4];
    const float* att_src    = (const float*)d_in[5];
    const float* att_dst    = (const float*)d_in[6];
    const float* gat_bias   = (const float*)d_in[7];

    float* out = (float*)d_out;
    float* delta_out = out + (size_t)NB * NC * NT * ND;

    cudaFuncSetAttribute(k_main, cudaFuncAttributeMaxDynamicSharedMemorySize, SM_MAIN);

    k_vsd<<<16, 256>>>(gat_lin, att_src, att_dst);
    k_quantG<<<2048, 256>>>(gat_lin);
    k_hmean<<<NB * NC, 256>>>(x);
    k_qk<<<NB * NC / 8, 256>>>(w_q, w_k);
    k_simtopk<<<NB * 4, 256>>>(static_adj, delta_out);
    k_main<<<NB * NT, MTHREADS, SM_MAIN>>>(x, gat_bias, out);
}

// round 11
// speedup vs baseline: 5.1656x; 1.1307x over previous
#include <cuda_runtime.h>
#include <cuda_bf16.h>
#include <cuda_fp16.h>
#include <math.h>
#include <stdint.h>
#include <string.h>

#define NB 16
#define NC 64
#define NT 128
#define ND 256
#define NH 8
#define NKD 32
#define NTOPK 8

// ======================= helpers =======================
__device__ __forceinline__ uint32_t smem_to_u32(const void* p) {
    uint32_t a;
    asm("{ .reg .u64 t; cvta.to.shared.u64 t, %1; cvt.u32.u64 %0, t; }" : "=r"(a) : "l"(p));
    return a;
}
#define CP_ASYNC16(sa, gp) \
    asm volatile("cp.async.cg.shared.global [%0], [%1], 16;" :: "r"(sa), "l"(gp))
#define CP_COMMIT() asm volatile("cp.async.commit_group;")
#define CP_WAIT0()  asm volatile("cp.async.wait_group 0;")
#define CP_WAIT1()  asm volatile("cp.async.wait_group 1;")
#define CP_WAIT2()  asm volatile("cp.async.wait_group 2;")

__device__ __forceinline__ void ldsm_x4(uint32_t* r, uint32_t addr) {
    asm volatile("ldmatrix.sync.aligned.m8n8.x4.shared.b16 {%0,%1,%2,%3}, [%4];"
                 : "=r"(r[0]), "=r"(r[1]), "=r"(r[2]), "=r"(r[3]) : "r"(addr));
}
__device__ __forceinline__ void ldsm_x4_t(uint32_t* r, uint32_t addr) {
    asm volatile("ldmatrix.sync.aligned.m8n8.x4.trans.shared.b16 {%0,%1,%2,%3}, [%4];"
                 : "=r"(r[0]), "=r"(r[1]), "=r"(r[2]), "=r"(r[3]) : "r"(addr));
}
__device__ __forceinline__ void mma16816f16(float* d, const uint32_t* a, const uint32_t* b) {
    asm volatile(
        "mma.sync.aligned.m16n8k16.row.col.f32.f16.f16.f32 "
        "{%0,%1,%2,%3}, {%4,%5,%6,%7}, {%8,%9}, {%0,%1,%2,%3};"
        : "+f"(d[0]), "+f"(d[1]), "+f"(d[2]), "+f"(d[3])
        : "r"(a[0]), "r"(a[1]), "r"(a[2]), "r"(a[3]), "r"(b[0]), "r"(b[1]));
}
__device__ __forceinline__ void mma16832s8(int* d, const uint32_t* a, const uint32_t* b) {
    asm volatile(
        "mma.sync.aligned.m16n8k32.row.col.s32.s8.s8.s32 "
        "{%0,%1,%2,%3}, {%4,%5,%6,%7}, {%8,%9}, {%0,%1,%2,%3};"
        : "+r"(d[0]), "+r"(d[1]), "+r"(d[2]), "+r"(d[3])
        : "r"(a[0]), "r"(a[1]), "r"(a[2]), "r"(a[3]), "r"(b[0]), "r"(b[1]));
}
__device__ __forceinline__ uint16_t f16_bits(float v) {
    __half h = __float2half_rn(v);
    uint16_t b; memcpy(&b, &h, 2);
    return b;
}

// ======================= device scratch =======================
__device__ float g_hmean[NB * NC * ND];
__device__ float g_q[NB * NC * NKD];
__device__ float g_k[NB * NC * NKD];
__device__ unsigned long long g_maskcol[NB * NC];
__device__ float g_vsrc[NH * ND];
__device__ float g_vdst[NH * ND];
__device__ int8_t g_gh8[NH * ND * ND];   // G16 hi limbs [2048][256]
__device__ int8_t g_gl8[NH * ND * ND];   // G16 lo limbs

// ======================= kernel: G int16 quant + limb split =======================
__global__ void k_quantG(const float* __restrict__ g) {
    uint32_t i = blockIdx.x * 256 + threadIdx.x;
    float v = g[i] * 65536.f;
    int q = __float2int_rn(v);
    q = max(-32639, min(32639, q));
    int lo = ((q + 128) & 255) - 128;
    int hi = (q - lo) >> 8;
    g_gh8[i] = (int8_t)hi;
    g_gl8[i] = (int8_t)lo;
}

// ======================= kernel: temporal mean =======================
__global__ void k_hmean(const float* __restrict__ x) {
    int bc = blockIdx.x;
    int d = threadIdx.x;
    const float* p = x + (size_t)bc * NT * ND + d;
    float s = 0.f;
#pragma unroll 8
    for (int t = 0; t < NT; ++t) s += p[(size_t)t * ND];
    g_hmean[bc * ND + d] = s * (1.0f / NT);
}

// ======================= kernel: v_src/v_dst =======================
__global__ void k_vsd(const float* __restrict__ gat_lin,
                      const float* __restrict__ att_src,
                      const float* __restrict__ att_dst) {
    int h = blockIdx.x & 7;
    int isdst = blockIdx.x >> 3;
    int d = threadIdx.x;
    const float* att = isdst ? att_dst : att_src;
    float acc = 0.f;
#pragma unroll 4
    for (int f = 0; f < ND; ++f)
        acc += att[h * ND + f] * gat_lin[((size_t)(h * ND + f)) * ND + d];
    (isdst ? g_vdst : g_vsrc)[h * ND + d] = acc;
}

// ======================= kernel: q/k projections + self-loop init =======================
__global__ __launch_bounds__(256)
void k_qk(const float* __restrict__ w_q, const float* __restrict__ w_k) {
    __shared__ float hs[8 * ND];
    int blk = blockIdx.x;
    int tid = threadIdx.x;
    for (int it = tid; it < 8 * ND; it += 256) hs[it] = g_hmean[(size_t)blk * 8 * ND + it];
    if (tid < 8) g_maskcol[blk * 8 + tid] = 1ull << ((blk * 8 + tid) & 63);
    __syncthreads();
#pragma unroll
    for (int k = 0; k < 2; ++k) {
        int o = tid + k * 256;
        int bcL = o >> 6, rem = o & 63;
        int which = rem >> 5, kd = rem & 31;
        const float4* w4 = (const float4*)((which ? w_k : w_q) + (size_t)kd * ND);
        const float* hr = hs + bcL * ND;
        float acc = 0.f;
#pragma unroll 8
        for (int d4 = 0; d4 < 64; ++d4) {
            float4 wv = __ldg(w4 + d4);
            acc += hr[d4 * 4] * wv.x + hr[d4 * 4 + 1] * wv.y
                 + hr[d4 * 4 + 2] * wv.z + hr[d4 * 4 + 3] * wv.w;
        }
        (which ? g_k : g_q)[(blk * 8 + bcL) * NKD + kd] = acc;
    }
}

// ======================= kernel: sim + tanh + top-k (merged) =======================
__global__ __launch_bounds__(256)
void k_simtopk(const float* __restrict__ static_adj, float* __restrict__ delta_out) {
    __shared__ float qs[16 * NKD];
    __shared__ float ks_[NC * NKD];
    __shared__ float arow[16 * NC];
    int b = blockIdx.x >> 2;
    int i0 = (blockIdx.x & 3) * 16;
    int tid = threadIdx.x;
    for (int it = tid; it < NC * NKD; it += 256) ks_[it] = g_k[b * NC * NKD + it];
    for (int it = tid; it < 16 * NKD; it += 256) qs[it] = g_q[b * NC * NKD + i0 * NKD + it];
    __syncthreads();
    const float inv = 0.17677669529663687f;
    for (int task = tid; task < 16 * NC; task += 256) {
        int i = task >> 6, j = task & 63;
        float acc = 0.f;
#pragma unroll
        for (int kd = 0; kd < NKD; ++kd) acc += qs[i * NKD + kd] * ks_[j * NKD + kd];
        float delta = tanhf(acc * inv);
        int gi = i0 + i;
        delta_out[b * NC * NC + gi * NC + j] = delta;
        arow[task] = static_adj[gi * NC + j] + delta;
    }
    __syncthreads();
    int w = tid >> 5, lane = tid & 31;
#pragma unroll
    for (int rr = 0; rr < 2; ++rr) {
        int i = w * 2 + rr;
        int gi = i0 + i;
        float v0 = fabsf(arow[i * NC + lane]);
        float v1 = fabsf(arow[i * NC + lane + 32]);
        for (int s = 0; s < NTOPK; ++s) {
            float bv; int bj;
            if (v0 >= v1) { bv = v0; bj = lane; } else { bv = v1; bj = lane + 32; }
#pragma unroll
            for (int off = 16; off > 0; off >>= 1) {
                float ov = __shfl_xor_sync(0xffffffffu, bv, off);
                int   oj = __shfl_xor_sync(0xffffffffu, bj, off);
                if (ov > bv || (ov == bv && oj < bj)) { bv = ov; bj = oj; }
            }
            if (lane == 0) atomicOr(&g_maskcol[b * NC + bj], 1ull << gi);
            if (bj == lane)      v0 = -1.0f;
            if (bj == lane + 32) v1 = -1.0f;
        }
    }
}

// ======================= kernel: FUSED int8 gemm + softmax + f16 aggregation =======================
// CTA = (b,t). GEMM in s8 IMMA (limb split, 3 terms), agg in single-term f16 HMMA.
#define MTHREADS 512
#define SM_A 0                       // 32768: [limb2][kb2][64 r][128B] int8, swizzled
#define SM_B 32768                   // 98304: 3 stages x [limb2][128 r][128B] int8
#define SM_WX 131072                 // 16384: wx f16 (single)
#define SM_ALPHA 163840              // 9216 f16 alpha (vt overlay in prologue)
#define SM_ASAD 182272               // 4096
#define SM_MAIN (SM_ASAD + 4096)     // 186368
#define XSTG 98304                   // 64KB fp32 X staging (prologue only)

__global__ __launch_bounds__(MTHREADS, 1)
void k_main(const float* __restrict__ x,
            const float* __restrict__ gat_bias,
            float* __restrict__ out) {
    extern __shared__ char smem[];
    uint32_t sb = smem_to_u32(smem);
    const int tid = threadIdx.x;
    const int w = tid >> 5, l = tid & 31;
    const int bx = blockIdx.x;
    const int b = bx >> 7, t = bx & 127;

    const char* ghp = (const char*)g_gh8;
    const char* glp = (const char*)g_gl8;

    // ---------------- prologue ----------------
#pragma unroll
    for (int ii = 0; ii < 8; ++ii) {
        int it = tid + ii * MTHREADS;
        int c = it >> 6, q = it & 63;
        CP_ASYNC16(sb + XSTG + (uint32_t)(c * 1024 + q * 16),
                   x + (((size_t)(b * 64 + c) * 128) + t) * 256 + q * 4);
    }
    CP_COMMIT();
#pragma unroll
    for (int st = 0; st < 2; ++st) {
#pragma unroll
        for (int ii = 0; ii < 4; ++ii) {
            int it = tid + ii * MTHREADS;
            int s = it >> 10, r = (it >> 3) & 127, q = it & 7;
            CP_ASYNC16(sb + SM_B + (uint32_t)(st * 32768 + s * 16384 + r * 128 + ((q * 16) ^ ((r & 7) << 4))),
                       (s ? glp : ghp) + ((size_t)r * 256 + st * 128 + q * 16));
        }
        CP_COMMIT();
    }
    float* vt = (float*)(smem + SM_ALPHA);
    for (int it = tid; it < 2048; it += MTHREADS) {
        int h = it >> 8, d = it & 255;
        vt[d * 17 + h]     = g_vsrc[it];
        vt[d * 17 + 8 + h] = g_vdst[it];
    }
    CP_WAIT2();
    __syncthreads();

    const float* stgf = (const float*)(smem + XSTG);
    float* as_s = (float*)(smem + SM_ASAD);
    float* ad_s = (float*)(smem + SM_ASAD + 2048);
#pragma unroll
    for (int k = 0; k < 2; ++k) {
        int task = tid + k * MTHREADS;
        int c = task >> 4, hv = task & 15, h = hv & 7, sd = hv >> 3;
        const float* sr = stgf + c * 256;
        const float* vr = vt + hv;
        float acc = 0.f;
#pragma unroll 8
        for (int d = 0; d < 256; ++d) acc += sr[d] * vr[d * 17];
        (sd ? ad_s : as_s)[h * 64 + c] = acc;
    }
    // X quantization: fp32 -> int16 -> int8 limbs into A region
#pragma unroll
    for (int k = 0; k < 2; ++k) {
        int it = tid + k * MTHREADS;
        int c = it >> 4, kb = (it >> 3) & 1, gn = it & 7;
        const float* src = stgf + c * 256 + kb * 128 + gn * 16;
        uint32_t hw[4], lw[4];
#pragma unroll
        for (int p = 0; p < 4; ++p) {
            uint32_t hpack = 0, lpack = 0;
#pragma unroll
            for (int e = 0; e < 4; ++e) {
                int q = __float2int_rn(src[p * 4 + e] * 4096.f);
                q = max(-32639, min(32639, q));
                int lo = ((q + 128) & 255) - 128;
                int hi = (q - lo) >> 8;
                hpack |= ((uint32_t)(uint8_t)(int8_t)hi) << (8 * e);
                lpack |= ((uint32_t)(uint8_t)(int8_t)lo) << (8 * e);
            }
            hw[p] = hpack; lw[p] = lpack;
        }
        uint32_t off = (uint32_t)(c * 128 + ((gn * 16) ^ ((c & 7) << 4)));
        *(uint4*)(smem + SM_A + kb * 8192 + off)         = make_uint4(hw[0], hw[1], hw[2], hw[3]);
        *(uint4*)(smem + SM_A + 16384 + kb * 8192 + off) = make_uint4(lw[0], lw[1], lw[2], lw[3]);
    }

    // ---------------- frag geometry ----------------
    const int mw2 = w & 3, nw2 = w >> 2;
    const int arow_g = mw2 * 16 + (l & 15);
    const uint32_t aoff = (uint32_t)(arow_g * 128);
    const uint32_t akx = (uint32_t)((arow_g & 7) << 4);
    const uint32_t akoff = (uint32_t)((l >> 4) * 16);
    int boff[2]; uint32_t bkx[2];
#pragma unroll
    for (int p = 0; p < 2; ++p) {
        int r = nw2 * 32 + p * 16 + (l & 7) + (l >> 4) * 8;
        boff[p] = r * 128;
        bkx[p] = (uint32_t)((r & 7) << 4);
    }
    const uint32_t bkoff = (uint32_t)(((l >> 3) & 1) * 16);
    const uint32_t aoffA = (uint32_t)(((mw2 * 16 + (l & 15)) * 72 + (l >> 4) * 8) * 2);
    const int aggI = (l & 7) + ((l >> 3) & 1) * 8;
    const int aggF = nw2 * 32 + (l >> 4) * 8;

    uint16_t* alh = (uint16_t*)(smem + SM_ALPHA);   // [j=64][i stride 72] f16

    unsigned long long msk[4];
#pragma unroll
    for (int jj = 0; jj < 4; ++jj) msk[jj] = g_maskcol[b * NC + w * 4 + jj];

    int acc_hi[4][4], acc_mid[4][4];
#pragma unroll
    for (int g = 0; g < 4; ++g)
#pragma unroll
        for (int q = 0; q < 4; ++q) { acc_hi[g][q] = 0; acc_mid[g][q] = 0; }
    float out_acc[2][4][4];
#pragma unroll
    for (int hh = 0; hh < 2; ++hh)
#pragma unroll
        for (int g = 0; g < 4; ++g)
#pragma unroll
            for (int q = 0; q < 4; ++q) out_acc[hh][g][q] = 0.f;

    const float NEGINF = __int_as_float(0xff800000);
    const float COMB = 1.f / 268435456.f;   // 2^-28

    // ---------------- main loop: 32 steps (nt 16 x kb 2), 3-stage pipeline ----------------
    for (int step = 0; step < 32; ++step) {
        const int nt = step >> 1, kb = step & 1;
        CP_WAIT1();
        __syncthreads();

        {
            int is = step + 2;
            int nn, nk;
            if (is < 32) { nn = is >> 1; nk = is & 1; } else { nn = 15; nk = 1; }
            int bs = is % 3;
#pragma unroll
            for (int ii = 0; ii < 4; ++ii) {
                int it = tid + ii * MTHREADS;
                int s = it >> 10, r = (it >> 3) & 127, q = it & 7;
                CP_ASYNC16(sb + SM_B + (uint32_t)(bs * 32768 + s * 16384 + r * 128 + ((q * 16) ^ ((r & 7) << 4))),
                           (s ? glp : ghp) + ((size_t)(nn * 128 + r) * 256 + nk * 128 + q * 16));
            }
            CP_COMMIT();
        }

        // s8 IMMA on stage step%3
        const int bs0 = step % 3;
        const uint32_t pAh = sb + SM_A + (uint32_t)(kb * 8192);
        const uint32_t pAl = pAh + 16384;
        const uint32_t pBh = sb + SM_B + (uint32_t)(bs0 * 32768);
        const uint32_t pBl = pBh + 16384;
#pragma unroll
        for (int ks = 0; ks < 4; ++ks) {
            uint32_t ah[4], al[4], bh[2][4], bl[2][4];
            uint32_t akb = ((uint32_t)(ks * 32) + akoff) ^ akx;
            ldsm_x4(ah, pAh + aoff + akb);
            ldsm_x4(al, pAl + aoff + akb);
#pragma unroll
            for (int p = 0; p < 2; ++p) {
                uint32_t kbyte = ((uint32_t)(ks * 32) + bkoff) ^ bkx[p];
                ldsm_x4(bh[p], pBh + boff[p] + kbyte);
                ldsm_x4(bl[p], pBl + boff[p] + kbyte);
            }
#pragma unroll
            for (int g = 0; g < 4; ++g) {
                const int p = g >> 1, o = (g & 1) * 2;
                mma16832s8(acc_hi[g],  ah, &bh[p][o]);
                mma16832s8(acc_mid[g], ah, &bl[p][o]);
                mma16832s8(acc_mid[g], al, &bh[p][o]);
            }
        }

        if (kb == 1) {
            const int hh = nt & 1;
            // combine limb accumulators -> wx fp32 -> f16 smem tile (single)
            int r1 = mw2 * 16 + (l >> 2);
#pragma unroll
            for (int g = 0; g < 4; ++g) {
                float wf[4];
#pragma unroll
                for (int q = 0; q < 4; ++q) {
                    wf[q] = ((float)acc_hi[g][q] * 65536.f + (float)acc_mid[g][q] * 256.f) * COMB;
                    acc_hi[g][q] = 0; acc_mid[g][q] = 0;
                }
                int f = nw2 * 32 + g * 8 + (l & 3) * 2;
                int fh = f >> 6, fb = (f & 63) * 2;
#pragma unroll
                for (int half = 0; half < 2; ++half) {
                    int r = r1 + half * 8;
                    uint16_t h0 = f16_bits(wf[half * 2]);
                    uint16_t h1 = f16_bits(wf[half * 2 + 1]);
                    uint32_t off = (uint32_t)((r * 2 + fh) * 128 + (fb ^ ((r & 7) << 4)));
                    *(uint32_t*)(smem + SM_WX + off) = (uint32_t)h0 | ((uint32_t)h1 << 16);
                }
            }
            // softmax once per head -> f16 alpha^T [j][i]
            if (hh == 0) {
                int h = nt >> 1;
#pragma unroll
                for (int jj = 0; jj < 4; ++jj) {
                    int j = w * 4 + jj;
                    unsigned long long m = msk[jj];
                    float adj = ad_s[h * 64 + j];
                    int i0 = l, i1 = l + 32;
                    float e0 = as_s[h * 64 + i0] + adj;
                    float e1 = as_s[h * 64 + i1] + adj;
                    e0 = e0 > 0.f ? e0 : 0.2f * e0;
                    e1 = e1 > 0.f ? e1 : 0.2f * e1;
                    bool m0 = (m >> i0) & 1ull;
                    bool m1 = (m >> i1) & 1ull;
                    float mx = fmaxf(m0 ? e0 : NEGINF, m1 ? e1 : NEGINF);
#pragma unroll
                    for (int off = 16; off > 0; off >>= 1)
                        mx = fmaxf(mx, __shfl_xor_sync(0xffffffffu, mx, off));
                    float p0 = m0 ? expf(e0 - mx) : 0.f;
                    float p1 = m1 ? expf(e1 - mx) : 0.f;
                    float ssum = p0 + p1;
#pragma unroll
                    for (int off = 16; off > 0; off >>= 1)
                        ssum += __shfl_xor_sync(0xffffffffu, ssum, off);
                    float invs = 1.0f / ssum;
                    alh[j * 72 + i0] = f16_bits(p0 * invs);
                    alh[j * 72 + i1] = f16_bits(p1 * invs);
                }
            }
            __syncthreads();

            // agg HMMA f16 single-term: out_acc[hh] += alpha^T @ wx
#pragma unroll
            for (int ks = 0; ks < 4; ++ks) {
                uint32_t aah[4], wbh[2][4];
                ldsm_x4(aah, sb + SM_ALPHA + aoffA + (uint32_t)(ks * 32));
#pragma unroll
                for (int nt2 = 0; nt2 < 2; ++nt2) {
                    int i = ks * 16 + aggI;
                    int f = aggF + nt2 * 16;
                    uint32_t off = (uint32_t)((i * 2 + (f >> 6)) * 128 + (((f & 63) * 2) ^ ((i & 7) << 4)));
                    ldsm_x4_t(wbh[nt2], sb + SM_WX + off);
                }
#pragma unroll
                for (int q = 0; q < 4; ++q) {
                    const int nt2 = q >> 1, o = (q & 1) * 2;
                    mma16816f16(out_acc[hh][q], aah, &wbh[nt2][o]);
                }
            }
        }
    }

    // ---------------- epilogue: mean heads + bias ----------------
    const float inv8 = 0.125f;
    int j0 = mw2 * 16 + (l >> 2);
#pragma unroll
    for (int hh = 0; hh < 2; ++hh) {
#pragma unroll
        for (int q = 0; q < 4; ++q) {
            int f = hh * 128 + nw2 * 32 + q * 8 + (l & 3) * 2;
            float b0 = __ldg(gat_bias + f), b1 = __ldg(gat_bias + f + 1);
            float2 v0 = make_float2(out_acc[hh][q][0] * inv8 + b0, out_acc[hh][q][1] * inv8 + b1);
            float2 v1 = make_float2(out_acc[hh][q][2] * inv8 + b0, out_acc[hh][q][3] * inv8 + b1);
            *(float2*)(out + (((size_t)b * NC + j0) * NT + t) * ND + f) = v0;
            *(float2*)(out + (((size_t)b * NC + j0 + 8) * NT + t) * ND + f) = v1;
        }
    }
}

// ======================= launch =======================
extern "C" void kernel_launch(void* const* d_in, const int* in_sizes, int n_in,
                              void* d_out, int out_size) {
    const float* x          = (const float*)d_in[0];
    const float* static_adj = (const float*)d_in[1];
    const float* w_q        = (const float*)d_in[2];
    const float* w_k        = (const float*)d_in[3];
    const float* gat_lin    = (const float*)d_in[4];
    const float* att_src    = (const float*)d_in[5];
    const float* att_dst    = (const float*)d_in[6];
    const float* gat_bias   = (const float*)d_in[7];

    float* out = (float*)d_out;
    float* delta_out = out + (size_t)NB * NC * NT * ND;

    cudaFuncSetAttribute(k_main, cudaFuncAttributeMaxDynamicSharedMemorySize, SM_MAIN);

    k_vsd<<<16, 256>>>(gat_lin, att_src, att_dst);
    k_quantG<<<2048, 256>>>(gat_lin);
    k_hmean<<<NB * NC, 256>>>(x);
    k_qk<<<NB * NC / 8, 256>>>(w_q, w_k);
    k_simtopk<<<NB * 4, 256>>>(static_adj, delta_out);
    k_main<<<NB * NT, MTHREADS, SM_MAIN>>>(x, gat_bias, out);
}

// round 12
// speedup vs baseline: 5.2130x; 1.0092x over previous
#include <cuda_runtime.h>
#include <cuda_bf16.h>
#include <cuda_fp16.h>
#include <math.h>
#include <stdint.h>
#include <string.h>

#define NB 16
#define NC 64
#define NT 128
#define ND 256
#define NH 8
#define NKD 32
#define NTOPK 8

// ======================= helpers =======================
__device__ __forceinline__ uint32_t smem_to_u32(const void* p) {
    uint32_t a;
    asm("{ .reg .u64 t; cvta.to.shared.u64 t, %1; cvt.u32.u64 %0, t; }" : "=r"(a) : "l"(p));
    return a;
}
#define CP_ASYNC16(sa, gp) \
    asm volatile("cp.async.cg.shared.global [%0], [%1], 16;" :: "r"(sa), "l"(gp))
#define CP_COMMIT() asm volatile("cp.async.commit_group;")
#define CP_WAIT0()  asm volatile("cp.async.wait_group 0;")
#define CP_WAIT1()  asm volatile("cp.async.wait_group 1;")

__device__ __forceinline__ void ldsm_x4(uint32_t* r, uint32_t addr) {
    asm volatile("ldmatrix.sync.aligned.m8n8.x4.shared.b16 {%0,%1,%2,%3}, [%4];"
                 : "=r"(r[0]), "=r"(r[1]), "=r"(r[2]), "=r"(r[3]) : "r"(addr));
}
__device__ __forceinline__ void ldsm_x4_t(uint32_t* r, uint32_t addr) {
    asm volatile("ldmatrix.sync.aligned.m8n8.x4.trans.shared.b16 {%0,%1,%2,%3}, [%4];"
                 : "=r"(r[0]), "=r"(r[1]), "=r"(r[2]), "=r"(r[3]) : "r"(addr));
}
__device__ __forceinline__ void mma16816f16(float* d, const uint32_t* a, const uint32_t* b) {
    asm volatile(
        "mma.sync.aligned.m16n8k16.row.col.f32.f16.f16.f32 "
        "{%0,%1,%2,%3}, {%4,%5,%6,%7}, {%8,%9}, {%0,%1,%2,%3};"
        : "+f"(d[0]), "+f"(d[1]), "+f"(d[2]), "+f"(d[3])
        : "r"(a[0]), "r"(a[1]), "r"(a[2]), "r"(a[3]), "r"(b[0]), "r"(b[1]));
}
__device__ __forceinline__ void mma16832s8(int* d, const uint32_t* a, const uint32_t* b) {
    asm volatile(
        "mma.sync.aligned.m16n8k32.row.col.s32.s8.s8.s32 "
        "{%0,%1,%2,%3}, {%4,%5,%6,%7}, {%8,%9}, {%0,%1,%2,%3};"
        : "+r"(d[0]), "+r"(d[1]), "+r"(d[2]), "+r"(d[3])
        : "r"(a[0]), "r"(a[1]), "r"(a[2]), "r"(a[3]), "r"(b[0]), "r"(b[1]));
}
__device__ __forceinline__ uint16_t f16_bits(float v) {
    __half h = __float2half_rn(v);
    uint16_t b; memcpy(&b, &h, 2);
    return b;
}

// ======================= device scratch =======================
__device__ float g_hmean[NB * NC * ND];
__device__ float g_q[NB * NC * NKD];
__device__ float g_k[NB * NC * NKD];
__device__ unsigned long long g_maskcol[NB * NC];
__device__ float g_vsrc[NH * ND];
__device__ float g_vdst[NH * ND];
__device__ int8_t g_gh8[NH * ND * ND];   // G16 hi limbs [2048][256]
__device__ int8_t g_gl8[NH * ND * ND];   // G16 lo limbs
__device__ unsigned int g_tilectr;

// ======================= kernel: G int16 quant + limb split (+counter reset) =======================
__global__ void k_quantG(const float* __restrict__ g) {
    if (blockIdx.x == 0 && threadIdx.x == 0) g_tilectr = 0;
    uint32_t i = blockIdx.x * 256 + threadIdx.x;
    float v = g[i] * 65536.f;
    int q = __float2int_rn(v);
    q = max(-32639, min(32639, q));
    int lo = ((q + 128) & 255) - 128;
    int hi = (q - lo) >> 8;
    g_gh8[i] = (int8_t)hi;
    g_gl8[i] = (int8_t)lo;
}

// ======================= kernel: temporal mean =======================
__global__ void k_hmean(const float* __restrict__ x) {
    int bc = blockIdx.x;
    int d = threadIdx.x;
    const float* p = x + (size_t)bc * NT * ND + d;
    float s = 0.f;
#pragma unroll 8
    for (int t = 0; t < NT; ++t) s += p[(size_t)t * ND];
    g_hmean[bc * ND + d] = s * (1.0f / NT);
}

// ======================= kernel: v_src/v_dst =======================
__global__ void k_vsd(const float* __restrict__ gat_lin,
                      const float* __restrict__ att_src,
                      const float* __restrict__ att_dst) {
    int h = blockIdx.x & 7;
    int isdst = blockIdx.x >> 3;
    int d = threadIdx.x;
    const float* att = isdst ? att_dst : att_src;
    float acc = 0.f;
#pragma unroll 4
    for (int f = 0; f < ND; ++f)
        acc += att[h * ND + f] * gat_lin[((size_t)(h * ND + f)) * ND + d];
    (isdst ? g_vdst : g_vsrc)[h * ND + d] = acc;
}

// ======================= kernel: q/k projections + self-loop init =======================
__global__ __launch_bounds__(256)
void k_qk(const float* __restrict__ w_q, const float* __restrict__ w_k) {
    __shared__ float hs[8 * ND];
    int blk = blockIdx.x;
    int tid = threadIdx.x;
    for (int it = tid; it < 8 * ND; it += 256) hs[it] = g_hmean[(size_t)blk * 8 * ND + it];
    if (tid < 8) g_maskcol[blk * 8 + tid] = 1ull << ((blk * 8 + tid) & 63);
    __syncthreads();
#pragma unroll
    for (int k = 0; k < 2; ++k) {
        int o = tid + k * 256;
        int bcL = o >> 6, rem = o & 63;
        int which = rem >> 5, kd = rem & 31;
        const float4* w4 = (const float4*)((which ? w_k : w_q) + (size_t)kd * ND);
        const float* hr = hs + bcL * ND;
        float acc = 0.f;
#pragma unroll 8
        for (int d4 = 0; d4 < 64; ++d4) {
            float4 wv = __ldg(w4 + d4);
            acc += hr[d4 * 4] * wv.x + hr[d4 * 4 + 1] * wv.y
                 + hr[d4 * 4 + 2] * wv.z + hr[d4 * 4 + 3] * wv.w;
        }
        (which ? g_k : g_q)[(blk * 8 + bcL) * NKD + kd] = acc;
    }
}

// ======================= kernel: sim + tanh + top-k (merged) =======================
__global__ __launch_bounds__(256)
void k_simtopk(const float* __restrict__ static_adj, float* __restrict__ delta_out) {
    __shared__ float qs[16 * NKD];
    __shared__ float ks_[NC * NKD];
    __shared__ float arow[16 * NC];
    int b = blockIdx.x >> 2;
    int i0 = (blockIdx.x & 3) * 16;
    int tid = threadIdx.x;
    for (int it = tid; it < NC * NKD; it += 256) ks_[it] = g_k[b * NC * NKD + it];
    for (int it = tid; it < 16 * NKD; it += 256) qs[it] = g_q[b * NC * NKD + i0 * NKD + it];
    __syncthreads();
    const float inv = 0.17677669529663687f;
    for (int task = tid; task < 16 * NC; task += 256) {
        int i = task >> 6, j = task & 63;
        float acc = 0.f;
#pragma unroll
        for (int kd = 0; kd < NKD; ++kd) acc += qs[i * NKD + kd] * ks_[j * NKD + kd];
        float delta = tanhf(acc * inv);
        int gi = i0 + i;
        delta_out[b * NC * NC + gi * NC + j] = delta;
        arow[task] = static_adj[gi * NC + j] + delta;
    }
    __syncthreads();
    int w = tid >> 5, lane = tid & 31;
#pragma unroll
    for (int rr = 0; rr < 2; ++rr) {
        int i = w * 2 + rr;
        int gi = i0 + i;
        float v0 = fabsf(arow[i * NC + lane]);
        float v1 = fabsf(arow[i * NC + lane + 32]);
        for (int s = 0; s < NTOPK; ++s) {
            float bv; int bj;
            if (v0 >= v1) { bv = v0; bj = lane; } else { bv = v1; bj = lane + 32; }
#pragma unroll
            for (int off = 16; off > 0; off >>= 1) {
                float ov = __shfl_xor_sync(0xffffffffu, bv, off);
                int   oj = __shfl_xor_sync(0xffffffffu, bj, off);
                if (ov > bv || (ov == bv && oj < bj)) { bv = ov; bj = oj; }
            }
            if (lane == 0) atomicOr(&g_maskcol[b * NC + bj], 1ull << gi);
            if (bj == lane)      v0 = -1.0f;
            if (bj == lane + 32) v1 = -1.0f;
        }
    }
}

// ======================= PERSISTENT fused kernel =======================
// One CTA per SM; tiles (b,t) popped from global counter. B pipeline runs
// continuously; next tile's X prefetched during steps 0-7 of current tile.
#define MTHREADS 512
#define SM_A 0                        // 32768: A limbs [limb2][kb2][64r][128B]
#define SM_B 32768                    // 65536: 2 stages x [limb2][128r][128B]
#define SM_WX 98304                   // 16384: wx f16 tile
#define SM_ALPHA 114688               // 9216: f16 alpha [64][72]
#define SM_VT 123904                  // 17408: vt [256][17] fp32
#define SM_ASAD 141312                // 4096: as[8][64], ad[8][64]
#define SM_XSTG 145408                // 65536: fp32 X staging (prefetch)
#define SM_IDS 210944                 // 16: tile ids
#define SM_MAIN 210960
#define NTILES 2048

// process staged X: att dots -> asad, quantize -> A limbs
__device__ __forceinline__ void process_x(char* smem, int tid) {
    const float* stgf = (const float*)(smem + SM_XSTG);
    const float* vt = (const float*)(smem + SM_VT);
    float* as_s = (float*)(smem + SM_ASAD);
    float* ad_s = as_s + 512;
#pragma unroll
    for (int k = 0; k < 2; ++k) {
        int task = tid + k * MTHREADS;
        int c = task >> 4, hv = task & 15, h = hv & 7, sd = hv >> 3;
        const float* sr = stgf + c * 256;
        const float* vr = vt + hv;
        float acc = 0.f;
#pragma unroll 8
        for (int d = 0; d < 256; ++d) acc += sr[d] * vr[d * 17];
        (sd ? ad_s : as_s)[h * 64 + c] = acc;
    }
#pragma unroll
    for (int k = 0; k < 2; ++k) {
        int it = tid + k * MTHREADS;
        int c = it >> 4, kb = (it >> 3) & 1, gn = it & 7;
        const float* src = stgf + c * 256 + kb * 128 + gn * 16;
        uint32_t hw[4], lw[4];
#pragma unroll
        for (int p = 0; p < 4; ++p) {
            uint32_t hpack = 0, lpack = 0;
#pragma unroll
            for (int e = 0; e < 4; ++e) {
                int q = __float2int_rn(src[p * 4 + e] * 4096.f);
                q = max(-32639, min(32639, q));
                int lo = ((q + 128) & 255) - 128;
                int hi = (q - lo) >> 8;
                hpack |= ((uint32_t)(uint8_t)(int8_t)hi) << (8 * e);
                lpack |= ((uint32_t)(uint8_t)(int8_t)lo) << (8 * e);
            }
            hw[p] = hpack; lw[p] = lpack;
        }
        uint32_t off = (uint32_t)(c * 128 + ((gn * 16) ^ ((c & 7) << 4)));
        *(uint4*)(smem + SM_A + kb * 8192 + off)         = make_uint4(hw[0], hw[1], hw[2], hw[3]);
        *(uint4*)(smem + SM_A + 16384 + kb * 8192 + off) = make_uint4(lw[0], lw[1], lw[2], lw[3]);
    }
}

__global__ __launch_bounds__(MTHREADS, 1)
void k_main(const float* __restrict__ x,
            const float* __restrict__ gat_bias,
            float* __restrict__ out) {
    extern __shared__ char smem[];
    uint32_t sb = smem_to_u32(smem);
    const int tid = threadIdx.x;
    const int w = tid >> 5, l = tid & 31;
    unsigned int* ids = (unsigned int*)(smem + SM_IDS);

    const char* ghp = (const char*)g_gh8;
    const char* glp = (const char*)g_gl8;

    // ---------------- prologue ----------------
    if (tid == 0) ids[0] = atomicAdd(&g_tilectr, 1u);
    __syncthreads();
    unsigned int id = ids[0];
    if (id >= NTILES) return;
    int b = id >> 7, t = id & 127;

    // X(id) -> XSTG (group)
#pragma unroll
    for (int ii = 0; ii < 8; ++ii) {
        int it = tid + ii * MTHREADS;
        int c = it >> 6, q = it & 63;
        CP_ASYNC16(sb + SM_XSTG + (uint32_t)(c * 1024 + q * 16),
                   x + (((size_t)(b * 64 + c) * 128) + t) * 256 + q * 4);
    }
    CP_COMMIT();
    // B G(0) -> stage 0 (group)
#pragma unroll
    for (int ii = 0; ii < 4; ++ii) {
        int it = tid + ii * MTHREADS;
        int s8 = it >> 10, r = (it >> 3) & 127, q = it & 7;
        CP_ASYNC16(sb + SM_B + (uint32_t)(s8 * 16384 + r * 128 + ((q * 16) ^ ((r & 7) << 4))),
                   (s8 ? glp : ghp) + ((size_t)r * 256 + q * 16));
    }
    CP_COMMIT();
    // vt (tile-invariant)
    {
        float* vt = (float*)(smem + SM_VT);
        for (int it = tid; it < 2048; it += MTHREADS) {
            int h = it >> 8, d = it & 255;
            vt[d * 17 + h]     = g_vsrc[it];
            vt[d * 17 + 8 + h] = g_vdst[it];
        }
    }
    CP_WAIT1();          // X landed (G0 may pend)
    __syncthreads();
    process_x(smem, tid);
    if (tid == 0) ids[1] = atomicAdd(&g_tilectr, 1u);
    // published by step-0 sync

    // ---------------- frag geometry ----------------
    const int mw2 = w & 3, nw2 = w >> 2;
    const int arow_g = mw2 * 16 + (l & 15);
    const uint32_t aoff = (uint32_t)(arow_g * 128);
    const uint32_t akx = (uint32_t)((arow_g & 7) << 4);
    const uint32_t akoff = (uint32_t)((l >> 4) * 16);
    int boff[2]; uint32_t bkx[2];
#pragma unroll
    for (int p = 0; p < 2; ++p) {
        int r = nw2 * 32 + p * 16 + (l & 7) + (l >> 4) * 8;
        boff[p] = r * 128;
        bkx[p] = (uint32_t)((r & 7) << 4);
    }
    const uint32_t bkoff = (uint32_t)(((l >> 3) & 1) * 16);
    const uint32_t aoffA = (uint32_t)(((mw2 * 16 + (l & 15)) * 72 + (l >> 4) * 8) * 2);
    const int aggI = (l & 7) + ((l >> 3) & 1) * 8;
    const int aggF = nw2 * 32 + (l >> 4) * 8;

    uint16_t* alh = (uint16_t*)(smem + SM_ALPHA);
    float* as_s = (float*)(smem + SM_ASAD);
    float* ad_s = as_s + 512;

    unsigned long long msk[4];
#pragma unroll
    for (int jj = 0; jj < 4; ++jj) msk[jj] = g_maskcol[b * NC + w * 4 + jj];

    int acc_hi[4][4], acc_mid[4][4];
#pragma unroll
    for (int g = 0; g < 4; ++g)
#pragma unroll
        for (int q = 0; q < 4; ++q) { acc_hi[g][q] = 0; acc_mid[g][q] = 0; }
    float out_acc[2][4][4];
#pragma unroll
    for (int hh = 0; hh < 2; ++hh)
#pragma unroll
        for (int g = 0; g < 4; ++g)
#pragma unroll
            for (int q = 0; q < 4; ++q) out_acc[hh][g][q] = 0.f;

    const float NEGINF = __int_as_float(0xff800000);
    const float COMB = 1.f / 268435456.f;   // 2^-28
    int buf = 0;
    unsigned int nextid = NTILES;

    // ---------------- persistent tile loop ----------------
    for (;;) {
        for (int s = 0; s < 32; ++s) {
            const int nt = s >> 1, kb = s & 1;
            __syncthreads();
            if (s == 0) nextid = ids[1];

            // issue G(s+1) into buf^1 (+X prefetch piece for s<8)
            {
                int ss2 = (s + 1) & 31;
                int nn = ss2 >> 1, nk = ss2 & 1;
                int b2 = buf ^ 1;
#pragma unroll
                for (int ii = 0; ii < 4; ++ii) {
                    int it = tid + ii * MTHREADS;
                    int s8 = it >> 10, r = (it >> 3) & 127, q = it & 7;
                    CP_ASYNC16(sb + SM_B + (uint32_t)(b2 * 32768 + s8 * 16384 + r * 128 + ((q * 16) ^ ((r & 7) << 4))),
                               (s8 ? glp : ghp) + ((size_t)(nn * 128 + r) * 256 + nk * 128 + q * 16));
                }
                if (s < 8 && nextid < NTILES) {
                    int it = tid + s * MTHREADS;
                    int c = it >> 6, q = it & 63;
                    int nb = nextid >> 7, ntt = nextid & 127;
                    CP_ASYNC16(sb + SM_XSTG + (uint32_t)(c * 1024 + q * 16),
                               x + (((size_t)(nb * 64 + c) * 128) + ntt) * 256 + q * 4);
                }
                CP_COMMIT();
            }
            CP_WAIT1();   // G(s) landed

            // s8 IMMA on buf
            const uint32_t pAh = sb + SM_A + (uint32_t)(kb * 8192);
            const uint32_t pAl = pAh + 16384;
            const uint32_t pBh = sb + SM_B + (uint32_t)(buf * 32768);
            const uint32_t pBl = pBh + 16384;
#pragma unroll
            for (int ks = 0; ks < 4; ++ks) {
                uint32_t ah[4], al[4], bh[2][4], bl[2][4];
                uint32_t akb = ((uint32_t)(ks * 32) + akoff) ^ akx;
                ldsm_x4(ah, pAh + aoff + akb);
                ldsm_x4(al, pAl + aoff + akb);
#pragma unroll
                for (int p = 0; p < 2; ++p) {
                    uint32_t kbyte = ((uint32_t)(ks * 32) + bkoff) ^ bkx[p];
                    ldsm_x4(bh[p], pBh + boff[p] + kbyte);
                    ldsm_x4(bl[p], pBl + boff[p] + kbyte);
                }
#pragma unroll
                for (int g = 0; g < 4; ++g) {
                    const int p = g >> 1, o = (g & 1) * 2;
                    mma16832s8(acc_hi[g],  ah, &bh[p][o]);
                    mma16832s8(acc_mid[g], ah, &bl[p][o]);
                    mma16832s8(acc_mid[g], al, &bh[p][o]);
                }
            }

            if (kb == 1) {
                const int hh = nt & 1;
                int r1 = mw2 * 16 + (l >> 2);
#pragma unroll
                for (int g = 0; g < 4; ++g) {
                    float wf[4];
#pragma unroll
                    for (int q = 0; q < 4; ++q) {
                        wf[q] = ((float)acc_hi[g][q] * 65536.f + (float)acc_mid[g][q] * 256.f) * COMB;
                        acc_hi[g][q] = 0; acc_mid[g][q] = 0;
                    }
                    int f = nw2 * 32 + g * 8 + (l & 3) * 2;
                    int fh = f >> 6, fb = (f & 63) * 2;
#pragma unroll
                    for (int half = 0; half < 2; ++half) {
                        int r = r1 + half * 8;
                        uint16_t h0 = f16_bits(wf[half * 2]);
                        uint16_t h1 = f16_bits(wf[half * 2 + 1]);
                        uint32_t off = (uint32_t)((r * 2 + fh) * 128 + (fb ^ ((r & 7) << 4)));
                        *(uint32_t*)(smem + SM_WX + off) = (uint32_t)h0 | ((uint32_t)h1 << 16);
                    }
                }
                if (hh == 0) {
                    int h = nt >> 1;
#pragma unroll
                    for (int jj = 0; jj < 4; ++jj) {
                        int j = w * 4 + jj;
                        unsigned long long m = msk[jj];
                        float adj = ad_s[h * 64 + j];
                        int i0 = l, i1 = l + 32;
                        float e0 = as_s[h * 64 + i0] + adj;
                        float e1 = as_s[h * 64 + i1] + adj;
                        e0 = e0 > 0.f ? e0 : 0.2f * e0;
                        e1 = e1 > 0.f ? e1 : 0.2f * e1;
                        bool m0 = (m >> i0) & 1ull;
                        bool m1 = (m >> i1) & 1ull;
                        float mx = fmaxf(m0 ? e0 : NEGINF, m1 ? e1 : NEGINF);
#pragma unroll
                        for (int off = 16; off > 0; off >>= 1)
                            mx = fmaxf(mx, __shfl_xor_sync(0xffffffffu, mx, off));
                        float p0 = m0 ? expf(e0 - mx) : 0.f;
                        float p1 = m1 ? expf(e1 - mx) : 0.f;
                        float ssum = p0 + p1;
#pragma unroll
                        for (int off = 16; off > 0; off >>= 1)
                            ssum += __shfl_xor_sync(0xffffffffu, ssum, off);
                        float invs = 1.0f / ssum;
                        alh[j * 72 + i0] = f16_bits(p0 * invs);
                        alh[j * 72 + i1] = f16_bits(p1 * invs);
                    }
                }
                __syncthreads();

#pragma unroll
                for (int ks = 0; ks < 4; ++ks) {
                    uint32_t aah[4], wbh[2][4];
                    ldsm_x4(aah, sb + SM_ALPHA + aoffA + (uint32_t)(ks * 32));
#pragma unroll
                    for (int n2 = 0; n2 < 2; ++n2) {
                        int i = ks * 16 + aggI;
                        int f = aggF + n2 * 16;
                        uint32_t off = (uint32_t)((i * 2 + (f >> 6)) * 128 + (((f & 63) * 2) ^ ((i & 7) << 4)));
                        ldsm_x4_t(wbh[n2], sb + SM_WX + off);
                    }
#pragma unroll
                    for (int q = 0; q < 4; ++q) {
                        const int n2 = q >> 1, o = (q & 1) * 2;
                        mma16816f16(out_acc[hh][q], aah, &wbh[n2][o]);
                    }
                }
            }
            buf ^= 1;
        }

        // ---------------- tile boundary ----------------
        __syncthreads();
        // epilogue for tile (b,t)
        {
            const float inv8 = 0.125f;
            int j0 = mw2 * 16 + (l >> 2);
#pragma unroll
            for (int hh = 0; hh < 2; ++hh) {
#pragma unroll
                for (int q = 0; q < 4; ++q) {
                    int f = hh * 128 + nw2 * 32 + q * 8 + (l & 3) * 2;
                    float b0 = __ldg(gat_bias + f), b1 = __ldg(gat_bias + f + 1);
                    float2 v0 = make_float2(out_acc[hh][q][0] * inv8 + b0, out_acc[hh][q][1] * inv8 + b1);
                    float2 v1 = make_float2(out_acc[hh][q][2] * inv8 + b0, out_acc[hh][q][3] * inv8 + b1);
                    *(float2*)(out + (((size_t)b * NC + j0) * NT + t) * ND + f) = v0;
                    *(float2*)(out + (((size_t)b * NC + j0 + 8) * NT + t) * ND + f) = v1;
                    out_acc[hh][q][0] = out_acc[hh][q][1] = out_acc[hh][q][2] = out_acc[hh][q][3] = 0.f;
                }
            }
        }
        unsigned int nid = nextid;
        __syncthreads();   // all threads read ids[1] (as nextid) before overwrite
        if (nid >= NTILES) { CP_WAIT0(); break; }
        id = nid; b = id >> 7; t = id & 127;
        if (tid == 0) ids[1] = atomicAdd(&g_tilectr, 1u);
        process_x(smem, tid);
#pragma unroll
        for (int jj = 0; jj < 4; ++jj) msk[jj] = g_maskcol[b * NC + w * 4 + jj];
        // step-0 sync publishes A/asad/ids[1]
    }
}

// ======================= launch =======================
extern "C" void kernel_launch(void* const* d_in, const int* in_sizes, int n_in,
                              void* d_out, int out_size) {
    const float* x          = (const float*)d_in[0];
    const float* static_adj = (const float*)d_in[1];
    const float* w_q        = (const float*)d_in[2];
    const float* w_k        = (const float*)d_in[3];
    const float* gat_lin    = (const float*)d_in[4];
    const float* att_src    = (const float*)d_in[5];
    const float* att_dst    = (const float*)d_in[6];
    const float* gat_bias   = (const float*)d_in[7];

    float* out = (float*)d_out;
    float* delta_out = out + (size_t)NB * NC * NT * ND;

    int nsm = 148;
    cudaDeviceGetAttribute(&nsm, cudaDevAttrMultiProcessorCount, 0);
    if (nsm <= 0) nsm = 148;
    if (nsm > NTILES) nsm = NTILES;

    cudaFuncSetAttribute(k_main, cudaFuncAttributeMaxDynamicSharedMemorySize, SM_MAIN);

    k_vsd<<<16, 256>>>(gat_lin, att_src, att_dst);
    k_quantG<<<2048, 256>>>(gat_lin);
    k_hmean<<<NB * NC, 256>>>(x);
    k_qk<<<NB * NC / 8, 256>>>(w_q, w_k);
    k_simtopk<<<NB * 4, 256>>>(static_adj, delta_out);
    k_main<<<nsm, MTHREADS, SM_MAIN>>>(x, gat_bias, out);
}

// round 14
// speedup vs baseline: 5.5916x; 1.0726x over previous
#include <cuda_runtime.h>
#include <cuda_bf16.h>
#include <cuda_fp16.h>
#include <math.h>
#include <stdint.h>
#include <string.h>

#define NB 16
#define NC 64
#define NT 128
#define ND 256
#define NH 8
#define NKD 32
#define NTOPK 8

// ======================= helpers =======================
__device__ __forceinline__ uint32_t smem_to_u32(const void* p) {
    uint32_t a;
    asm("{ .reg .u64 t; cvta.to.shared.u64 t, %1; cvt.u32.u64 %0, t; }" : "=r"(a) : "l"(p));
    return a;
}
#define CP_ASYNC16(sa, gp) \
    asm volatile("cp.async.cg.shared.global [%0], [%1], 16;" :: "r"(sa), "l"(gp))
#define CP_COMMIT() asm volatile("cp.async.commit_group;")
#define CP_WAIT0()  asm volatile("cp.async.wait_group 0;")
#define CP_WAIT1()  asm volatile("cp.async.wait_group 1;")

__device__ __forceinline__ void ldsm_x4(uint32_t* r, uint32_t addr) {
    asm volatile("ldmatrix.sync.aligned.m8n8.x4.shared.b16 {%0,%1,%2,%3}, [%4];"
                 : "=r"(r[0]), "=r"(r[1]), "=r"(r[2]), "=r"(r[3]) : "r"(addr));
}
__device__ __forceinline__ void ldsm_x4_t(uint32_t* r, uint32_t addr) {
    asm volatile("ldmatrix.sync.aligned.m8n8.x4.trans.shared.b16 {%0,%1,%2,%3}, [%4];"
                 : "=r"(r[0]), "=r"(r[1]), "=r"(r[2]), "=r"(r[3]) : "r"(addr));
}
__device__ __forceinline__ void mma16816f16(float* d, const uint32_t* a, const uint32_t* b) {
    asm volatile(
        "mma.sync.aligned.m16n8k16.row.col.f32.f16.f16.f32 "
        "{%0,%1,%2,%3}, {%4,%5,%6,%7}, {%8,%9}, {%0,%1,%2,%3};"
        : "+f"(d[0]), "+f"(d[1]), "+f"(d[2]), "+f"(d[3])
        : "r"(a[0]), "r"(a[1]), "r"(a[2]), "r"(a[3]), "r"(b[0]), "r"(b[1]));
}
__device__ __forceinline__ uint16_t f16_bits(float v) {
    __half h = __float2half_rn(v);
    uint16_t b; memcpy(&b, &h, 2);
    return b;
}

// ======================= device scratch =======================
__device__ float g_hmean[NB * NC * ND];
__device__ float g_q[NB * NC * NKD];
__device__ float g_k[NB * NC * NKD];
__device__ unsigned long long g_maskcol[NB * NC];
__device__ float g_vsrc[NH * ND];
__device__ float g_vdst[NH * ND];
__device__ uint16_t g_gf16[NH * ND * ND];   // G as f16 [2048 rows][256 k]
__device__ unsigned int g_tilectr;

// ======================= kernel: G -> f16 (+counter reset) =======================
__global__ void k_prepG(const float* __restrict__ g) {
    if (blockIdx.x == 0 && threadIdx.x == 0) g_tilectr = 0;
    uint32_t i = blockIdx.x * 256 + threadIdx.x;
    g_gf16[i] = f16_bits(g[i]);
}

// ======================= kernel: temporal mean =======================
__global__ void k_hmean(const float* __restrict__ x) {
    int bc = blockIdx.x;
    int d = threadIdx.x;
    const float* p = x + (size_t)bc * NT * ND + d;
    float s = 0.f;
#pragma unroll 8
    for (int t = 0; t < NT; ++t) s += p[(size_t)t * ND];
    g_hmean[bc * ND + d] = s * (1.0f / NT);
}

// ======================= kernel: v_src/v_dst =======================
__global__ void k_vsd(const float* __restrict__ gat_lin,
                      const float* __restrict__ att_src,
                      const float* __restrict__ att_dst) {
    int h = blockIdx.x & 7;
    int isdst = blockIdx.x >> 3;
    int d = threadIdx.x;
    const float* att = isdst ? att_dst : att_src;
    float acc = 0.f;
#pragma unroll 4
    for (int f = 0; f < ND; ++f)
        acc += att[h * ND + f] * gat_lin[((size_t)(h * ND + f)) * ND + d];
    (isdst ? g_vdst : g_vsrc)[h * ND + d] = acc;
}

// ======================= kernel: q/k projections + self-loop init =======================
__global__ __launch_bounds__(256)
void k_qk(const float* __restrict__ w_q, const float* __restrict__ w_k) {
    __shared__ float hs[8 * ND];
    int blk = blockIdx.x;
    int tid = threadIdx.x;
    for (int it = tid; it < 8 * ND; it += 256) hs[it] = g_hmean[(size_t)blk * 8 * ND + it];
    if (tid < 8) g_maskcol[blk * 8 + tid] = 1ull << ((blk * 8 + tid) & 63);
    __syncthreads();
#pragma unroll
    for (int k = 0; k < 2; ++k) {
        int o = tid + k * 256;
        int bcL = o >> 6, rem = o & 63;
        int which = rem >> 5, kd = rem & 31;
        const float4* w4 = (const float4*)((which ? w_k : w_q) + (size_t)kd * ND);
        const float* hr = hs + bcL * ND;
        float acc = 0.f;
#pragma unroll 8
        for (int d4 = 0; d4 < 64; ++d4) {
            float4 wv = __ldg(w4 + d4);
            acc += hr[d4 * 4] * wv.x + hr[d4 * 4 + 1] * wv.y
                 + hr[d4 * 4 + 2] * wv.z + hr[d4 * 4 + 3] * wv.w;
        }
        (which ? g_k : g_q)[(blk * 8 + bcL) * NKD + kd] = acc;
    }
}

// ======================= kernel: sim + tanh + top-k (merged) =======================
__global__ __launch_bounds__(256)
void k_simtopk(const float* __restrict__ static_adj, float* __restrict__ delta_out) {
    __shared__ float qs[16 * NKD];
    __shared__ float ks_[NC * NKD];
    __shared__ float arow[16 * NC];
    int b = blockIdx.x >> 2;
    int i0 = (blockIdx.x & 3) * 16;
    int tid = threadIdx.x;
    for (int it = tid; it < NC * NKD; it += 256) ks_[it] = g_k[b * NC * NKD + it];
    for (int it = tid; it < 16 * NKD; it += 256) qs[it] = g_q[b * NC * NKD + i0 * NKD + it];
    __syncthreads();
    const float inv = 0.17677669529663687f;
    for (int task = tid; task < 16 * NC; task += 256) {
        int i = task >> 6, j = task & 63;
        float acc = 0.f;
#pragma unroll
        for (int kd = 0; kd < NKD; ++kd) acc += qs[i * NKD + kd] * ks_[j * NKD + kd];
        float delta = tanhf(acc * inv);
        int gi = i0 + i;
        delta_out[b * NC * NC + gi * NC + j] = delta;
        arow[task] = static_adj[gi * NC + j] + delta;
    }
    __syncthreads();
    int w = tid >> 5, lane = tid & 31;
#pragma unroll
    for (int rr = 0; rr < 2; ++rr) {
        int i = w * 2 + rr;
        int gi = i0 + i;
        float v0 = fabsf(arow[i * NC + lane]);
        float v1 = fabsf(arow[i * NC + lane + 32]);
        for (int s = 0; s < NTOPK; ++s) {
            float bv; int bj;
            if (v0 >= v1) { bv = v0; bj = lane; } else { bv = v1; bj = lane + 32; }
#pragma unroll
            for (int off = 16; off > 0; off >>= 1) {
                float ov = __shfl_xor_sync(0xffffffffu, bv, off);
                int   oj = __shfl_xor_sync(0xffffffffu, bj, off);
                if (ov > bv || (ov == bv && oj < bj)) { bv = ov; bj = oj; }
            }
            if (lane == 0) atomicOr(&g_maskcol[b * NC + bj], 1ull << gi);
            if (bj == lane)      v0 = -1.0f;
            if (bj == lane + 32) v1 = -1.0f;
        }
    }
}

// ======================= PERSISTENT fused kernel (f16 GEMM on R12 skeleton) =======================
// SMEM map identical to R12. B "limb" slots become k-half slots (same sizes/cadence).
#define MTHREADS 512
#define SM_A 0                        // 32768: A f16 [kh2][kb2][64r][128B] (chunk idx kb2*2+kh)
#define SM_B 32768                    // 65536: 2 stages x [kh2][128r][128B]
#define SM_WX 98304                   // 16384: wx f16 tile
#define SM_ALPHA 114688               // 9216: f16 alpha [64][72]
#define SM_VT 123904                  // 17408: vt [256][17] fp32
#define SM_ASAD 141312                // 4096: as[8][64], ad[8][64]
#define SM_XSTG 145408                // 65536: fp32 X staging (prefetch)
#define SM_IDS 210944                 // 16
#define SM_MAIN 210960
#define NTILES 2048

// process staged X: att dots -> asad, f16 convert -> A
__device__ __forceinline__ void process_x(char* smem, int tid) {
    const float* stgf = (const float*)(smem + SM_XSTG);
    const float* vt = (const float*)(smem + SM_VT);
    float* as_s = (float*)(smem + SM_ASAD);
    float* ad_s = as_s + 512;
#pragma unroll
    for (int k = 0; k < 2; ++k) {
        int task = tid + k * MTHREADS;
        int c = task >> 4, hv = task & 15, h = hv & 7, sd = hv >> 3;
        const float* sr = stgf + c * 256;
        const float* vr = vt + hv;
        float acc = 0.f;
#pragma unroll 8
        for (int d = 0; d < 256; ++d) acc += sr[d] * vr[d * 17];
        (sd ? ad_s : as_s)[h * 64 + c] = acc;
    }
    // f16 convert: 2048 granules of 8 floats -> 16B, chunk c64 = k/64
#pragma unroll
    for (int k = 0; k < 4; ++k) {
        int it = tid + k * MTHREADS;           // 0..2047
        int c = it >> 5, c64 = (it >> 3) & 3, gn = it & 7;
        const float* src = stgf + c * 256 + c64 * 64 + gn * 8;
        uint32_t wv[4];
#pragma unroll
        for (int p = 0; p < 4; ++p)
            wv[p] = (uint32_t)f16_bits(src[2 * p]) | ((uint32_t)f16_bits(src[2 * p + 1]) << 16);
        uint32_t off = (uint32_t)(c * 128 + ((gn * 16) ^ ((c & 7) << 4)));
        *(uint4*)(smem + SM_A + c64 * 8192 + off) = make_uint4(wv[0], wv[1], wv[2], wv[3]);
    }
}

__global__ __launch_bounds__(MTHREADS, 1)
void k_main(const float* __restrict__ x,
            const float* __restrict__ gat_bias,
            float* __restrict__ out) {
    extern __shared__ char smem[];
    uint32_t sb = smem_to_u32(smem);
    const int tid = threadIdx.x;
    const int w = tid >> 5, l = tid & 31;
    unsigned int* ids = (unsigned int*)(smem + SM_IDS);

    const char* gp = (const char*)g_gf16;   // [2048 n][512 B]

    // ---------------- prologue (R12 structure) ----------------
    if (tid == 0) ids[0] = atomicAdd(&g_tilectr, 1u);
    __syncthreads();
    unsigned int id = ids[0];
    if (id >= NTILES) return;
    int b = id >> 7, t = id & 127;

    // X(id) -> XSTG (group 0)
#pragma unroll
    for (int ii = 0; ii < 8; ++ii) {
        int it = tid + ii * MTHREADS;
        int c = it >> 6, q = it & 63;
        CP_ASYNC16(sb + SM_XSTG + (uint32_t)(c * 1024 + q * 16),
                   x + (((size_t)(b * 64 + c) * 128) + t) * 256 + q * 4);
    }
    CP_COMMIT();
    // B step 0 (nt=0, kb2=0): both k-halves -> stage 0 (group 1)
#pragma unroll
    for (int ii = 0; ii < 4; ++ii) {
        int it = tid + ii * MTHREADS;
        int kh = it >> 10, r = (it >> 3) & 127, q = it & 7;
        CP_ASYNC16(sb + SM_B + (uint32_t)(kh * 16384 + r * 128 + ((q * 16) ^ ((r & 7) << 4))),
                   gp + ((size_t)r * 512 + kh * 128 + q * 16));
    }
    CP_COMMIT();
    // vt (tile-invariant)
    {
        float* vt = (float*)(smem + SM_VT);
        for (int it = tid; it < 2048; it += MTHREADS) {
            int h = it >> 8, d = it & 255;
            vt[d * 17 + h]     = g_vsrc[it];
            vt[d * 17 + 8 + h] = g_vdst[it];
        }
    }
    CP_WAIT1();          // X landed
    __syncthreads();
    process_x(smem, tid);
    if (tid == 0) ids[1] = atomicAdd(&g_tilectr, 1u);

    // ---------------- frag geometry (R12 verbatim) ----------------
    const int mw2 = w & 3, nw2 = w >> 2;
    const int arow_g = mw2 * 16 + (l & 15);
    const uint32_t aoff = (uint32_t)(arow_g * 128);
    const uint32_t akx = (uint32_t)((arow_g & 7) << 4);
    const uint32_t akoff = (uint32_t)((l >> 4) * 16);
    int boff[2]; uint32_t bkx[2];
#pragma unroll
    for (int p = 0; p < 2; ++p) {
        int r = nw2 * 32 + p * 16 + (l & 7) + (l >> 4) * 8;
        boff[p] = r * 128;
        bkx[p] = (uint32_t)((r & 7) << 4);
    }
    const uint32_t bkoff = (uint32_t)(((l >> 3) & 1) * 16);
    const uint32_t aoffA = (uint32_t)(((mw2 * 16 + (l & 15)) * 72 + (l >> 4) * 8) * 2);
    const int aggI = (l & 7) + ((l >> 3) & 1) * 8;
    const int aggF = nw2 * 32 + (l >> 4) * 8;

    uint16_t* alh = (uint16_t*)(smem + SM_ALPHA);
    float* as_s = (float*)(smem + SM_ASAD);
    float* ad_s = as_s + 512;

    unsigned long long msk[4];
#pragma unroll
    for (int jj = 0; jj < 4; ++jj) msk[jj] = g_maskcol[b * NC + w * 4 + jj];

    float wx_acc[4][4];
#pragma unroll
    for (int g = 0; g < 4; ++g)
#pragma unroll
        for (int q = 0; q < 4; ++q) wx_acc[g][q] = 0.f;
    float out_acc[2][4][4];
#pragma unroll
    for (int hh = 0; hh < 2; ++hh)
#pragma unroll
        for (int g = 0; g < 4; ++g)
#pragma unroll
            for (int q = 0; q < 4; ++q) out_acc[hh][g][q] = 0.f;

    const float NEGINF = __int_as_float(0xff800000);
    int buf = 0;
    unsigned int nextid = NTILES;

    // ---------------- persistent tile loop: 32 steps (nt 16 x kb2 2) ----------------
    for (;;) {
        for (int s = 0; s < 32; ++s) {
            const int nt = s >> 1, kb2 = s & 1;
            __syncthreads();
            if (s == 0) nextid = ids[1];

            // issue B(s+1) into buf^1 (+X prefetch piece for s<8)
            {
                int ss2 = (s + 1) & 31;
                int nn = ss2 >> 1, nk = ss2 & 1;
                int b2 = buf ^ 1;
#pragma unroll
                for (int ii = 0; ii < 4; ++ii) {
                    int it = tid + ii * MTHREADS;
                    int kh = it >> 10, r = (it >> 3) & 127, q = it & 7;
                    CP_ASYNC16(sb + SM_B + (uint32_t)(b2 * 32768 + kh * 16384 + r * 128 + ((q * 16) ^ ((r & 7) << 4))),
                               gp + ((size_t)(nn * 128 + r) * 512 + nk * 256 + kh * 128 + q * 16));
                }
                if (s < 8 && nextid < NTILES) {
                    int it = tid + s * MTHREADS;
                    int c = it >> 6, q = it & 63;
                    int nb = nextid >> 7, ntt = nextid & 127;
                    CP_ASYNC16(sb + SM_XSTG + (uint32_t)(c * 1024 + q * 16),
                               x + (((size_t)(nb * 64 + c) * 128) + ntt) * 256 + q * 4);
                }
                CP_COMMIT();
            }
            CP_WAIT1();   // B(s) landed

            // f16 HMMA: two k-halves of this step's 128-k range
#pragma unroll
            for (int kh = 0; kh < 2; ++kh) {
                const uint32_t pA = sb + SM_A + (uint32_t)((kb2 * 2 + kh) * 8192);
                const uint32_t pB = sb + SM_B + (uint32_t)(buf * 32768 + kh * 16384);
#pragma unroll
                for (int ks = 0; ks < 4; ++ks) {
                    uint32_t ah[4], bh[2][4];
                    uint32_t akb = ((uint32_t)(ks * 32) + akoff) ^ akx;
                    ldsm_x4(ah, pA + aoff + akb);
#pragma unroll
                    for (int p = 0; p < 2; ++p) {
                        uint32_t kbyte = ((uint32_t)(ks * 32) + bkoff) ^ bkx[p];
                        ldsm_x4(bh[p], pB + boff[p] + kbyte);
                    }
#pragma unroll
                    for (int g = 0; g < 4; ++g) {
                        const int p = g >> 1, o = (g & 1) * 2;
                        mma16816f16(wx_acc[g], ah, &bh[p][o]);
                    }
                }
            }

            if (kb2 == 1) {
                const int hh = nt & 1;
                int r1 = mw2 * 16 + (l >> 2);
#pragma unroll
                for (int g = 0; g < 4; ++g) {
                    int f = nw2 * 32 + g * 8 + (l & 3) * 2;
                    int fh = f >> 6, fb = (f & 63) * 2;
#pragma unroll
                    for (int half = 0; half < 2; ++half) {
                        int r = r1 + half * 8;
                        uint16_t h0 = f16_bits(wx_acc[g][half * 2]);
                        uint16_t h1 = f16_bits(wx_acc[g][half * 2 + 1]);
                        uint32_t off = (uint32_t)((r * 2 + fh) * 128 + (fb ^ ((r & 7) << 4)));
                        *(uint32_t*)(smem + SM_WX + off) = (uint32_t)h0 | ((uint32_t)h1 << 16);
                    }
                    wx_acc[g][0] = wx_acc[g][1] = wx_acc[g][2] = wx_acc[g][3] = 0.f;
                }
                if (hh == 0) {
                    int h = nt >> 1;
#pragma unroll
                    for (int jj = 0; jj < 4; ++jj) {
                        int j = w * 4 + jj;
                        unsigned long long m = msk[jj];
                        float adj = ad_s[h * 64 + j];
                        int i0 = l, i1 = l + 32;
                        float e0 = as_s[h * 64 + i0] + adj;
                        float e1 = as_s[h * 64 + i1] + adj;
                        e0 = e0 > 0.f ? e0 : 0.2f * e0;
                        e1 = e1 > 0.f ? e1 : 0.2f * e1;
                        bool m0 = (m >> i0) & 1ull;
                        bool m1 = (m >> i1) & 1ull;
                        float mx = fmaxf(m0 ? e0 : NEGINF, m1 ? e1 : NEGINF);
#pragma unroll
                        for (int off = 16; off > 0; off >>= 1)
                            mx = fmaxf(mx, __shfl_xor_sync(0xffffffffu, mx, off));
                        float p0 = m0 ? expf(e0 - mx) : 0.f;
                        float p1 = m1 ? expf(e1 - mx) : 0.f;
                        float ssum = p0 + p1;
#pragma unroll
                        for (int off = 16; off > 0; off >>= 1)
                            ssum += __shfl_xor_sync(0xffffffffu, ssum, off);
                        float invs = 1.0f / ssum;
                        alh[j * 72 + i0] = f16_bits(p0 * invs);
                        alh[j * 72 + i1] = f16_bits(p1 * invs);
                    }
                }
                __syncthreads();

#pragma unroll
                for (int ks = 0; ks < 4; ++ks) {
                    uint32_t aah[4], wbh[2][4];
                    ldsm_x4(aah, sb + SM_ALPHA + aoffA + (uint32_t)(ks * 32));
#pragma unroll
                    for (int n2 = 0; n2 < 2; ++n2) {
                        int i = ks * 16 + aggI;
                        int f = aggF + n2 * 16;
                        uint32_t off = (uint32_t)((i * 2 + (f >> 6)) * 128 + (((f & 63) * 2) ^ ((i & 7) << 4)));
                        ldsm_x4_t(wbh[n2], sb + SM_WX + off);
                    }
#pragma unroll
                    for (int q = 0; q < 4; ++q) {
                        const int n2 = q >> 1, o = (q & 1) * 2;
                        mma16816f16(out_acc[hh][q], aah, &wbh[n2][o]);
                    }
                }
            }
            buf ^= 1;
        }

        // ---------------- tile boundary (R12 verbatim) ----------------
        __syncthreads();
        {
            const float inv8 = 0.125f;
            int j0 = mw2 * 16 + (l >> 2);
#pragma unroll
            for (int hh = 0; hh < 2; ++hh) {
#pragma unroll
                for (int q = 0; q < 4; ++q) {
                    int f = hh * 128 + nw2 * 32 + q * 8 + (l & 3) * 2;
                    float b0 = __ldg(gat_bias + f), b1 = __ldg(gat_bias + f + 1);
                    float2 v0 = make_float2(out_acc[hh][q][0] * inv8 + b0, out_acc[hh][q][1] * inv8 + b1);
                    float2 v1 = make_float2(out_acc[hh][q][2] * inv8 + b0, out_acc[hh][q][3] * inv8 + b1);
                    *(float2*)(out + (((size_t)b * NC + j0) * NT + t) * ND + f) = v0;
                    *(float2*)(out + (((size_t)b * NC + j0 + 8) * NT + t) * ND + f) = v1;
                    out_acc[hh][q][0] = out_acc[hh][q][1] = out_acc[hh][q][2] = out_acc[hh][q][3] = 0.f;
                }
            }
        }
        unsigned int nid = nextid;
        __syncthreads();
        if (nid >= NTILES) { CP_WAIT0(); break; }
        id = nid; b = id >> 7; t = id & 127;
        if (tid == 0) ids[1] = atomicAdd(&g_tilectr, 1u);
        process_x(smem, tid);
#pragma unroll
        for (int jj = 0; jj < 4; ++jj) msk[jj] = g_maskcol[b * NC + w * 4 + jj];
    }
}

// ======================= launch =======================
extern "C" void kernel_launch(void* const* d_in, const int* in_sizes, int n_in,
                              void* d_out, int out_size) {
    const float* x          = (const float*)d_in[0];
    const float* static_adj = (const float*)d_in[1];
    const float* w_q        = (const float*)d_in[2];
    const float* w_k        = (const float*)d_in[3];
    const float* gat_lin    = (const float*)d_in[4];
    const float* att_src    = (const float*)d_in[5];
    const float* att_dst    = (const float*)d_in[6];
    const float* gat_bias   = (const float*)d_in[7];

    float* out = (float*)d_out;
    float* delta_out = out + (size_t)NB * NC * NT * ND;

    int nsm = 148;
    cudaDeviceGetAttribute(&nsm, cudaDevAttrMultiProcessorCount, 0);
    if (nsm <= 0) nsm = 148;
    if (nsm > NTILES) nsm = NTILES;

    cudaFuncSetAttribute(k_main, cudaFuncAttributeMaxDynamicSharedMemorySize, SM_MAIN);

    k_vsd<<<16, 256>>>(gat_lin, att_src, att_dst);
    k_prepG<<<2048, 256>>>(gat_lin);
    k_hmean<<<NB * NC, 256>>>(x);
    k_qk<<<NB * NC / 8, 256>>>(w_q, w_k);
    k_simtopk<<<NB * 4, 256>>>(static_adj, delta_out);
    k_main<<<nsm, MTHREADS, SM_MAIN>>>(x, gat_bias, out);
}

// round 15
// speedup vs baseline: 5.8960x; 1.0544x over previous
#include <cuda_runtime.h>
#include <cuda_bf16.h>
#include <cuda_fp16.h>
#include <math.h>
#include <stdint.h>
#include <string.h>

#define NB 16
#define NC 64
#define NT 128
#define ND 256
#define NH 8
#define NKD 32
#define NTOPK 8

// ======================= helpers =======================
__device__ __forceinline__ uint32_t smem_to_u32(const void* p) {
    uint32_t a;
    asm("{ .reg .u64 t; cvta.to.shared.u64 t, %1; cvt.u32.u64 %0, t; }" : "=r"(a) : "l"(p));
    return a;
}
#define CP_ASYNC16(sa, gp) \
    asm volatile("cp.async.cg.shared.global [%0], [%1], 16;" :: "r"(sa), "l"(gp))
#define CP_COMMIT() asm volatile("cp.async.commit_group;")
#define CP_WAIT0()  asm volatile("cp.async.wait_group 0;")
#define CP_WAIT1()  asm volatile("cp.async.wait_group 1;")

__device__ __forceinline__ void ldsm_x4(uint32_t* r, uint32_t addr) {
    asm volatile("ldmatrix.sync.aligned.m8n8.x4.shared.b16 {%0,%1,%2,%3}, [%4];"
                 : "=r"(r[0]), "=r"(r[1]), "=r"(r[2]), "=r"(r[3]) : "r"(addr));
}
__device__ __forceinline__ void ldsm_x4_t(uint32_t* r, uint32_t addr) {
    asm volatile("ldmatrix.sync.aligned.m8n8.x4.trans.shared.b16 {%0,%1,%2,%3}, [%4];"
                 : "=r"(r[0]), "=r"(r[1]), "=r"(r[2]), "=r"(r[3]) : "r"(addr));
}
__device__ __forceinline__ void mma16816f16(float* d, const uint32_t* a, const uint32_t* b) {
    asm volatile(
        "mma.sync.aligned.m16n8k16.row.col.f32.f16.f16.f32 "
        "{%0,%1,%2,%3}, {%4,%5,%6,%7}, {%8,%9}, {%0,%1,%2,%3};"
        : "+f"(d[0]), "+f"(d[1]), "+f"(d[2]), "+f"(d[3])
        : "r"(a[0]), "r"(a[1]), "r"(a[2]), "r"(a[3]), "r"(b[0]), "r"(b[1]));
}
__device__ __forceinline__ uint16_t f16_bits(float v) {
    __half h = __float2half_rn(v);
    uint16_t b; memcpy(&b, &h, 2);
    return b;
}

// ======================= device scratch =======================
__device__ float g_hmean[NB * NC * ND];
__device__ float g_q[NB * NC * NKD];
__device__ float g_k[NB * NC * NKD];
__device__ unsigned long long g_maskcol[NB * NC];
__device__ float g_vsrc[NH * ND];
__device__ float g_vdst[NH * ND];
__device__ uint16_t g_gf16[NH * ND * ND];   // G as f16 [2048 rows][256 k]
__device__ unsigned int g_tilectr;

// ======================= kernel: fused v_src/v_dst + G->f16 (+counter reset) =======================
__global__ void k_prep(const float* __restrict__ gat_lin,
                       const float* __restrict__ att_src,
                       const float* __restrict__ att_dst) {
    int bx = blockIdx.x;
    int tid = threadIdx.x;
    if (bx < 16) {
        int h = bx & 7;
        int isdst = bx >> 3;
        const float* att = isdst ? att_dst : att_src;
        float acc = 0.f;
#pragma unroll 4
        for (int f = 0; f < ND; ++f)
            acc += att[h * ND + f] * gat_lin[((size_t)(h * ND + f)) * ND + tid];
        (isdst ? g_vdst : g_vsrc)[h * ND + tid] = acc;
    } else {
        if (bx == 16 && tid == 0) g_tilectr = 0;
        uint32_t i = (uint32_t)(bx - 16) * 256 + tid;
        g_gf16[i] = f16_bits(gat_lin[i]);
    }
}

// ======================= kernel: temporal mean =======================
__global__ void k_hmean(const float* __restrict__ x) {
    int bc = blockIdx.x;
    int d = threadIdx.x;
    const float* p = x + (size_t)bc * NT * ND + d;
    float s = 0.f;
#pragma unroll 8
    for (int t = 0; t < NT; ++t) s += p[(size_t)t * ND];
    g_hmean[bc * ND + d] = s * (1.0f / NT);
}

// ======================= kernel: q/k projections + self-loop init =======================
__global__ __launch_bounds__(256)
void k_qk(const float* __restrict__ w_q, const float* __restrict__ w_k) {
    __shared__ float hs[8 * ND];
    int blk = blockIdx.x;
    int tid = threadIdx.x;
    for (int it = tid; it < 8 * ND; it += 256) hs[it] = g_hmean[(size_t)blk * 8 * ND + it];
    if (tid < 8) g_maskcol[blk * 8 + tid] = 1ull << ((blk * 8 + tid) & 63);
    __syncthreads();
#pragma unroll
    for (int k = 0; k < 2; ++k) {
        int o = tid + k * 256;
        int bcL = o >> 6, rem = o & 63;
        int which = rem >> 5, kd = rem & 31;
        const float4* w4 = (const float4*)((which ? w_k : w_q) + (size_t)kd * ND);
        const float* hr = hs + bcL * ND;
        float acc = 0.f;
#pragma unroll 8
        for (int d4 = 0; d4 < 64; ++d4) {
            float4 wv = __ldg(w4 + d4);
            acc += hr[d4 * 4] * wv.x + hr[d4 * 4 + 1] * wv.y
                 + hr[d4 * 4 + 2] * wv.z + hr[d4 * 4 + 3] * wv.w;
        }
        (which ? g_k : g_q)[(blk * 8 + bcL) * NKD + kd] = acc;
    }
}

// ======================= kernel: sim + tanh + top-k (merged) =======================
__global__ __launch_bounds__(256)
void k_simtopk(const float* __restrict__ static_adj, float* __restrict__ delta_out) {
    __shared__ float qs[16 * NKD];
    __shared__ float ks_[NC * NKD];
    __shared__ float arow[16 * NC];
    int b = blockIdx.x >> 2;
    int i0 = (blockIdx.x & 3) * 16;
    int tid = threadIdx.x;
    for (int it = tid; it < NC * NKD; it += 256) ks_[it] = g_k[b * NC * NKD + it];
    for (int it = tid; it < 16 * NKD; it += 256) qs[it] = g_q[b * NC * NKD + i0 * NKD + it];
    __syncthreads();
    const float inv = 0.17677669529663687f;
    for (int task = tid; task < 16 * NC; task += 256) {
        int i = task >> 6, j = task & 63;
        float acc = 0.f;
#pragma unroll
        for (int kd = 0; kd < NKD; ++kd) acc += qs[i * NKD + kd] * ks_[j * NKD + kd];
        float delta = tanhf(acc * inv);
        int gi = i0 + i;
        delta_out[b * NC * NC + gi * NC + j] = delta;
        arow[task] = static_adj[gi * NC + j] + delta;
    }
    __syncthreads();
    int w = tid >> 5, lane = tid & 31;
#pragma unroll
    for (int rr = 0; rr < 2; ++rr) {
        int i = w * 2 + rr;
        int gi = i0 + i;
        float v0 = fabsf(arow[i * NC + lane]);
        float v1 = fabsf(arow[i * NC + lane + 32]);
        for (int s = 0; s < NTOPK; ++s) {
            float bv; int bj;
            if (v0 >= v1) { bv = v0; bj = lane; } else { bv = v1; bj = lane + 32; }
#pragma unroll
            for (int off = 16; off > 0; off >>= 1) {
                float ov = __shfl_xor_sync(0xffffffffu, bv, off);
                int   oj = __shfl_xor_sync(0xffffffffu, bj, off);
                if (ov > bv || (ov == bv && oj < bj)) { bv = ov; bj = oj; }
            }
            if (lane == 0) atomicOr(&g_maskcol[b * NC + bj], 1ull << gi);
            if (bj == lane)      v0 = -1.0f;
            if (bj == lane + 32) v1 = -1.0f;
        }
    }
}

// ======================= PERSISTENT fused kernel (pipelined agg) =======================
#define MTHREADS 512
#define SM_A 0                        // 32768: A f16 [chunk4][64r][128B]
#define SM_B 32768                    // 65536: 2 stages x [kh2][128r][128B]
#define SM_WX 98304                   // 32768: 2 x 16384 wx f16 buffers
#define SM_ALPHA 131072               // 18432: 2 x 9216 f16 alpha [64][72] (vt overlay)
#define SM_ASAD 149504                // 4096
#define SM_XSTG 153600                // 65536
#define SM_IDS 219136                 // 16
#define SM_MAIN 219152
#define NTILES 2048

__device__ __forceinline__ void process_x(char* smem, int tid) {
    const float* stgf = (const float*)(smem + SM_XSTG);
    const float* vt = (const float*)(smem + SM_ALPHA);
    float* as_s = (float*)(smem + SM_ASAD);
    float* ad_s = as_s + 512;
#pragma unroll
    for (int k = 0; k < 2; ++k) {
        int task = tid + k * MTHREADS;
        int c = task >> 4, hv = task & 15, h = hv & 7, sd = hv >> 3;
        const float* sr = stgf + c * 256;
        const float* vr = vt + hv;
        float acc = 0.f;
#pragma unroll 8
        for (int d = 0; d < 256; ++d) acc += sr[d] * vr[d * 17];
        (sd ? ad_s : as_s)[h * 64 + c] = acc;
    }
#pragma unroll
    for (int k = 0; k < 4; ++k) {
        int it = tid + k * MTHREADS;
        int c = it >> 5, c64 = (it >> 3) & 3, gn = it & 7;
        const float* src = stgf + c * 256 + c64 * 64 + gn * 8;
        uint32_t wv[4];
#pragma unroll
        for (int p = 0; p < 4; ++p)
            wv[p] = (uint32_t)f16_bits(src[2 * p]) | ((uint32_t)f16_bits(src[2 * p + 1]) << 16);
        uint32_t off = (uint32_t)(c * 128 + ((gn * 16) ^ ((c & 7) << 4)));
        *(uint4*)(smem + SM_A + c64 * 8192 + off) = make_uint4(wv[0], wv[1], wv[2], wv[3]);
    }
}

__device__ __forceinline__ void load_vt(char* smem, int tid) {
    float* vt = (float*)(smem + SM_ALPHA);
    for (int it = tid; it < 2048; it += MTHREADS) {
        int h = it >> 8, d = it & 255;
        vt[d * 17 + h]     = g_vsrc[it];
        vt[d * 17 + 8 + h] = g_vdst[it];
    }
}

__global__ __launch_bounds__(MTHREADS, 1)
void k_main(const float* __restrict__ x,
            const float* __restrict__ gat_bias,
            float* __restrict__ out) {
    extern __shared__ char smem[];
    uint32_t sb = smem_to_u32(smem);
    const int tid = threadIdx.x;
    const int w = tid >> 5, l = tid & 31;
    unsigned int* ids = (unsigned int*)(smem + SM_IDS);

    const char* gp = (const char*)g_gf16;

    // ---------------- prologue ----------------
    if (tid == 0) ids[0] = atomicAdd(&g_tilectr, 1u);
    __syncthreads();
    unsigned int id = ids[0];
    if (id >= NTILES) return;
    int b = id >> 7, t = id & 127;

#pragma unroll
    for (int ii = 0; ii < 8; ++ii) {
        int it = tid + ii * MTHREADS;
        int c = it >> 6, q = it & 63;
        CP_ASYNC16(sb + SM_XSTG + (uint32_t)(c * 1024 + q * 16),
                   x + (((size_t)(b * 64 + c) * 128) + t) * 256 + q * 4);
    }
    CP_COMMIT();
#pragma unroll
    for (int ii = 0; ii < 4; ++ii) {
        int it = tid + ii * MTHREADS;
        int kh = it >> 10, r = (it >> 3) & 127, q = it & 7;
        CP_ASYNC16(sb + SM_B + (uint32_t)(kh * 16384 + r * 128 + ((q * 16) ^ ((r & 7) << 4))),
                   gp + ((size_t)r * 512 + kh * 128 + q * 16));
    }
    CP_COMMIT();
    load_vt(smem, tid);
    CP_WAIT1();          // X landed
    __syncthreads();
    process_x(smem, tid);
    if (tid == 0) ids[1] = atomicAdd(&g_tilectr, 1u);

    // ---------------- frag geometry ----------------
    const int mw2 = w & 3, nw2 = w >> 2;
    const int arow_g = mw2 * 16 + (l & 15);
    const uint32_t aoff = (uint32_t)(arow_g * 128);
    const uint32_t akx = (uint32_t)((arow_g & 7) << 4);
    const uint32_t akoff = (uint32_t)((l >> 4) * 16);
    int boff[2]; uint32_t bkx[2];
#pragma unroll
    for (int p = 0; p < 2; ++p) {
        int r = nw2 * 32 + p * 16 + (l & 7) + (l >> 4) * 8;
        boff[p] = r * 128;
        bkx[p] = (uint32_t)((r & 7) << 4);
    }
    const uint32_t bkoff = (uint32_t)(((l >> 3) & 1) * 16);
    const uint32_t aoffA = (uint32_t)(((mw2 * 16 + (l & 15)) * 72 + (l >> 4) * 8) * 2);
    const int aggI = (l & 7) + ((l >> 3) & 1) * 8;
    const int aggF = nw2 * 32 + (l >> 4) * 8;

    float* as_s = (float*)(smem + SM_ASAD);
    float* ad_s = as_s + 512;

    unsigned long long msk[4];
#pragma unroll
    for (int jj = 0; jj < 4; ++jj) msk[jj] = g_maskcol[b * NC + w * 4 + jj];

    float wx_acc[4][4];
#pragma unroll
    for (int g = 0; g < 4; ++g)
#pragma unroll
        for (int q = 0; q < 4; ++q) wx_acc[g][q] = 0.f;
    float out_acc[2][4][4];
#pragma unroll
    for (int hh = 0; hh < 2; ++hh)
#pragma unroll
        for (int g = 0; g < 4; ++g)
#pragma unroll
            for (int q = 0; q < 4; ++q) out_acc[hh][g][q] = 0.f;

    const float NEGINF = __int_as_float(0xff800000);
    int buf = 0;
    unsigned int nextid = NTILES;

    // agg(prev) macro-block
#define DO_AGG(prev_nt) do { \
        const int _p = (prev_nt); \
        const uint32_t _wb = sb + SM_WX + (uint32_t)((_p & 1) * 16384); \
        const uint32_t _ab = sb + SM_ALPHA + (uint32_t)(((_p >> 1) & 1) * 9216); \
        const int _hh = _p & 1; \
        _Pragma("unroll") \
        for (int ks = 0; ks < 4; ++ks) { \
            uint32_t aah[4], wbh[2][4]; \
            ldsm_x4(aah, _ab + aoffA + (uint32_t)(ks * 32)); \
            _Pragma("unroll") \
            for (int n2 = 0; n2 < 2; ++n2) { \
                int i = ks * 16 + aggI; \
                int f = aggF + n2 * 16; \
                uint32_t off = (uint32_t)((i * 2 + (f >> 6)) * 128 + (((f & 63) * 2) ^ ((i & 7) << 4))); \
                ldsm_x4_t(wbh[n2], _wb + off); \
            } \
            _Pragma("unroll") \
            for (int q = 0; q < 4; ++q) { \
                const int n2 = q >> 1, o = (q & 1) * 2; \
                mma16816f16(out_acc[_hh][q], aah, &wbh[n2][o]); \
            } \
        } \
    } while (0)

    // ---------------- persistent tile loop ----------------
    for (;;) {
        for (int s = 0; s < 32; ++s) {
            const int nt = s >> 1, kb2 = s & 1;
            __syncthreads();
            if (s == 0) nextid = ids[1];

            // issue B(s+1) (+X prefetch for s<8)
            {
                int ss2 = (s + 1) & 31;
                int nn = ss2 >> 1, nk = ss2 & 1;
                int b2 = buf ^ 1;
#pragma unroll
                for (int ii = 0; ii < 4; ++ii) {
                    int it = tid + ii * MTHREADS;
                    int kh = it >> 10, r = (it >> 3) & 127, q = it & 7;
                    CP_ASYNC16(sb + SM_B + (uint32_t)(b2 * 32768 + kh * 16384 + r * 128 + ((q * 16) ^ ((r & 7) << 4))),
                               gp + ((size_t)(nn * 128 + r) * 512 + nk * 256 + kh * 128 + q * 16));
                }
                if (s < 8 && nextid < NTILES) {
                    int it = tid + s * MTHREADS;
                    int c = it >> 6, q = it & 63;
                    int nb = nextid >> 7, ntt = nextid & 127;
                    CP_ASYNC16(sb + SM_XSTG + (uint32_t)(c * 1024 + q * 16),
                               x + (((size_t)(nb * 64 + c) * 128) + ntt) * 256 + q * 4);
                }
                CP_COMMIT();
            }

            // pipelined agg of previous n-tile (overlaps B landing)
            if (kb2 == 1 && nt > 0) DO_AGG(nt - 1);

            CP_WAIT1();

            // f16 HMMA gemm
#pragma unroll
            for (int kh = 0; kh < 2; ++kh) {
                const uint32_t pA = sb + SM_A + (uint32_t)((kb2 * 2 + kh) * 8192);
                const uint32_t pB = sb + SM_B + (uint32_t)(buf * 32768 + kh * 16384);
#pragma unroll
                for (int ks = 0; ks < 4; ++ks) {
                    uint32_t ah[4], bh[2][4];
                    uint32_t akb = ((uint32_t)(ks * 32) + akoff) ^ akx;
                    ldsm_x4(ah, pA + aoff + akb);
#pragma unroll
                    for (int p = 0; p < 2; ++p) {
                        uint32_t kbyte = ((uint32_t)(ks * 32) + bkoff) ^ bkx[p];
                        ldsm_x4(bh[p], pB + boff[p] + kbyte);
                    }
#pragma unroll
                    for (int g = 0; g < 4; ++g) {
                        const int p = g >> 1, o = (g & 1) * 2;
                        mma16816f16(wx_acc[g], ah, &bh[p][o]);
                    }
                }
            }

            if (kb2 == 0) {
                // softmax for new head (once per head, at its first n-tile)
                if ((nt & 1) == 0) {
                    int h = nt >> 1;
                    uint16_t* alw = (uint16_t*)(smem + SM_ALPHA + (h & 1) * 9216);
#pragma unroll
                    for (int jj = 0; jj < 4; ++jj) {
                        int j = w * 4 + jj;
                        unsigned long long m = msk[jj];
                        float adj = ad_s[h * 64 + j];
                        int i0 = l, i1 = l + 32;
                        float e0 = as_s[h * 64 + i0] + adj;
                        float e1 = as_s[h * 64 + i1] + adj;
                        e0 = e0 > 0.f ? e0 : 0.2f * e0;
                        e1 = e1 > 0.f ? e1 : 0.2f * e1;
                        bool m0 = (m >> i0) & 1ull;
                        bool m1 = (m >> i1) & 1ull;
                        float mx = fmaxf(m0 ? e0 : NEGINF, m1 ? e1 : NEGINF);
#pragma unroll
                        for (int off = 16; off > 0; off >>= 1)
                            mx = fmaxf(mx, __shfl_xor_sync(0xffffffffu, mx, off));
                        float p0 = m0 ? expf(e0 - mx) : 0.f;
                        float p1 = m1 ? expf(e1 - mx) : 0.f;
                        float ssum = p0 + p1;
#pragma unroll
                        for (int off = 16; off > 0; off >>= 1)
                            ssum += __shfl_xor_sync(0xffffffffu, ssum, off);
                        float invs = 1.0f / ssum;
                        alw[j * 72 + i0] = f16_bits(p0 * invs);
                        alw[j * 72 + i1] = f16_bits(p1 * invs);
                    }
                }
            } else {
                // store wx tile into WX[nt&1] (no trailing sync — agg is pipelined)
                char* wxb = smem + SM_WX + (nt & 1) * 16384;
                int r1 = mw2 * 16 + (l >> 2);
#pragma unroll
                for (int g = 0; g < 4; ++g) {
                    int f = nw2 * 32 + g * 8 + (l & 3) * 2;
                    int fh = f >> 6, fb = (f & 63) * 2;
#pragma unroll
                    for (int half = 0; half < 2; ++half) {
                        int r = r1 + half * 8;
                        uint16_t h0 = f16_bits(wx_acc[g][half * 2]);
                        uint16_t h1 = f16_bits(wx_acc[g][half * 2 + 1]);
                        uint32_t off = (uint32_t)((r * 2 + fh) * 128 + (fb ^ ((r & 7) << 4)));
                        *(uint32_t*)(wxb + off) = (uint32_t)h0 | ((uint32_t)h1 << 16);
                    }
                    wx_acc[g][0] = wx_acc[g][1] = wx_acc[g][2] = wx_acc[g][3] = 0.f;
                }
            }
            buf ^= 1;
        }

        // ---------------- tile boundary ----------------
        __syncthreads();        // order WX[1] stores before final agg
        DO_AGG(15);
        {
            const float inv8 = 0.125f;
            int j0 = mw2 * 16 + (l >> 2);
#pragma unroll
            for (int hh = 0; hh < 2; ++hh) {
#pragma unroll
                for (int q = 0; q < 4; ++q) {
                    int f = hh * 128 + nw2 * 32 + q * 8 + (l & 3) * 2;
                    float b0 = __ldg(gat_bias + f), b1 = __ldg(gat_bias + f + 1);
                    float2 v0 = make_float2(out_acc[hh][q][0] * inv8 + b0, out_acc[hh][q][1] * inv8 + b1);
                    float2 v1 = make_float2(out_acc[hh][q][2] * inv8 + b0, out_acc[hh][q][3] * inv8 + b1);
                    *(float2*)(out + (((size_t)b * NC + j0) * NT + t) * ND + f) = v0;
                    *(float2*)(out + (((size_t)b * NC + j0 + 8) * NT + t) * ND + f) = v1;
                    out_acc[hh][q][0] = out_acc[hh][q][1] = out_acc[hh][q][2] = out_acc[hh][q][3] = 0.f;
                }
            }
        }
        unsigned int nid = nextid;
        __syncthreads();        // all agg reads of ALPHA done before vt overlay; ids[1] safe
        if (nid >= NTILES) { CP_WAIT0(); break; }
        id = nid; b = id >> 7; t = id & 127;
        load_vt(smem, tid);
        if (tid == 0) ids[1] = atomicAdd(&g_tilectr, 1u);
        __syncthreads();        // vt visible before process_x
        process_x(smem, tid);
#pragma unroll
        for (int jj = 0; jj < 4; ++jj) msk[jj] = g_maskcol[b * NC + w * 4 + jj];
        // loop-top sync publishes A/asad/ids[1]
    }
#undef DO_AGG
}

// ======================= launch =======================
extern "C" void kernel_launch(void* const* d_in, const int* in_sizes, int n_in,
                              void* d_out, int out_size) {
    const float* x          = (const float*)d_in[0];
    const float* static_adj = (const float*)d_in[1];
    const float* w_q        = (const float*)d_in[2];
    const float* w_k        = (const float*)d_in[3];
    const float* gat_lin    = (const float*)d_in[4];
    const float* att_src    = (const float*)d_in[5];
    const float* att_dst    = (const float*)d_in[6];
    const float* gat_bias   = (const float*)d_in[7];

    float* out = (float*)d_out;
    float* delta_out = out + (size_t)NB * NC * NT * ND;

    int nsm = 148;
    cudaDeviceGetAttribute(&nsm, cudaDevAttrMultiProcessorCount, 0);
    if (nsm <= 0) nsm = 148;
    if (nsm > NTILES) nsm = NTILES;

    cudaFuncSetAttribute(k_main, cudaFuncAttributeMaxDynamicSharedMemorySize, SM_MAIN);

    k_prep<<<16 + 2048, 256>>>(gat_lin, att_src, att_dst);
    k_hmean<<<NB * NC, 256>>>(x);
    k_qk<<<NB * NC / 8, 256>>>(w_q, w_k);
    k_simtopk<<<NB * 4, 256>>>(static_adj, delta_out);
    k_main<<<nsm, MTHREADS, SM_MAIN>>>(x, gat_bias, out);
}